// round 1
// baseline (speedup 1.0000x reference)
#include <cuda_runtime.h>
#include <math.h>

#define V_N 20496
#define E_N 61440
#define F_N 3840
#define H_N 256
#define LDH 264   // 259 (concat width) padded to multiple of 8

// ---------------------------------------------------------------------------
// Scratch (static device globals — no allocation allowed)
// ---------------------------------------------------------------------------
__device__ float g_h  [(size_t)V_N * LDH];  // concat(relu(backbone), verts, pad)
__device__ float g_x  [(size_t)V_N * H_N];  // ping
__device__ float g_y  [(size_t)V_N * H_N];  // pong
__device__ float g_nbr[(size_t)V_N * H_N];  // nbr buffer / z1 reuse
__device__ float g_z2 [(size_t)V_N * 64];

// ---------------------------------------------------------------------------
// Classic 128x128x8 SGEMM, 8x8 microtile, relu fusable on A-read and C-write.
// C[M,N] = (RELU_IN ? relu(A) : A)[M,K] @ B[K,N] + bias[N]
// A row stride = lda, C row stride = ldc, B row stride = N.
// Fully bounds-checked (M=20496 not a tile multiple, K=259 for layer 0).
// ---------------------------------------------------------------------------
template<bool RELU_IN, bool RELU_OUT>
__global__ __launch_bounds__(256, 2)
void sgemm_kernel(const float* __restrict__ A, const float* __restrict__ B,
                  const float* __restrict__ bias, float* __restrict__ C,
                  int M, int N, int K, int lda, int ldc)
{
    __shared__ float As[8][132];   // +4 pad: conflict-free transposed stores
    __shared__ float Bs[8][128];

    const int tid = threadIdx.x;
    const int bm = blockIdx.y * 128;
    const int bn = blockIdx.x * 128;
    const int tr = (tid >> 4) << 3;   // 0..120, row of 8x8 microtile
    const int tc = (tid & 15) << 3;   // 0..120, col of 8x8 microtile

    float acc[8][8];
#pragma unroll
    for (int i = 0; i < 8; i++)
#pragma unroll
        for (int j = 0; j < 8; j++) acc[i][j] = 0.f;

    const int a_m = tid >> 3;          // 0..31
    const int a_k = tid & 7;           // 0..7
    const int b_k = tid >> 5;          // 0..7
    const int b_n = (tid & 31) << 2;   // 0..124 (float4)

    for (int k0 = 0; k0 < K; k0 += 8) {
        // ---- load A tile (128 x 8), transposed into SMEM ----
#pragma unroll
        for (int p = 0; p < 4; p++) {
            int m  = a_m + p * 32;
            int gm = bm + m;
            int gk = k0 + a_k;
            float v = 0.f;
            if (gm < M && gk < K) v = __ldg(&A[(size_t)gm * lda + gk]);
            if (RELU_IN) v = fmaxf(v, 0.f);
            As[a_k][m] = v;
        }
        // ---- load B tile (8 x 128) ----
        {
            int gk = k0 + b_k;
            int gn = bn + b_n;
            float4 v = make_float4(0.f, 0.f, 0.f, 0.f);
            if (gk < K) {
                if (gn + 3 < N) {
                    v = *(const float4*)(B + (size_t)gk * N + gn);
                } else {
                    float* vp = &v.x;
#pragma unroll
                    for (int q = 0; q < 4; q++)
                        if (gn + q < N) vp[q] = B[(size_t)gk * N + gn + q];
                }
            }
            *(float4*)&Bs[b_k][b_n] = v;
        }
        __syncthreads();

#pragma unroll
        for (int k = 0; k < 8; k++) {
            float af[8], bf[8];
#pragma unroll
            for (int i = 0; i < 8; i++) af[i] = As[k][tr + i];
#pragma unroll
            for (int j = 0; j < 8; j++) bf[j] = Bs[k][tc + j];
#pragma unroll
            for (int i = 0; i < 8; i++)
#pragma unroll
                for (int j = 0; j < 8; j++)
                    acc[i][j] = fmaf(af[i], bf[j], acc[i][j]);
        }
        __syncthreads();
    }

#pragma unroll
    for (int i = 0; i < 8; i++) {
        int gm = bm + tr + i;
        if (gm >= M) continue;
#pragma unroll
        for (int j = 0; j < 8; j++) {
            int gn = bn + tc + j;
            if (gn >= N) continue;
            float v = acc[i][j] + bias[gn];
            if (RELU_OUT) v = fmaxf(v, 0.f);
            C[(size_t)gm * ldc + gn] = v;
        }
    }
}

// ---------------------------------------------------------------------------
// Copy verts into cols 256..258 of g_h, zero pad cols 259..263
// ---------------------------------------------------------------------------
__global__ void concat_verts_kernel(const float* __restrict__ verts)
{
    int v = blockIdx.x * blockDim.x + threadIdx.x;
    if (v < V_N) {
        size_t base = (size_t)v * LDH + 256;
#pragma unroll
        for (int c = 0; c < 3; c++) g_h[base + c] = verts[v * 3 + c];
#pragma unroll
        for (int c = 3; c < 8; c++) g_h[base + c] = 0.f;
    }
}

// ---------------------------------------------------------------------------
// Edge scatter: out[i] += nbr[j]; out[j] += nbr[i]  (256-wide rows)
// One block per edge, one thread per column.
// ---------------------------------------------------------------------------
__global__ void scatter_kernel(const int* __restrict__ edges,
                               const float* __restrict__ nbr,
                               float* __restrict__ out)
{
    int e = blockIdx.x;
    int c = threadIdx.x;
    int i = edges[2 * e];
    int j = edges[2 * e + 1];
    float vj = nbr[(size_t)j * H_N + c];
    float vi = nbr[(size_t)i * H_N + c];
    atomicAdd(&out[(size_t)i * H_N + c], vj);
    atomicAdd(&out[(size_t)j * H_N + c], vi);
}

// ---------------------------------------------------------------------------
// delta_v = relu(h) @ Wo + bo   ([V,256] @ [256,3])
// ---------------------------------------------------------------------------
__global__ void delta_kernel(const float* __restrict__ h,
                             const float* __restrict__ Wo,
                             const float* __restrict__ bo,
                             float* __restrict__ out)
{
    __shared__ float sW[H_N * 3];
    __shared__ float sb[3];
    for (int i = threadIdx.x; i < H_N * 3; i += blockDim.x) sW[i] = Wo[i];
    if (threadIdx.x < 3) sb[threadIdx.x] = bo[threadIdx.x];
    __syncthreads();

    int idx = blockIdx.x * blockDim.x + threadIdx.x;
    if (idx >= V_N * 3) return;
    int v = idx / 3, c = idx % 3;
    const float* hr = h + (size_t)v * H_N;
    float s = sb[c];
#pragma unroll 8
    for (int k = 0; k < H_N; k++) s += fmaxf(hr[k], 0.f) * sW[k * 3 + c];
    out[idx] = s;
}

// ---------------------------------------------------------------------------
// Fused tail: z3 = relu(z2 @ A3 + a3); conf = sigmoid(z3 @ A4 + a4)
// z2: [V,64], A3: [64,32], A4: [32,1]
// ---------------------------------------------------------------------------
__global__ void tail_kernel(const float* __restrict__ z2,
                            const float* __restrict__ A3,
                            const float* __restrict__ a3,
                            const float* __restrict__ A4,
                            const float* __restrict__ a4,
                            float* __restrict__ conf)
{
    __shared__ float sA3[64 * 32];
    __shared__ float sa3[32];
    __shared__ float sA4[32];
    for (int i = threadIdx.x; i < 64 * 32; i += blockDim.x) sA3[i] = A3[i];
    if (threadIdx.x < 32) {
        sa3[threadIdx.x] = a3[threadIdx.x];
        sA4[threadIdx.x] = A4[threadIdx.x];
    }
    __syncthreads();

    float b4 = a4[0];
    for (int v = blockIdx.x * blockDim.x + threadIdx.x; v < V_N;
         v += gridDim.x * blockDim.x) {
        float x[64];
        const float* zr = z2 + (size_t)v * 64;
#pragma unroll
        for (int k = 0; k < 64; k++) x[k] = zr[k];
        float acc = b4;
#pragma unroll 4
        for (int m = 0; m < 32; m++) {
            float s = sa3[m];
#pragma unroll
            for (int k = 0; k < 64; k++) s = fmaf(x[k], sA3[k * 32 + m], s);
            acc = fmaf(fmaxf(s, 0.f), sA4[m], acc);
        }
        conf[v] = 1.f / (1.f + expf(-acc));
    }
}

// ---------------------------------------------------------------------------
// Launcher
// ---------------------------------------------------------------------------
extern "C" void kernel_launch(void* const* d_in, const int* in_sizes, int n_in,
                              void* d_out, int out_size)
{
    const float* X     = (const float*)d_in[0];
    const float* verts = (const float*)d_in[1];
    const int*   edges = (const int*)  d_in[2];
    const float* Wb    = (const float*)d_in[3];
    const float* bb    = (const float*)d_in[4];
    const float* W0_0  = (const float*)d_in[5];
    const float* b0_0  = (const float*)d_in[6];
    const float* W1_0  = (const float*)d_in[7];
    const float* b1_0  = (const float*)d_in[8];
    const float* gW0   = (const float*)d_in[9];
    const float* gb0   = (const float*)d_in[10];
    const float* gW1   = (const float*)d_in[11];
    const float* gb1   = (const float*)d_in[12];
    const float* Wo    = (const float*)d_in[13];
    const float* bo    = (const float*)d_in[14];
    const float* A1    = (const float*)d_in[15];
    const float* a1    = (const float*)d_in[16];
    const float* A2    = (const float*)d_in[17];
    const float* a2    = (const float*)d_in[18];
    const float* A3    = (const float*)d_in[19];
    const float* a3    = (const float*)d_in[20];
    const float* A4    = (const float*)d_in[21];
    const float* a4    = (const float*)d_in[22];
    float* out = (float*)d_out;

    float *p_h, *p_x, *p_y, *p_nbr, *p_z2;
    cudaGetSymbolAddress((void**)&p_h,   g_h);
    cudaGetSymbolAddress((void**)&p_x,   g_x);
    cudaGetSymbolAddress((void**)&p_y,   g_y);
    cudaGetSymbolAddress((void**)&p_nbr, g_nbr);
    cudaGetSymbolAddress((void**)&p_z2,  g_z2);

    const dim3 gemm_block(256);
    const dim3 grid256(2,  (V_N + 127) / 128);   // N=256
    const dim3 grid64 (1,  (V_N + 127) / 128);   // N=64

    // 1) backbone: h_img = relu(X @ Wb + bb) -> g_h[:, :256]
    sgemm_kernel<false, true><<<grid256, gemm_block>>>(
        X, Wb, bb, p_h, V_N, 256, F_N, F_N, LDH);

    // 2) concat verts into g_h[:, 256:259] (+ zero pad)
    concat_verts_kernel<<<(V_N + 255) / 256, 256>>>(verts);

    // 3) layer 0 (K = 259, input already activated)
    sgemm_kernel<false, false><<<grid256, gemm_block>>>(
        p_h, W0_0, b0_0, p_x, V_N, 256, 259, LDH, 256);
    sgemm_kernel<false, false><<<grid256, gemm_block>>>(
        p_h, W1_0, b1_0, p_nbr, V_N, 256, 259, LDH, 256);
    scatter_kernel<<<E_N, 256>>>(edges, p_nbr, p_x);

    // 4) layers 1..9 (K = 256, relu fused on input read)
    float* cur = p_x;
    float* nxt = p_y;
    for (int k = 0; k < 9; k++) {
        const float* W0 = gW0 + (size_t)k * H_N * H_N;
        const float* B0 = gb0 + (size_t)k * H_N;
        const float* W1 = gW1 + (size_t)k * H_N * H_N;
        const float* B1 = gb1 + (size_t)k * H_N;
        sgemm_kernel<true, false><<<grid256, gemm_block>>>(
            cur, W0, B0, nxt, V_N, 256, 256, 256, 256);
        sgemm_kernel<true, false><<<grid256, gemm_block>>>(
            cur, W1, B1, p_nbr, V_N, 256, 256, 256, 256);
        scatter_kernel<<<E_N, 256>>>(edges, p_nbr, nxt);
        float* t = cur; cur = nxt; nxt = t;
    }
    // final pre-relu h lives in `cur`

    // 5) delta_v = relu(h) @ Wo + bo  -> out[0 : V*3]
    delta_kernel<<<(V_N * 3 + 255) / 256, 256>>>(cur, Wo, bo, out);

    // 6) z1 = relu(relu(h) @ A1 + a1)   (reuse g_nbr)
    sgemm_kernel<true, true><<<grid256, gemm_block>>>(
        cur, A1, a1, p_nbr, V_N, 256, 256, 256, 256);

    // 7) z2 = relu(z1 @ A2 + a2)
    sgemm_kernel<false, true><<<grid64, gemm_block>>>(
        p_nbr, A2, a2, p_z2, V_N, 64, 256, 256, 64);

    // 8) conf = sigmoid(relu(z2 @ A3 + a3) @ A4 + a4) -> out[V*3 : V*4]
    tail_kernel<<<128, 256>>>(p_z2, A3, a3, A4, a4, out + (size_t)V_N * 3);
}

// round 3
// speedup vs baseline: 2.1420x; 2.1420x over previous
#include <cuda_runtime.h>
#include <cuda_bf16.h>
#include <math.h>
#include <stdint.h>

#define V_N 20496
#define E_N 61440
#define F_N 3840
#define H_N 256
#define LDH 260   // 259 concat width padded to mult of 4

// ---------------------------------------------------------------------------
// Scratch (static device globals — no allocation allowed)
// ---------------------------------------------------------------------------
__device__ __align__(16) float g_h  [(size_t)V_N * LDH];
__device__ __align__(16) float g_x  [(size_t)V_N * H_N];
__device__ __align__(16) float g_y  [(size_t)V_N * H_N];
__device__ __align__(16) float g_nbr[(size_t)V_N * H_N];
__device__ __align__(16) float g_z2 [(size_t)V_N * 64];

// weight scratch: transposed [N, K_pad] bf16 hi/lo
__device__ __align__(16) __nv_bfloat16 wb_h [256 * 3840];
__device__ __align__(16) __nv_bfloat16 wb_l [256 * 3840];
__device__ __align__(16) __nv_bfloat16 w0_h [256 * 320];
__device__ __align__(16) __nv_bfloat16 w0_l [256 * 320];
__device__ __align__(16) __nv_bfloat16 w1_h [256 * 320];
__device__ __align__(16) __nv_bfloat16 w1_l [256 * 320];
__device__ __align__(16) __nv_bfloat16 gw0_h[9 * 256 * 256];
__device__ __align__(16) __nv_bfloat16 gw0_l[9 * 256 * 256];
__device__ __align__(16) __nv_bfloat16 gw1_h[9 * 256 * 256];
__device__ __align__(16) __nv_bfloat16 gw1_l[9 * 256 * 256];
__device__ __align__(16) __nv_bfloat16 a1_h [256 * 256];
__device__ __align__(16) __nv_bfloat16 a1_l [256 * 256];
__device__ __align__(16) __nv_bfloat16 a2_h [64 * 256];
__device__ __align__(16) __nv_bfloat16 a2_l [64 * 256];

// ---------------------------------------------------------------------------
// PTX helpers (all legal on plain compute_103: mma.sync / ldmatrix / cp.async)
// ---------------------------------------------------------------------------
__device__ __forceinline__ void ldsm_x4(uint32_t* r, uint32_t addr) {
    asm volatile("ldmatrix.sync.aligned.m8n8.x4.shared.b16 {%0,%1,%2,%3}, [%4];"
        : "=r"(r[0]), "=r"(r[1]), "=r"(r[2]), "=r"(r[3]) : "r"(addr));
}

__device__ __forceinline__ void mma16816(float* d, const uint32_t* a, const uint32_t* b) {
    asm volatile(
        "mma.sync.aligned.m16n8k16.row.col.f32.bf16.bf16.f32 "
        "{%0,%1,%2,%3}, {%4,%5,%6,%7}, {%8,%9}, {%0,%1,%2,%3};"
        : "+f"(d[0]), "+f"(d[1]), "+f"(d[2]), "+f"(d[3])
        : "r"(a[0]), "r"(a[1]), "r"(a[2]), "r"(a[3]), "r"(b[0]), "r"(b[1]));
}

__device__ __forceinline__ void cp_async16(uint32_t dst, const void* src, bool pred) {
    int sz = pred ? 16 : 0;
    asm volatile("cp.async.cg.shared.global [%0], [%1], 16, %2;"
                 :: "r"(dst), "l"(src), "r"(sz));
}
#define CP_COMMIT() asm volatile("cp.async.commit_group;")
#define CP_WAIT0()  asm volatile("cp.async.wait_group 0;")

// pack two floats into bf16x2 (low = f0), also return the bf16-rounded floats
__device__ __forceinline__ uint32_t packbf(float f0, float f1, float& r0, float& r1) {
    __nv_bfloat16 h0 = __float2bfloat16(f0);
    __nv_bfloat16 h1 = __float2bfloat16(f1);
    r0 = __bfloat162float(h0);
    r1 = __bfloat162float(h1);
    __nv_bfloat162 p;
    p.x = h0; p.y = h1;
    return *(uint32_t*)&p;
}

// ---------------------------------------------------------------------------
// Split-bf16 3-pass mma.sync GEMM.
//   C[M,N] = act(A_fp32)[M,K] @ W^T + bias,  W prepped as [N,K_pad] bf16 hi/lo.
// CTA tile 128x128, K-chunk 32, 8 warps (warp tile 32x64), double-buffered.
// SMEM layout per stage: Ahi(8K) Alo(8K) Bhi(8K) Blo(8K); rows = 64B, XOR swizzle.
// ---------------------------------------------------------------------------
#define OFF_ALO 8192
#define OFF_BHI 16384
#define OFF_BLO 24576
#define STAGE_B 32768

template<bool RELU_IN, bool RELU_OUT>
__global__ void __launch_bounds__(256)
gemm_mma(const float* __restrict__ A,
         const __nv_bfloat16* __restrict__ Bhi, const __nv_bfloat16* __restrict__ Blo,
         const float* __restrict__ bias, float* __restrict__ C,
         int M, int N, int Kin, int K_pad, int lda, int ldc)
{
    extern __shared__ char smp[];
    const uint32_t sbase = (uint32_t)__cvta_generic_to_shared(smp);

    const int tid  = threadIdx.x;
    const int lane = tid & 31;
    const int w    = tid >> 5;
    const int mw   = w & 3;      // 0..3 -> m offset 32*mw
    const int nw   = w >> 2;     // 0..1 -> n offset 64*nw
    const int bm   = blockIdx.y * 128;
    const int bn   = blockIdx.x * 128;
    const int rows_valid = M - bm;

    float acc[2][8][4];
#pragma unroll
    for (int a = 0; a < 2; a++)
#pragma unroll
        for (int b = 0; b < 8; b++)
#pragma unroll
            for (int c = 0; c < 4; c++) acc[a][b][c] = 0.f;

    const int ar   = tid >> 1;       // A row this thread loads (0..127)
    const int half = tid & 1;        // which 16-float half of the 32-wide chunk
    const float* aRow = A + (size_t)(bm + ar) * lda;

    const int nc = K_pad >> 5;
    float rA[16];

    // ---------------- prologue: load chunk 0 ----------------
    {
        const int kb = half * 16;
#pragma unroll
        for (int q = 0; q < 4; q++) {
            int gk = kb + q * 4;
            float4 v = make_float4(0.f, 0.f, 0.f, 0.f);
            if (ar < rows_valid) {
                if (gk + 3 < Kin) v = *(const float4*)(aRow + gk);
                else {
                    float* vp = &v.x;
#pragma unroll
                    for (int e = 0; e < 4; e++) if (gk + e < Kin) vp[e] = aRow[gk + e];
                }
            }
            rA[q * 4 + 0] = v.x; rA[q * 4 + 1] = v.y;
            rA[q * 4 + 2] = v.z; rA[q * 4 + 3] = v.w;
        }
        // B chunk 0 cp.async
#pragma unroll
        for (int g = 0; g < 2; g++) {
            int id = tid + g * 256;
            int br = id >> 2, bc = id & 3;
            bool pred = (bn + br) < N;
            size_t go = (size_t)(bn + br) * K_pad + bc * 8;
            int phys = bc ^ ((br >> 1) & 3);
            uint32_t dst = sbase + (uint32_t)(br * 64 + phys * 16);
            cp_async16(dst + OFF_BHI, Bhi + go, pred);
            cp_async16(dst + OFF_BLO, Blo + go, pred);
        }
        CP_COMMIT();
    }

    for (int c = 0; c < nc; c++) {
        const int s = c & 1;
        const uint32_t stg = sbase + (uint32_t)(s * STAGE_B);
        char* stg_p = smp + s * STAGE_B;

        // ---- STS A chunk c from registers (relu + split) ----
        {
            float* v = rA;
            if (RELU_IN) {
#pragma unroll
                for (int e = 0; e < 16; e++) v[e] = fmaxf(v[e], 0.f);
            }
#pragma unroll
            for (int cc = 0; cc < 2; cc++) {
                uint32_t hi[4], lo[4];
#pragma unroll
                for (int p = 0; p < 4; p++) {
                    float f0 = v[cc * 8 + 2 * p], f1 = v[cc * 8 + 2 * p + 1];
                    float h0, h1;
                    hi[p] = packbf(f0, f1, h0, h1);
                    float dummy0, dummy1;
                    lo[p] = packbf(f0 - h0, f1 - h1, dummy0, dummy1);
                }
                int ch = half * 2 + cc;
                int phys = ch ^ ((ar >> 1) & 3);
                char* dst = stg_p + ar * 64 + phys * 16;
                *(uint4*)(dst)           = *(uint4*)hi;
                *(uint4*)(dst + OFF_ALO) = *(uint4*)lo;
            }
        }
        CP_WAIT0();        // B chunk c complete
        __syncthreads();

        // ---- issue loads for chunk c+1 ----
        if (c + 1 < nc) {
            const int col0 = (c + 1) << 5;
            const int kb = col0 + half * 16;
#pragma unroll
            for (int q = 0; q < 4; q++) {
                int gk = kb + q * 4;
                float4 v = make_float4(0.f, 0.f, 0.f, 0.f);
                if (ar < rows_valid) {
                    if (gk + 3 < Kin) v = *(const float4*)(aRow + gk);
                    else {
                        float* vp = &v.x;
#pragma unroll
                        for (int e = 0; e < 4; e++) if (gk + e < Kin) vp[e] = aRow[gk + e];
                    }
                }
                rA[q * 4 + 0] = v.x; rA[q * 4 + 1] = v.y;
                rA[q * 4 + 2] = v.z; rA[q * 4 + 3] = v.w;
            }
            const uint32_t ostg = sbase + (uint32_t)((s ^ 1) * STAGE_B);
#pragma unroll
            for (int g = 0; g < 2; g++) {
                int id = tid + g * 256;
                int br = id >> 2, bc = id & 3;
                bool pred = (bn + br) < N;
                size_t go = (size_t)(bn + br) * K_pad + col0 + bc * 8;
                int phys = bc ^ ((br >> 1) & 3);
                uint32_t dst = ostg + (uint32_t)(br * 64 + phys * 16);
                cp_async16(dst + OFF_BHI, Bhi + go, pred);
                cp_async16(dst + OFF_BLO, Blo + go, pred);
            }
            CP_COMMIT();
        }

        // ---- compute chunk c: 2 k16 steps x 3 passes ----
#pragma unroll
        for (int kk = 0; kk < 2; kk++) {
            uint32_t ah[2][4], al[2][4], bh[4][4], bl[4][4];
#pragma unroll
            for (int mi = 0; mi < 2; mi++) {
                int row = mw * 32 + mi * 16 + (lane & 15);
                int ch  = 2 * kk + (lane >> 4);
                int phys = ch ^ ((row >> 1) & 3);
                uint32_t off = stg + (uint32_t)(row * 64 + phys * 16);
                ldsm_x4(ah[mi], off);
                ldsm_x4(al[mi], off + OFF_ALO);
            }
#pragma unroll
            for (int t4 = 0; t4 < 4; t4++) {
                int row = nw * 64 + t4 * 16 + (lane & 7) + ((lane >> 4) << 3);
                int ch  = 2 * kk + ((lane >> 3) & 1);
                int phys = ch ^ ((row >> 1) & 3);
                uint32_t off = stg + (uint32_t)(row * 64 + phys * 16);
                ldsm_x4(bh[t4], off + OFF_BHI);
                ldsm_x4(bl[t4], off + OFF_BLO);
            }
#pragma unroll
            for (int mi = 0; mi < 2; mi++)
#pragma unroll
                for (int n8 = 0; n8 < 8; n8++) {
                    const uint32_t* pbh = &bh[n8 >> 1][(n8 & 1) * 2];
                    const uint32_t* pbl = &bl[n8 >> 1][(n8 & 1) * 2];
                    mma16816(acc[mi][n8], ah[mi], pbh);
                    mma16816(acc[mi][n8], ah[mi], pbl);
                    mma16816(acc[mi][n8], al[mi], pbh);
                }
        }
        __syncthreads();
    }

    // ---------------- epilogue ----------------
#pragma unroll
    for (int mi = 0; mi < 2; mi++) {
        int row0 = bm + mw * 32 + mi * 16 + (lane >> 2);
#pragma unroll
        for (int n8 = 0; n8 < 8; n8++) {
            int col = bn + nw * 64 + n8 * 8 + (lane & 3) * 2;
            if (col >= N) continue;
            float b0 = bias[col], b1 = bias[col + 1];
            float* d = acc[mi][n8];
            float v0 = d[0] + b0, v1 = d[1] + b1;
            float v2 = d[2] + b0, v3 = d[3] + b1;
            if (RELU_OUT) {
                v0 = fmaxf(v0, 0.f); v1 = fmaxf(v1, 0.f);
                v2 = fmaxf(v2, 0.f); v3 = fmaxf(v3, 0.f);
            }
            if (row0 < M)     *(float2*)(C + (size_t)row0 * ldc + col)       = make_float2(v0, v1);
            if (row0 + 8 < M) *(float2*)(C + (size_t)(row0 + 8) * ldc + col) = make_float2(v2, v3);
        }
    }
}

// ---------------------------------------------------------------------------
// Weight prep: W[Kin,N] fp32 -> Wt_hi/lo[N,K_pad] bf16 (transpose + split)
// ---------------------------------------------------------------------------
__global__ void prep_w_kernel(const float* __restrict__ W,
                              __nv_bfloat16* __restrict__ oh,
                              __nv_bfloat16* __restrict__ ol,
                              int Kin, int N, int K_pad,
                              size_t in_stride, size_t out_stride)
{
    int mat = blockIdx.y;
    const float* w = W + (size_t)mat * in_stride;
    __nv_bfloat16* ph = oh + (size_t)mat * out_stride;
    __nv_bfloat16* pl = ol + (size_t)mat * out_stride;
    int total = N * K_pad;
    int idx = blockIdx.x * blockDim.x + threadIdx.x;
    if (idx >= total) return;
    int n = idx / K_pad, k = idx - n * K_pad;
    float v = (k < Kin) ? w[(size_t)k * N + n] : 0.f;
    __nv_bfloat16 h = __float2bfloat16(v);
    ph[idx] = h;
    pl[idx] = __float2bfloat16(v - __bfloat162float(h));
}

// ---------------------------------------------------------------------------
__global__ void concat_verts_kernel(const float* __restrict__ verts)
{
    int v = blockIdx.x * blockDim.x + threadIdx.x;
    if (v < V_N) {
        size_t base = (size_t)v * LDH + 256;
#pragma unroll
        for (int c = 0; c < 3; c++) g_h[base + c] = verts[v * 3 + c];
        g_h[base + 3] = 0.f;
    }
}

// ---------------------------------------------------------------------------
// Edge scatter: out[i] += nbr[j]; out[j] += nbr[i]  (float4 loads, 4x atomicAdd)
// ---------------------------------------------------------------------------
__global__ void scatter_kernel(const int* __restrict__ edges,
                               const float* __restrict__ nbr,
                               float* __restrict__ out)
{
    int gt = blockIdx.x * blockDim.x + threadIdx.x;
    int e = gt >> 7;
    if (e >= E_N) return;
    int t = gt & 127;
    int dir = t >> 6;
    int u = (t & 63) << 2;
    int i = edges[2 * e];
    int j = edges[2 * e + 1];
    int src = dir ? i : j;
    int dst = dir ? j : i;
    float4 v = *(const float4*)(nbr + (size_t)src * H_N + u);
    float* o = out + (size_t)dst * H_N + u;
    atomicAdd(o + 0, v.x);
    atomicAdd(o + 1, v.y);
    atomicAdd(o + 2, v.z);
    atomicAdd(o + 3, v.w);
}

// ---------------------------------------------------------------------------
__global__ void delta_kernel(const float* __restrict__ h,
                             const float* __restrict__ Wo,
                             const float* __restrict__ bo,
                             float* __restrict__ out)
{
    __shared__ float sW[H_N * 3];
    __shared__ float sb[3];
    for (int i = threadIdx.x; i < H_N * 3; i += blockDim.x) sW[i] = Wo[i];
    if (threadIdx.x < 3) sb[threadIdx.x] = bo[threadIdx.x];
    __syncthreads();

    int idx = blockIdx.x * blockDim.x + threadIdx.x;
    if (idx >= V_N * 3) return;
    int v = idx / 3, c = idx % 3;
    const float* hr = h + (size_t)v * H_N;
    float s = sb[c];
#pragma unroll 8
    for (int k = 0; k < H_N; k++) s += fmaxf(hr[k], 0.f) * sW[k * 3 + c];
    out[idx] = s;
}

// ---------------------------------------------------------------------------
__global__ void tail_kernel(const float* __restrict__ z2,
                            const float* __restrict__ A3,
                            const float* __restrict__ a3,
                            const float* __restrict__ A4,
                            const float* __restrict__ a4,
                            float* __restrict__ conf)
{
    __shared__ float sA3[64 * 32];
    __shared__ float sa3[32];
    __shared__ float sA4[32];
    for (int i = threadIdx.x; i < 64 * 32; i += blockDim.x) sA3[i] = A3[i];
    if (threadIdx.x < 32) {
        sa3[threadIdx.x] = a3[threadIdx.x];
        sA4[threadIdx.x] = A4[threadIdx.x];
    }
    __syncthreads();

    float b4 = a4[0];
    for (int v = blockIdx.x * blockDim.x + threadIdx.x; v < V_N;
         v += gridDim.x * blockDim.x) {
        float x[64];
        const float* zr = z2 + (size_t)v * 64;
#pragma unroll
        for (int k = 0; k < 64; k++) x[k] = zr[k];
        float acc = b4;
#pragma unroll 4
        for (int m = 0; m < 32; m++) {
            float s = sa3[m];
#pragma unroll
            for (int k = 0; k < 64; k++) s = fmaf(x[k], sA3[k * 32 + m], s);
            acc = fmaf(fmaxf(s, 0.f), sA4[m], acc);
        }
        conf[v] = 1.f / (1.f + expf(-acc));
    }
}

// ---------------------------------------------------------------------------
// Launcher
// ---------------------------------------------------------------------------
extern "C" void kernel_launch(void* const* d_in, const int* in_sizes, int n_in,
                              void* d_out, int out_size)
{
    (void)in_sizes; (void)n_in; (void)out_size;
    const float* X     = (const float*)d_in[0];
    const float* verts = (const float*)d_in[1];
    const int*   edges = (const int*)  d_in[2];
    const float* Wb    = (const float*)d_in[3];
    const float* bb    = (const float*)d_in[4];
    const float* W0_0  = (const float*)d_in[5];
    const float* b0_0  = (const float*)d_in[6];
    const float* W1_0  = (const float*)d_in[7];
    const float* b1_0  = (const float*)d_in[8];
    const float* gW0   = (const float*)d_in[9];
    const float* gb0   = (const float*)d_in[10];
    const float* gW1   = (const float*)d_in[11];
    const float* gb1   = (const float*)d_in[12];
    const float* Wo    = (const float*)d_in[13];
    const float* bo    = (const float*)d_in[14];
    const float* A1    = (const float*)d_in[15];
    const float* a1    = (const float*)d_in[16];
    const float* A2    = (const float*)d_in[17];
    const float* a2    = (const float*)d_in[18];
    const float* A3    = (const float*)d_in[19];
    const float* a3    = (const float*)d_in[20];
    const float* A4    = (const float*)d_in[21];
    const float* a4    = (const float*)d_in[22];
    float* out = (float*)d_out;

    float *p_h, *p_x, *p_y, *p_nbr, *p_z2;
    cudaGetSymbolAddress((void**)&p_h,   g_h);
    cudaGetSymbolAddress((void**)&p_x,   g_x);
    cudaGetSymbolAddress((void**)&p_y,   g_y);
    cudaGetSymbolAddress((void**)&p_nbr, g_nbr);
    cudaGetSymbolAddress((void**)&p_z2,  g_z2);

    __nv_bfloat16 *pwb_h, *pwb_l, *pw0_h, *pw0_l, *pw1_h, *pw1_l;
    __nv_bfloat16 *pg0_h, *pg0_l, *pg1_h, *pg1_l, *pa1_h, *pa1_l, *pa2_h, *pa2_l;
    cudaGetSymbolAddress((void**)&pwb_h, wb_h);  cudaGetSymbolAddress((void**)&pwb_l, wb_l);
    cudaGetSymbolAddress((void**)&pw0_h, w0_h);  cudaGetSymbolAddress((void**)&pw0_l, w0_l);
    cudaGetSymbolAddress((void**)&pw1_h, w1_h);  cudaGetSymbolAddress((void**)&pw1_l, w1_l);
    cudaGetSymbolAddress((void**)&pg0_h, gw0_h); cudaGetSymbolAddress((void**)&pg0_l, gw0_l);
    cudaGetSymbolAddress((void**)&pg1_h, gw1_h); cudaGetSymbolAddress((void**)&pg1_l, gw1_l);
    cudaGetSymbolAddress((void**)&pa1_h, a1_h);  cudaGetSymbolAddress((void**)&pa1_l, a1_l);
    cudaGetSymbolAddress((void**)&pa2_h, a2_h);  cudaGetSymbolAddress((void**)&pa2_l, a2_l);

    const int SMEM = 65536;
    cudaFuncSetAttribute(gemm_mma<false, true >, cudaFuncAttributeMaxDynamicSharedMemorySize, SMEM);
    cudaFuncSetAttribute(gemm_mma<false, false>, cudaFuncAttributeMaxDynamicSharedMemorySize, SMEM);
    cudaFuncSetAttribute(gemm_mma<true,  false>, cudaFuncAttributeMaxDynamicSharedMemorySize, SMEM);
    cudaFuncSetAttribute(gemm_mma<true,  true >, cudaFuncAttributeMaxDynamicSharedMemorySize, SMEM);

    const int MT = (V_N + 127) / 128;   // 161
    const dim3 blk(256);
    const dim3 g2(2, MT);   // N=256
    const dim3 g1(1, MT);   // N<=128

    // ---- weight prep (transpose + hi/lo split) ----
    {
        int n;
        n = 256 * 3840;
        prep_w_kernel<<<dim3((n + 255) / 256, 1), 256>>>(Wb, pwb_h, pwb_l, 3840, 256, 3840, 0, 0);
        n = 256 * 288;
        prep_w_kernel<<<dim3((n + 255) / 256, 1), 256>>>(W0_0, pw0_h, pw0_l, 259, 256, 288, 0, 0);
        prep_w_kernel<<<dim3((n + 255) / 256, 1), 256>>>(W1_0, pw1_h, pw1_l, 259, 256, 288, 0, 0);
        n = 256 * 256;
        prep_w_kernel<<<dim3((n + 255) / 256, 9), 256>>>(gW0, pg0_h, pg0_l, 256, 256, 256, 65536, 65536);
        prep_w_kernel<<<dim3((n + 255) / 256, 9), 256>>>(gW1, pg1_h, pg1_l, 256, 256, 256, 65536, 65536);
        prep_w_kernel<<<dim3((n + 255) / 256, 1), 256>>>(A1, pa1_h, pa1_l, 256, 256, 256, 0, 0);
        n = 64 * 256;
        prep_w_kernel<<<dim3((n + 255) / 256, 1), 256>>>(A2, pa2_h, pa2_l, 256, 64, 256, 0, 0);
    }

    // 1) backbone: g_h[:, :256] = relu(X @ Wb + bb)
    gemm_mma<false, true><<<g2, blk, SMEM>>>(
        X, pwb_h, pwb_l, bb, p_h, V_N, 256, 3840, 3840, 3840, LDH);

    // 2) concat verts
    concat_verts_kernel<<<(V_N + 255) / 256, 256>>>(verts);

    // 3) layer 0 (Kin=259, K_pad=288, input already activated)
    gemm_mma<false, false><<<g2, blk, SMEM>>>(
        p_h, pw0_h, pw0_l, b0_0, p_x, V_N, 256, 259, 288, LDH, 256);
    gemm_mma<false, false><<<g2, blk, SMEM>>>(
        p_h, pw1_h, pw1_l, b1_0, p_nbr, V_N, 256, 259, 288, LDH, 256);
    scatter_kernel<<<(E_N * 128) / 256, 256>>>(edges, p_nbr, p_x);

    // 4) layers 1..9 (relu fused on A-read)
    float* cur = p_x;
    float* nxt = p_y;
    for (int k = 0; k < 9; k++) {
        const __nv_bfloat16* W0h = pg0_h + (size_t)k * 65536;
        const __nv_bfloat16* W0l = pg0_l + (size_t)k * 65536;
        const __nv_bfloat16* W1h = pg1_h + (size_t)k * 65536;
        const __nv_bfloat16* W1l = pg1_l + (size_t)k * 65536;
        const float* B0 = gb0 + (size_t)k * H_N;
        const float* B1 = gb1 + (size_t)k * H_N;
        gemm_mma<true, false><<<g2, blk, SMEM>>>(
            cur, W0h, W0l, B0, nxt, V_N, 256, 256, 256, 256, 256);
        gemm_mma<true, false><<<g2, blk, SMEM>>>(
            cur, W1h, W1l, B1, p_nbr, V_N, 256, 256, 256, 256, 256);
        scatter_kernel<<<(E_N * 128) / 256, 256>>>(edges, p_nbr, nxt);
        float* t = cur; cur = nxt; nxt = t;
    }
    // final pre-relu h in `cur`

    // 5) delta_v -> out[0 : V*3]
    delta_kernel<<<(V_N * 3 + 255) / 256, 256>>>(cur, Wo, bo, out);

    // 6) z1 = relu(relu(h) @ A1 + a1) -> g_nbr
    gemm_mma<true, true><<<g2, blk, SMEM>>>(
        cur, pa1_h, pa1_l, a1, p_nbr, V_N, 256, 256, 256, 256, 256);

    // 7) z2 = relu(z1 @ A2 + a2) -> g_z2
    gemm_mma<false, true><<<g1, blk, SMEM>>>(
        p_nbr, pa2_h, pa2_l, a2, p_z2, V_N, 64, 256, 256, 256, 64);

    // 8) conf -> out[V*3 : V*4]
    tail_kernel<<<128, 256>>>(p_z2, A3, a3, A4, a4, out + (size_t)V_N * 3);
}

// round 4
// speedup vs baseline: 2.4693x; 1.1528x over previous
#include <cuda_runtime.h>
#include <cuda_bf16.h>
#include <math.h>
#include <stdint.h>

#define V_N 20496
#define E_N 61440
#define F_N 3840
#define H_N 256

// ---------------------------------------------------------------------------
// Scratch (static device globals — no allocation allowed)
// ---------------------------------------------------------------------------
// pre-split activations (bf16 hi/lo)
__device__ __align__(16) __nv_bfloat16 g_xh [(size_t)V_N * F_N];
__device__ __align__(16) __nv_bfloat16 g_xl [(size_t)V_N * F_N];
__device__ __align__(16) __nv_bfloat16 g_h0h[(size_t)V_N * 288];
__device__ __align__(16) __nv_bfloat16 g_h0l[(size_t)V_N * 288];
__device__ __align__(16) __nv_bfloat16 g_ah [(size_t)V_N * H_N];
__device__ __align__(16) __nv_bfloat16 g_al [(size_t)V_N * H_N];
__device__ __align__(16) __nv_bfloat16 g_bh [(size_t)V_N * H_N];
__device__ __align__(16) __nv_bfloat16 g_bl [(size_t)V_N * H_N];
__device__ __align__(16) __nv_bfloat16 g_z1h[(size_t)V_N * H_N];
__device__ __align__(16) __nv_bfloat16 g_z1l[(size_t)V_N * H_N];
// fp32 intermediates
__device__ __align__(16) float g_t0 [(size_t)V_N * H_N];
__device__ __align__(16) float g_t1 [(size_t)V_N * H_N];
__device__ __align__(16) float g_z2 [(size_t)V_N * 64];

// weight scratch: transposed [N, K_pad] bf16 hi/lo
__device__ __align__(16) __nv_bfloat16 wb_h [256 * 3840];
__device__ __align__(16) __nv_bfloat16 wb_l [256 * 3840];
__device__ __align__(16) __nv_bfloat16 w0_h [256 * 288];
__device__ __align__(16) __nv_bfloat16 w0_l [256 * 288];
__device__ __align__(16) __nv_bfloat16 w1_h [256 * 288];
__device__ __align__(16) __nv_bfloat16 w1_l [256 * 288];
__device__ __align__(16) __nv_bfloat16 gw0_h[9 * 256 * 256];
__device__ __align__(16) __nv_bfloat16 gw0_l[9 * 256 * 256];
__device__ __align__(16) __nv_bfloat16 gw1_h[9 * 256 * 256];
__device__ __align__(16) __nv_bfloat16 gw1_l[9 * 256 * 256];
__device__ __align__(16) __nv_bfloat16 a1_h [256 * 256];
__device__ __align__(16) __nv_bfloat16 a1_l [256 * 256];
__device__ __align__(16) __nv_bfloat16 a2_h [64 * 256];
__device__ __align__(16) __nv_bfloat16 a2_l [64 * 256];

// ---------------------------------------------------------------------------
// PTX helpers (plain compute_103-legal: mma.sync / ldmatrix / cp.async)
// ---------------------------------------------------------------------------
__device__ __forceinline__ void ldsm_x4(uint32_t* r, uint32_t addr) {
    asm volatile("ldmatrix.sync.aligned.m8n8.x4.shared.b16 {%0,%1,%2,%3}, [%4];"
        : "=r"(r[0]), "=r"(r[1]), "=r"(r[2]), "=r"(r[3]) : "r"(addr));
}
__device__ __forceinline__ void mma16816(float* d, const uint32_t* a, const uint32_t* b) {
    asm volatile(
        "mma.sync.aligned.m16n8k16.row.col.f32.bf16.bf16.f32 "
        "{%0,%1,%2,%3}, {%4,%5,%6,%7}, {%8,%9}, {%0,%1,%2,%3};"
        : "+f"(d[0]), "+f"(d[1]), "+f"(d[2]), "+f"(d[3])
        : "r"(a[0]), "r"(a[1]), "r"(a[2]), "r"(a[3]), "r"(b[0]), "r"(b[1]));
}
__device__ __forceinline__ void cp_async16(uint32_t dst, const void* src, bool pred) {
    int sz = pred ? 16 : 0;
    asm volatile("cp.async.cg.shared.global [%0], [%1], 16, %2;"
                 :: "r"(dst), "l"(src), "r"(sz));
}
#define CP_COMMIT() asm volatile("cp.async.commit_group;")
#define CP_WAIT(n)  asm volatile("cp.async.wait_group %0;" :: "n"(n))

__device__ __forceinline__ uint32_t pack2(float f0, float f1) {
    __nv_bfloat162 p;
    p.x = __float2bfloat16(f0);
    p.y = __float2bfloat16(f1);
    return *(uint32_t*)&p;
}

// ---------------------------------------------------------------------------
// Split-bf16 3-pass mma.sync GEMM; A and B both pre-split bf16 hi/lo.
// C = A[M,K] @ W^T + bias.   CTA tile 128x128, K-chunk 32, 8 warps,
// double-buffered cp.async.  OUT_MODE: 0=fp32, 1=fp32+relu, 2=bf16 split+relu.
// SMEM stage: Ahi(8K) Alo(8K) Bhi(8K) Blo(8K); 64B rows, XOR swizzle.
// ---------------------------------------------------------------------------
#define OFF_ALO 8192
#define OFF_BHI 16384
#define OFF_BLO 24576
#define STAGE_B 32768

template<int OUT_MODE>
__global__ void __launch_bounds__(256, 2)
gemm_bb(const __nv_bfloat16* __restrict__ Ahi, const __nv_bfloat16* __restrict__ Alo,
        const __nv_bfloat16* __restrict__ Bhi, const __nv_bfloat16* __restrict__ Blo,
        const float* __restrict__ bias,
        float* __restrict__ Cf, __nv_bfloat16* __restrict__ Chi, __nv_bfloat16* __restrict__ Clo,
        int M, int N, int K_pad, int lda, int ldc)
{
    extern __shared__ char smp[];
    const uint32_t sbase = (uint32_t)__cvta_generic_to_shared(smp);

    const int tid  = threadIdx.x;
    const int lane = tid & 31;
    const int w    = tid >> 5;
    const int mw   = w & 3;
    const int nw   = w >> 2;
    const int bm   = blockIdx.y * 128;
    const int bn   = blockIdx.x * 128;

    float acc[2][8][4];
#pragma unroll
    for (int a = 0; a < 2; a++)
#pragma unroll
        for (int b = 0; b < 8; b++)
#pragma unroll
            for (int c = 0; c < 4; c++) acc[a][b][c] = 0.f;

    const int nc = K_pad >> 5;

    // loader: slot id -> (row, 16B-col); 512 slots for A, 512 for B
    const int r0 = tid >> 1;            // used twice: rows r0, r0 (g=0,1 -> +0/+128?) no:
    // slots: id = tid + g*256; br = id >> 2; bc = id & 3
#define LOAD_CHUNK(cidx, stg_u32)                                                   \
    {                                                                               \
        const int col0 = (cidx) << 5;                                               \
        _Pragma("unroll")                                                           \
        for (int g = 0; g < 2; g++) {                                               \
            int id = tid + g * 256;                                                 \
            int br = id >> 2, bc = id & 3;                                          \
            uint32_t dst = (stg_u32) + (uint32_t)(br * 64 + ((bc ^ ((br >> 1) & 3)) << 4)); \
            bool pa = (bm + br) < M;                                                \
            size_t ga = (size_t)(bm + br) * lda + col0 + bc * 8;                    \
            cp_async16(dst,           Ahi + ga, pa);                                \
            cp_async16(dst + OFF_ALO, Alo + ga, pa);                                \
            bool pb = (bn + br) < N;                                                \
            size_t gb = (size_t)(bn + br) * K_pad + col0 + bc * 8;                  \
            cp_async16(dst + OFF_BHI, Bhi + gb, pb);                                \
            cp_async16(dst + OFF_BLO, Blo + gb, pb);                                \
        }                                                                           \
        CP_COMMIT();                                                                \
    }

    LOAD_CHUNK(0, sbase);

    for (int c = 0; c < nc; c++) {
        const int s = c & 1;
        const uint32_t stg = sbase + (uint32_t)(s * STAGE_B);

        if (c + 1 < nc) {
            LOAD_CHUNK(c + 1, sbase + (uint32_t)((s ^ 1) * STAGE_B));
            CP_WAIT(1);
        } else {
            CP_WAIT(0);
        }
        __syncthreads();

#pragma unroll
        for (int kk = 0; kk < 2; kk++) {
            uint32_t ah[2][4], al[2][4];
#pragma unroll
            for (int mi = 0; mi < 2; mi++) {
                int row = mw * 32 + mi * 16 + (lane & 15);
                int ch  = 2 * kk + (lane >> 4);
                int phys = ch ^ ((row >> 1) & 3);
                uint32_t off = stg + (uint32_t)(row * 64 + phys * 16);
                ldsm_x4(ah[mi], off);
                ldsm_x4(al[mi], off + OFF_ALO);
            }
#pragma unroll
            for (int h2 = 0; h2 < 2; h2++) {
                uint32_t bh[2][4], bl[2][4];
#pragma unroll
                for (int t4 = 0; t4 < 2; t4++) {
                    int row = nw * 64 + (h2 * 2 + t4) * 16 + (lane & 7) + ((lane >> 4) << 3);
                    int ch  = 2 * kk + ((lane >> 3) & 1);
                    int phys = ch ^ ((row >> 1) & 3);
                    uint32_t off = stg + (uint32_t)(row * 64 + phys * 16);
                    ldsm_x4(bh[t4], off + OFF_BHI);
                    ldsm_x4(bl[t4], off + OFF_BLO);
                }
#pragma unroll
                for (int mi = 0; mi < 2; mi++)
#pragma unroll
                    for (int q = 0; q < 4; q++) {
                        const uint32_t* pbh = &bh[q >> 1][(q & 1) * 2];
                        const uint32_t* pbl = &bl[q >> 1][(q & 1) * 2];
                        float* d = acc[mi][h2 * 4 + q];
                        mma16816(d, ah[mi], pbh);
                        mma16816(d, ah[mi], pbl);
                        mma16816(d, al[mi], pbh);
                    }
            }
        }
        __syncthreads();
    }

    // ---------------- epilogue ----------------
#pragma unroll
    for (int mi = 0; mi < 2; mi++) {
        int row0 = bm + mw * 32 + mi * 16 + (lane >> 2);
#pragma unroll
        for (int n8 = 0; n8 < 8; n8++) {
            int col = bn + nw * 64 + n8 * 8 + (lane & 3) * 2;
            if (col >= N) continue;
            float b0 = bias[col], b1 = bias[col + 1];
            float* d = acc[mi][n8];
            float v0 = d[0] + b0, v1 = d[1] + b1;
            float v2 = d[2] + b0, v3 = d[3] + b1;
            if (OUT_MODE >= 1) {
                v0 = fmaxf(v0, 0.f); v1 = fmaxf(v1, 0.f);
                v2 = fmaxf(v2, 0.f); v3 = fmaxf(v3, 0.f);
            }
            if (OUT_MODE == 2) {
                uint32_t h01 = pack2(v0, v1);
                float r0f = __bfloat162float(((__nv_bfloat162*)&h01)->x);
                float r1f = __bfloat162float(((__nv_bfloat162*)&h01)->y);
                uint32_t l01 = pack2(v0 - r0f, v1 - r1f);
                uint32_t h23 = pack2(v2, v3);
                float r2f = __bfloat162float(((__nv_bfloat162*)&h23)->x);
                float r3f = __bfloat162float(((__nv_bfloat162*)&h23)->y);
                uint32_t l23 = pack2(v2 - r2f, v3 - r3f);
                if (row0 < M) {
                    *(uint32_t*)(Chi + (size_t)row0 * ldc + col) = h01;
                    *(uint32_t*)(Clo + (size_t)row0 * ldc + col) = l01;
                }
                if (row0 + 8 < M) {
                    *(uint32_t*)(Chi + (size_t)(row0 + 8) * ldc + col) = h23;
                    *(uint32_t*)(Clo + (size_t)(row0 + 8) * ldc + col) = l23;
                }
            } else {
                if (row0 < M)     *(float2*)(Cf + (size_t)row0 * ldc + col)       = make_float2(v0, v1);
                if (row0 + 8 < M) *(float2*)(Cf + (size_t)(row0 + 8) * ldc + col) = make_float2(v2, v3);
            }
        }
    }
}

// ---------------------------------------------------------------------------
// Weight prep: W[Kin,N] fp32 -> Wt_hi/lo[N,K_pad] bf16 (transpose + split)
// ---------------------------------------------------------------------------
__global__ void prep_w_kernel(const float* __restrict__ W,
                              __nv_bfloat16* __restrict__ oh,
                              __nv_bfloat16* __restrict__ ol,
                              int Kin, int N, int K_pad,
                              size_t in_stride, size_t out_stride)
{
    int mat = blockIdx.y;
    const float* w = W + (size_t)mat * in_stride;
    __nv_bfloat16* ph = oh + (size_t)mat * out_stride;
    __nv_bfloat16* pl = ol + (size_t)mat * out_stride;
    int total = N * K_pad;
    int idx = blockIdx.x * blockDim.x + threadIdx.x;
    if (idx >= total) return;
    int n = idx / K_pad, k = idx - n * K_pad;
    float v = (k < Kin) ? w[(size_t)k * N + n] : 0.f;
    __nv_bfloat16 h = __float2bfloat16(v);
    ph[idx] = h;
    pl[idx] = __float2bfloat16(v - __bfloat162float(h));
}

// ---------------------------------------------------------------------------
// Split fp32 -> bf16 hi/lo, optional relu. Vectorized x4.
// ---------------------------------------------------------------------------
template<bool RELU>
__global__ void split_kernel(const float* __restrict__ in,
                             __nv_bfloat16* __restrict__ oh,
                             __nv_bfloat16* __restrict__ ol, int n4)
{
    int idx = blockIdx.x * blockDim.x + threadIdx.x;
    if (idx >= n4) return;
    float4 v = ((const float4*)in)[idx];
    if (RELU) {
        v.x = fmaxf(v.x, 0.f); v.y = fmaxf(v.y, 0.f);
        v.z = fmaxf(v.z, 0.f); v.w = fmaxf(v.w, 0.f);
    }
    uint32_t h01 = pack2(v.x, v.y);
    uint32_t h23 = pack2(v.z, v.w);
    __nv_bfloat162 hh01 = *(__nv_bfloat162*)&h01;
    __nv_bfloat162 hh23 = *(__nv_bfloat162*)&h23;
    uint32_t l01 = pack2(v.x - __bfloat162float(hh01.x), v.y - __bfloat162float(hh01.y));
    uint32_t l23 = pack2(v.z - __bfloat162float(hh23.x), v.w - __bfloat162float(hh23.y));
    ((uint2*)oh)[idx] = make_uint2(h01, h23);
    ((uint2*)ol)[idx] = make_uint2(l01, l23);
}

// ---------------------------------------------------------------------------
// concat verts (split) into h0 cols 256..287
// ---------------------------------------------------------------------------
__global__ void concat_verts_kernel(const float* __restrict__ verts)
{
    int idx = blockIdx.x * blockDim.x + threadIdx.x;  // V * 32
    if (idx >= V_N * 32) return;
    int v = idx >> 5, c = idx & 31;
    float x = (c < 3) ? verts[v * 3 + c] : 0.f;
    __nv_bfloat16 h = __float2bfloat16(x);
    __nv_bfloat16 l = __float2bfloat16(x - __bfloat162float(h));
    size_t o = (size_t)v * 288 + 256 + c;
    g_h0h[o] = h;
    g_h0l[o] = l;
}

// ---------------------------------------------------------------------------
// Edge scatter: out[i] += nbr[j]; out[j] += nbr[i]
// ---------------------------------------------------------------------------
__global__ void scatter_kernel(const int* __restrict__ edges,
                               const float* __restrict__ nbr,
                               float* __restrict__ out)
{
    int gt = blockIdx.x * blockDim.x + threadIdx.x;
    int e = gt >> 7;
    if (e >= E_N) return;
    int t = gt & 127;
    int dir = t >> 6;
    int u = (t & 63) << 2;
    int i = edges[2 * e];
    int j = edges[2 * e + 1];
    int src = dir ? i : j;
    int dst = dir ? j : i;
    float4 v = *(const float4*)(nbr + (size_t)src * H_N + u);
    float* o = out + (size_t)dst * H_N + u;
    atomicAdd(o + 0, v.x);
    atomicAdd(o + 1, v.y);
    atomicAdd(o + 2, v.z);
    atomicAdd(o + 3, v.w);
}

// ---------------------------------------------------------------------------
// delta_v = h @ Wo + bo    (h given as split hi/lo, relu already applied)
// ---------------------------------------------------------------------------
__global__ void delta_kernel(const __nv_bfloat16* __restrict__ hh,
                             const __nv_bfloat16* __restrict__ hl,
                             const float* __restrict__ Wo,
                             const float* __restrict__ bo,
                             float* __restrict__ out)
{
    __shared__ float sW[H_N * 3];
    __shared__ float sb[3];
    for (int i = threadIdx.x; i < H_N * 3; i += blockDim.x) sW[i] = Wo[i];
    if (threadIdx.x < 3) sb[threadIdx.x] = bo[threadIdx.x];
    __syncthreads();

    int idx = blockIdx.x * blockDim.x + threadIdx.x;
    if (idx >= V_N * 3) return;
    int v = idx / 3, c = idx % 3;
    const __nv_bfloat162* ph = (const __nv_bfloat162*)(hh + (size_t)v * H_N);
    const __nv_bfloat162* pl = (const __nv_bfloat162*)(hl + (size_t)v * H_N);
    float s = sb[c];
#pragma unroll 4
    for (int k = 0; k < H_N / 2; k++) {
        __nv_bfloat162 a = ph[k], b = pl[k];
        float x0 = __bfloat162float(a.x) + __bfloat162float(b.x);
        float x1 = __bfloat162float(a.y) + __bfloat162float(b.y);
        s = fmaf(x0, sW[(2 * k) * 3 + c], s);
        s = fmaf(x1, sW[(2 * k + 1) * 3 + c], s);
    }
    out[idx] = s;
}

// ---------------------------------------------------------------------------
__global__ void tail_kernel(const float* __restrict__ z2,
                            const float* __restrict__ A3,
                            const float* __restrict__ a3,
                            const float* __restrict__ A4,
                            const float* __restrict__ a4,
                            float* __restrict__ conf)
{
    __shared__ float sA3[64 * 32];
    __shared__ float sa3[32];
    __shared__ float sA4[32];
    for (int i = threadIdx.x; i < 64 * 32; i += blockDim.x) sA3[i] = A3[i];
    if (threadIdx.x < 32) {
        sa3[threadIdx.x] = a3[threadIdx.x];
        sA4[threadIdx.x] = A4[threadIdx.x];
    }
    __syncthreads();

    float b4 = a4[0];
    for (int v = blockIdx.x * blockDim.x + threadIdx.x; v < V_N;
         v += gridDim.x * blockDim.x) {
        float x[64];
        const float* zr = z2 + (size_t)v * 64;
#pragma unroll
        for (int k = 0; k < 64; k++) x[k] = zr[k];
        float acc = b4;
#pragma unroll 4
        for (int m = 0; m < 32; m++) {
            float s = sa3[m];
#pragma unroll
            for (int k = 0; k < 64; k++) s = fmaf(x[k], sA3[k * 32 + m], s);
            acc = fmaf(fmaxf(s, 0.f), sA4[m], acc);
        }
        conf[v] = 1.f / (1.f + expf(-acc));
    }
}

// ---------------------------------------------------------------------------
// Launcher
// ---------------------------------------------------------------------------
extern "C" void kernel_launch(void* const* d_in, const int* in_sizes, int n_in,
                              void* d_out, int out_size)
{
    (void)in_sizes; (void)n_in; (void)out_size;
    const float* X     = (const float*)d_in[0];
    const float* verts = (const float*)d_in[1];
    const int*   edges = (const int*)  d_in[2];
    const float* Wb    = (const float*)d_in[3];
    const float* bb    = (const float*)d_in[4];
    const float* W0_0  = (const float*)d_in[5];
    const float* b0_0  = (const float*)d_in[6];
    const float* W1_0  = (const float*)d_in[7];
    const float* b1_0  = (const float*)d_in[8];
    const float* gW0   = (const float*)d_in[9];
    const float* gb0   = (const float*)d_in[10];
    const float* gW1   = (const float*)d_in[11];
    const float* gb1   = (const float*)d_in[12];
    const float* Wo    = (const float*)d_in[13];
    const float* bo    = (const float*)d_in[14];
    const float* A1    = (const float*)d_in[15];
    const float* a1    = (const float*)d_in[16];
    const float* A2    = (const float*)d_in[17];
    const float* a2    = (const float*)d_in[18];
    const float* A3    = (const float*)d_in[19];
    const float* a3    = (const float*)d_in[20];
    const float* A4    = (const float*)d_in[21];
    const float* a4    = (const float*)d_in[22];
    float* out = (float*)d_out;

    __nv_bfloat16 *pxh, *pxl, *ph0h, *ph0l, *pah, *pal, *pbh, *pbl, *pz1h, *pz1l;
    float *pt0, *pt1, *pz2;
    cudaGetSymbolAddress((void**)&pxh,  g_xh);   cudaGetSymbolAddress((void**)&pxl,  g_xl);
    cudaGetSymbolAddress((void**)&ph0h, g_h0h);  cudaGetSymbolAddress((void**)&ph0l, g_h0l);
    cudaGetSymbolAddress((void**)&pah,  g_ah);   cudaGetSymbolAddress((void**)&pal,  g_al);
    cudaGetSymbolAddress((void**)&pbh,  g_bh);   cudaGetSymbolAddress((void**)&pbl,  g_bl);
    cudaGetSymbolAddress((void**)&pz1h, g_z1h);  cudaGetSymbolAddress((void**)&pz1l, g_z1l);
    cudaGetSymbolAddress((void**)&pt0,  g_t0);   cudaGetSymbolAddress((void**)&pt1,  g_t1);
    cudaGetSymbolAddress((void**)&pz2,  g_z2);

    __nv_bfloat16 *pwb_h, *pwb_l, *pw0_h, *pw0_l, *pw1_h, *pw1_l;
    __nv_bfloat16 *pg0_h, *pg0_l, *pg1_h, *pg1_l, *pa1_h, *pa1_l, *pa2_h, *pa2_l;
    cudaGetSymbolAddress((void**)&pwb_h, wb_h);  cudaGetSymbolAddress((void**)&pwb_l, wb_l);
    cudaGetSymbolAddress((void**)&pw0_h, w0_h);  cudaGetSymbolAddress((void**)&pw0_l, w0_l);
    cudaGetSymbolAddress((void**)&pw1_h, w1_h);  cudaGetSymbolAddress((void**)&pw1_l, w1_l);
    cudaGetSymbolAddress((void**)&pg0_h, gw0_h); cudaGetSymbolAddress((void**)&pg0_l, gw0_l);
    cudaGetSymbolAddress((void**)&pg1_h, gw1_h); cudaGetSymbolAddress((void**)&pg1_l, gw1_l);
    cudaGetSymbolAddress((void**)&pa1_h, a1_h);  cudaGetSymbolAddress((void**)&pa1_l, a1_l);
    cudaGetSymbolAddress((void**)&pa2_h, a2_h);  cudaGetSymbolAddress((void**)&pa2_l, a2_l);

    const int SMEM = 65536;
    cudaFuncSetAttribute(gemm_bb<0>, cudaFuncAttributeMaxDynamicSharedMemorySize, SMEM);
    cudaFuncSetAttribute(gemm_bb<1>, cudaFuncAttributeMaxDynamicSharedMemorySize, SMEM);
    cudaFuncSetAttribute(gemm_bb<2>, cudaFuncAttributeMaxDynamicSharedMemorySize, SMEM);

    const int MT = (V_N + 127) / 128;   // 161
    const dim3 blk(256);
    const dim3 g2(2, MT);   // N=256
    const dim3 g1(1, MT);   // N<=128

    // ---- weight prep ----
    {
        int n;
        n = 256 * 3840;
        prep_w_kernel<<<dim3((n + 255) / 256, 1), 256>>>(Wb, pwb_h, pwb_l, 3840, 256, 3840, 0, 0);
        n = 256 * 288;
        prep_w_kernel<<<dim3((n + 255) / 256, 1), 256>>>(W0_0, pw0_h, pw0_l, 259, 256, 288, 0, 0);
        prep_w_kernel<<<dim3((n + 255) / 256, 1), 256>>>(W1_0, pw1_h, pw1_l, 259, 256, 288, 0, 0);
        n = 256 * 256;
        prep_w_kernel<<<dim3((n + 255) / 256, 9), 256>>>(gW0, pg0_h, pg0_l, 256, 256, 256, 65536, 65536);
        prep_w_kernel<<<dim3((n + 255) / 256, 9), 256>>>(gW1, pg1_h, pg1_l, 256, 256, 256, 65536, 65536);
        prep_w_kernel<<<dim3((n + 255) / 256, 1), 256>>>(A1, pa1_h, pa1_l, 256, 256, 256, 0, 0);
        n = 64 * 256;
        prep_w_kernel<<<dim3((n + 255) / 256, 1), 256>>>(A2, pa2_h, pa2_l, 256, 64, 256, 0, 0);
    }

    // ---- split X (no relu) ----
    {
        int n4 = (V_N * F_N) / 4;
        split_kernel<false><<<(n4 + 255) / 256, 256>>>(X, pxh, pxl, n4);
    }

    // 1) backbone: h0[:, :256] = relu(X @ Wb + bb), written split
    gemm_bb<2><<<g2, blk, SMEM>>>(pxh, pxl, pwb_h, pwb_l, bb,
                                  nullptr, ph0h, ph0l, V_N, 256, 3840, 3840, 288);
    // 2) concat verts (split) into cols 256..287
    concat_verts_kernel<<<(V_N * 32 + 255) / 256, 256>>>(verts);

    // 3) layer 0 (K_pad=288)
    gemm_bb<0><<<g2, blk, SMEM>>>(ph0h, ph0l, pw0_h, pw0_l, b0_0,
                                  pt0, nullptr, nullptr, V_N, 256, 288, 288, 256);
    gemm_bb<0><<<g2, blk, SMEM>>>(ph0h, ph0l, pw1_h, pw1_l, b1_0,
                                  pt1, nullptr, nullptr, V_N, 256, 288, 288, 256);
    scatter_kernel<<<(E_N * 128) / 256, 256>>>(edges, pt1, pt0);
    {
        int n4 = (V_N * H_N) / 4;
        split_kernel<true><<<(n4 + 255) / 256, 256>>>(pt0, pah, pal, n4);
    }

    // 4) layers 1..9
    __nv_bfloat16 *curh = pah, *curl = pal, *nxth = pbh, *nxtl = pbl;
    const int n4h = (V_N * H_N) / 4;
    for (int k = 0; k < 9; k++) {
        const __nv_bfloat16* W0h = pg0_h + (size_t)k * 65536;
        const __nv_bfloat16* W0l = pg0_l + (size_t)k * 65536;
        const __nv_bfloat16* W1h = pg1_h + (size_t)k * 65536;
        const __nv_bfloat16* W1l = pg1_l + (size_t)k * 65536;
        const float* B0 = gb0 + (size_t)k * H_N;
        const float* B1 = gb1 + (size_t)k * H_N;
        gemm_bb<0><<<g2, blk, SMEM>>>(curh, curl, W0h, W0l, B0,
                                      pt0, nullptr, nullptr, V_N, 256, 256, 256, 256);
        gemm_bb<0><<<g2, blk, SMEM>>>(curh, curl, W1h, W1l, B1,
                                      pt1, nullptr, nullptr, V_N, 256, 256, 256, 256);
        scatter_kernel<<<(E_N * 128) / 256, 256>>>(edges, pt1, pt0);
        split_kernel<true><<<(n4h + 255) / 256, 256>>>(pt0, nxth, nxtl, n4h);
        __nv_bfloat16* t;
        t = curh; curh = nxth; nxth = t;
        t = curl; curl = nxtl; nxtl = t;
    }
    // final relu(h) split in (curh, curl)

    // 5) delta_v -> out[0 : V*3]
    delta_kernel<<<(V_N * 3 + 255) / 256, 256>>>(curh, curl, Wo, bo, out);

    // 6) z1 = relu(h_relu @ A1 + a1), written split
    gemm_bb<2><<<g2, blk, SMEM>>>(curh, curl, pa1_h, pa1_l, a1,
                                  nullptr, pz1h, pz1l, V_N, 256, 256, 256, 256);

    // 7) z2 = relu(z1 @ A2 + a2) fp32
    gemm_bb<1><<<g1, blk, SMEM>>>(pz1h, pz1l, pa2_h, pa2_l, a2,
                                  pz2, nullptr, nullptr, V_N, 64, 256, 256, 64);

    // 8) conf -> out[V*3 : V*4]
    tail_kernel<<<128, 256>>>(pz2, A3, a3, A4, a4, out + (size_t)V_N * 3);
}

// round 5
// speedup vs baseline: 3.5876x; 1.4529x over previous
#include <cuda_runtime.h>
#include <cuda_bf16.h>
#include <math.h>
#include <stdint.h>

#define V_N 20496
#define E_N 61440
#define F_N 3840
#define H_N 256

// ---------------------------------------------------------------------------
// Scratch (static device globals — no allocation allowed)
// ---------------------------------------------------------------------------
__device__ __align__(16) __nv_bfloat16 g_xh [(size_t)V_N * F_N];
__device__ __align__(16) __nv_bfloat16 g_xl [(size_t)V_N * F_N];
__device__ __align__(16) __nv_bfloat16 g_h0h[(size_t)V_N * 288];
__device__ __align__(16) __nv_bfloat16 g_h0l[(size_t)V_N * 288];
__device__ __align__(16) __nv_bfloat16 g_ah [(size_t)V_N * H_N];
__device__ __align__(16) __nv_bfloat16 g_al [(size_t)V_N * H_N];
__device__ __align__(16) __nv_bfloat16 g_bh [(size_t)V_N * H_N];
__device__ __align__(16) __nv_bfloat16 g_bl [(size_t)V_N * H_N];
__device__ __align__(16) __nv_bfloat16 g_z1h[(size_t)V_N * H_N];
__device__ __align__(16) __nv_bfloat16 g_z1l[(size_t)V_N * H_N];
__device__ __align__(16) float g_t0 [(size_t)V_N * H_N];   // self contribution
__device__ __align__(16) float g_t1 [(size_t)V_N * H_N];   // nbr contribution
__device__ __align__(16) float g_z2 [(size_t)V_N * 64];

// CSR adjacency (built once per call)
__device__ int g_deg[V_N];
__device__ int g_cur[V_N];
__device__ int g_off[V_N + 1];
__device__ int g_adj[2 * E_N];

// weight scratch: transposed [N, K_pad] bf16 hi/lo
__device__ __align__(16) __nv_bfloat16 wb_h [256 * 3840];
__device__ __align__(16) __nv_bfloat16 wb_l [256 * 3840];
__device__ __align__(16) __nv_bfloat16 w0_h [256 * 288];
__device__ __align__(16) __nv_bfloat16 w0_l [256 * 288];
__device__ __align__(16) __nv_bfloat16 w1_h [256 * 288];
__device__ __align__(16) __nv_bfloat16 w1_l [256 * 288];
__device__ __align__(16) __nv_bfloat16 gw0_h[9 * 256 * 256];
__device__ __align__(16) __nv_bfloat16 gw0_l[9 * 256 * 256];
__device__ __align__(16) __nv_bfloat16 gw1_h[9 * 256 * 256];
__device__ __align__(16) __nv_bfloat16 gw1_l[9 * 256 * 256];
__device__ __align__(16) __nv_bfloat16 a1_h [256 * 256];
__device__ __align__(16) __nv_bfloat16 a1_l [256 * 256];
__device__ __align__(16) __nv_bfloat16 a2_h [64 * 256];
__device__ __align__(16) __nv_bfloat16 a2_l [64 * 256];

// ---------------------------------------------------------------------------
// PTX helpers (plain compute_103-legal: mma.sync / ldmatrix / cp.async)
// ---------------------------------------------------------------------------
__device__ __forceinline__ void ldsm_x4(uint32_t* r, uint32_t addr) {
    asm volatile("ldmatrix.sync.aligned.m8n8.x4.shared.b16 {%0,%1,%2,%3}, [%4];"
        : "=r"(r[0]), "=r"(r[1]), "=r"(r[2]), "=r"(r[3]) : "r"(addr));
}
__device__ __forceinline__ void mma16816(float* d, const uint32_t* a, const uint32_t* b) {
    asm volatile(
        "mma.sync.aligned.m16n8k16.row.col.f32.bf16.bf16.f32 "
        "{%0,%1,%2,%3}, {%4,%5,%6,%7}, {%8,%9}, {%0,%1,%2,%3};"
        : "+f"(d[0]), "+f"(d[1]), "+f"(d[2]), "+f"(d[3])
        : "r"(a[0]), "r"(a[1]), "r"(a[2]), "r"(a[3]), "r"(b[0]), "r"(b[1]));
}
__device__ __forceinline__ void cp_async16(uint32_t dst, const void* src, bool pred) {
    int sz = pred ? 16 : 0;
    asm volatile("cp.async.cg.shared.global [%0], [%1], 16, %2;"
                 :: "r"(dst), "l"(src), "r"(sz));
}
#define CP_COMMIT() asm volatile("cp.async.commit_group;")
#define CP_WAIT(n)  asm volatile("cp.async.wait_group %0;" :: "n"(n))

__device__ __forceinline__ uint32_t pack2(float f0, float f1) {
    __nv_bfloat162 p;
    p.x = __float2bfloat16(f0);
    p.y = __float2bfloat16(f1);
    return *(uint32_t*)&p;
}

// ---------------------------------------------------------------------------
// Split-bf16 3-pass mma.sync GEMM (same as R4).
// OUT_MODE: 0=fp32, 1=fp32+relu, 2=bf16 split+relu.
// ---------------------------------------------------------------------------
#define OFF_ALO 8192
#define OFF_BHI 16384
#define OFF_BLO 24576
#define STAGE_B 32768

template<int OUT_MODE>
__global__ void __launch_bounds__(256, 2)
gemm_bb(const __nv_bfloat16* __restrict__ Ahi, const __nv_bfloat16* __restrict__ Alo,
        const __nv_bfloat16* __restrict__ Bhi, const __nv_bfloat16* __restrict__ Blo,
        const float* __restrict__ bias,
        float* __restrict__ Cf, __nv_bfloat16* __restrict__ Chi, __nv_bfloat16* __restrict__ Clo,
        int M, int N, int K_pad, int lda, int ldc)
{
    extern __shared__ char smp[];
    const uint32_t sbase = (uint32_t)__cvta_generic_to_shared(smp);

    const int tid  = threadIdx.x;
    const int lane = tid & 31;
    const int w    = tid >> 5;
    const int mw   = w & 3;
    const int nw   = w >> 2;
    const int bm   = blockIdx.y * 128;
    const int bn   = blockIdx.x * 128;

    float acc[2][8][4];
#pragma unroll
    for (int a = 0; a < 2; a++)
#pragma unroll
        for (int b = 0; b < 8; b++)
#pragma unroll
            for (int c = 0; c < 4; c++) acc[a][b][c] = 0.f;

    const int nc = K_pad >> 5;

#define LOAD_CHUNK(cidx, stg_u32)                                                   \
    {                                                                               \
        const int col0 = (cidx) << 5;                                               \
        _Pragma("unroll")                                                           \
        for (int g = 0; g < 2; g++) {                                               \
            int id = tid + g * 256;                                                 \
            int br = id >> 2, bc = id & 3;                                          \
            uint32_t dst = (stg_u32) + (uint32_t)(br * 64 + ((bc ^ ((br >> 1) & 3)) << 4)); \
            bool pa = (bm + br) < M;                                                \
            size_t ga = (size_t)(bm + br) * lda + col0 + bc * 8;                    \
            cp_async16(dst,           Ahi + ga, pa);                                \
            cp_async16(dst + OFF_ALO, Alo + ga, pa);                                \
            bool pb = (bn + br) < N;                                                \
            size_t gb = (size_t)(bn + br) * K_pad + col0 + bc * 8;                  \
            cp_async16(dst + OFF_BHI, Bhi + gb, pb);                                \
            cp_async16(dst + OFF_BLO, Blo + gb, pb);                                \
        }                                                                           \
        CP_COMMIT();                                                                \
    }

    LOAD_CHUNK(0, sbase);

    for (int c = 0; c < nc; c++) {
        const int s = c & 1;
        const uint32_t stg = sbase + (uint32_t)(s * STAGE_B);

        if (c + 1 < nc) {
            LOAD_CHUNK(c + 1, sbase + (uint32_t)((s ^ 1) * STAGE_B));
            CP_WAIT(1);
        } else {
            CP_WAIT(0);
        }
        __syncthreads();

#pragma unroll
        for (int kk = 0; kk < 2; kk++) {
            uint32_t ah[2][4], al[2][4];
#pragma unroll
            for (int mi = 0; mi < 2; mi++) {
                int row = mw * 32 + mi * 16 + (lane & 15);
                int ch  = 2 * kk + (lane >> 4);
                int phys = ch ^ ((row >> 1) & 3);
                uint32_t off = stg + (uint32_t)(row * 64 + phys * 16);
                ldsm_x4(ah[mi], off);
                ldsm_x4(al[mi], off + OFF_ALO);
            }
#pragma unroll
            for (int h2 = 0; h2 < 2; h2++) {
                uint32_t bh[2][4], bl[2][4];
#pragma unroll
                for (int t4 = 0; t4 < 2; t4++) {
                    int row = nw * 64 + (h2 * 2 + t4) * 16 + (lane & 7) + ((lane >> 4) << 3);
                    int ch  = 2 * kk + ((lane >> 3) & 1);
                    int phys = ch ^ ((row >> 1) & 3);
                    uint32_t off = stg + (uint32_t)(row * 64 + phys * 16);
                    ldsm_x4(bh[t4], off + OFF_BHI);
                    ldsm_x4(bl[t4], off + OFF_BLO);
                }
#pragma unroll
                for (int mi = 0; mi < 2; mi++)
#pragma unroll
                    for (int q = 0; q < 4; q++) {
                        const uint32_t* pbh = &bh[q >> 1][(q & 1) * 2];
                        const uint32_t* pbl = &bl[q >> 1][(q & 1) * 2];
                        float* d = acc[mi][h2 * 4 + q];
                        mma16816(d, ah[mi], pbh);
                        mma16816(d, ah[mi], pbl);
                        mma16816(d, al[mi], pbh);
                    }
            }
        }
        __syncthreads();
    }

#pragma unroll
    for (int mi = 0; mi < 2; mi++) {
        int row0 = bm + mw * 32 + mi * 16 + (lane >> 2);
#pragma unroll
        for (int n8 = 0; n8 < 8; n8++) {
            int col = bn + nw * 64 + n8 * 8 + (lane & 3) * 2;
            if (col >= N) continue;
            float b0 = bias[col], b1 = bias[col + 1];
            float* d = acc[mi][n8];
            float v0 = d[0] + b0, v1 = d[1] + b1;
            float v2 = d[2] + b0, v3 = d[3] + b1;
            if (OUT_MODE >= 1) {
                v0 = fmaxf(v0, 0.f); v1 = fmaxf(v1, 0.f);
                v2 = fmaxf(v2, 0.f); v3 = fmaxf(v3, 0.f);
            }
            if (OUT_MODE == 2) {
                uint32_t h01 = pack2(v0, v1);
                float r0f = __bfloat162float(((__nv_bfloat162*)&h01)->x);
                float r1f = __bfloat162float(((__nv_bfloat162*)&h01)->y);
                uint32_t l01 = pack2(v0 - r0f, v1 - r1f);
                uint32_t h23 = pack2(v2, v3);
                float r2f = __bfloat162float(((__nv_bfloat162*)&h23)->x);
                float r3f = __bfloat162float(((__nv_bfloat162*)&h23)->y);
                uint32_t l23 = pack2(v2 - r2f, v3 - r3f);
                if (row0 < M) {
                    *(uint32_t*)(Chi + (size_t)row0 * ldc + col) = h01;
                    *(uint32_t*)(Clo + (size_t)row0 * ldc + col) = l01;
                }
                if (row0 + 8 < M) {
                    *(uint32_t*)(Chi + (size_t)(row0 + 8) * ldc + col) = h23;
                    *(uint32_t*)(Clo + (size_t)(row0 + 8) * ldc + col) = l23;
                }
            } else {
                if (row0 < M)     *(float2*)(Cf + (size_t)row0 * ldc + col)       = make_float2(v0, v1);
                if (row0 + 8 < M) *(float2*)(Cf + (size_t)(row0 + 8) * ldc + col) = make_float2(v2, v3);
            }
        }
    }
}

// ---------------------------------------------------------------------------
// CSR build kernels
// ---------------------------------------------------------------------------
__global__ void csr_zero_kernel()
{
    int v = blockIdx.x * blockDim.x + threadIdx.x;
    if (v < V_N) { g_deg[v] = 0; g_cur[v] = 0; }
}

__global__ void csr_count_kernel(const int* __restrict__ edges)
{
    int e = blockIdx.x * blockDim.x + threadIdx.x;
    if (e >= E_N) return;
    atomicAdd(&g_deg[edges[2 * e]], 1);
    atomicAdd(&g_deg[edges[2 * e + 1]], 1);
}

__global__ void __launch_bounds__(1024) csr_scan_kernel()
{
    __shared__ int part[1024];
    const int tid = threadIdx.x;
    const int CH = (V_N + 1023) / 1024;   // 21
    const int base = tid * CH;
    int s = 0;
#pragma unroll
    for (int q = 0; q < CH; q++) {
        int idx = base + q;
        if (idx < V_N) s += g_deg[idx];
    }
    part[tid] = s;
    __syncthreads();
    // inclusive Hillis-Steele scan
    for (int o = 1; o < 1024; o <<= 1) {
        int t = (tid >= o) ? part[tid - o] : 0;
        __syncthreads();
        part[tid] += t;
        __syncthreads();
    }
    int run = part[tid] - s;   // exclusive chunk start
    for (int q = 0; q < CH; q++) {
        int idx = base + q;
        if (idx < V_N) {
            g_off[idx] = run;
            run += g_deg[idx];
        }
    }
    if (tid == 1023) g_off[V_N] = part[1023];
}

__global__ void csr_fill_kernel(const int* __restrict__ edges)
{
    int e = blockIdx.x * blockDim.x + threadIdx.x;
    if (e >= E_N) return;
    int i = edges[2 * e], j = edges[2 * e + 1];
    int p = g_off[i] + atomicAdd(&g_cur[i], 1);
    g_adj[p] = j;
    p = g_off[j] + atomicAdd(&g_cur[j], 1);
    g_adj[p] = i;
}

// ---------------------------------------------------------------------------
// Fused gather + relu + split:
//   h[v] = relu(self[v] + sum_{u in adj(v)} nbr[u])  -> (oh, ol) bf16 hi/lo
// 64 threads per vertex (float4 over 256 cols), 4 vertices per block.
// ---------------------------------------------------------------------------
__global__ void __launch_bounds__(256)
gather_split_kernel(const float* __restrict__ self, const float* __restrict__ nbr,
                    __nv_bfloat16* __restrict__ oh, __nv_bfloat16* __restrict__ ol)
{
    int v = blockIdx.x * 4 + (threadIdx.x >> 6);
    if (v >= V_N) return;
    int c = (threadIdx.x & 63) << 2;

    float4 acc = *(const float4*)(self + (size_t)v * H_N + c);
    int s = g_off[v], e = g_off[v + 1];
    for (int p = s; p < e; p++) {
        int u = g_adj[p];
        float4 w = *(const float4*)(nbr + (size_t)u * H_N + c);
        acc.x += w.x; acc.y += w.y; acc.z += w.z; acc.w += w.w;
    }
    acc.x = fmaxf(acc.x, 0.f); acc.y = fmaxf(acc.y, 0.f);
    acc.z = fmaxf(acc.z, 0.f); acc.w = fmaxf(acc.w, 0.f);

    uint32_t h01 = pack2(acc.x, acc.y);
    uint32_t h23 = pack2(acc.z, acc.w);
    __nv_bfloat162 hh01 = *(__nv_bfloat162*)&h01;
    __nv_bfloat162 hh23 = *(__nv_bfloat162*)&h23;
    uint32_t l01 = pack2(acc.x - __bfloat162float(hh01.x), acc.y - __bfloat162float(hh01.y));
    uint32_t l23 = pack2(acc.z - __bfloat162float(hh23.x), acc.w - __bfloat162float(hh23.y));
    *(uint2*)(oh + (size_t)v * H_N + c) = make_uint2(h01, h23);
    *(uint2*)(ol + (size_t)v * H_N + c) = make_uint2(l01, l23);
}

// ---------------------------------------------------------------------------
// Weight prep: W[Kin,N] fp32 -> Wt_hi/lo[N,K_pad] bf16 (transpose + split)
// ---------------------------------------------------------------------------
__global__ void prep_w_kernel(const float* __restrict__ W,
                              __nv_bfloat16* __restrict__ oh,
                              __nv_bfloat16* __restrict__ ol,
                              int Kin, int N, int K_pad,
                              size_t in_stride, size_t out_stride)
{
    int mat = blockIdx.y;
    const float* w = W + (size_t)mat * in_stride;
    __nv_bfloat16* ph = oh + (size_t)mat * out_stride;
    __nv_bfloat16* pl = ol + (size_t)mat * out_stride;
    int total = N * K_pad;
    int idx = blockIdx.x * blockDim.x + threadIdx.x;
    if (idx >= total) return;
    int n = idx / K_pad, k = idx - n * K_pad;
    float v = (k < Kin) ? w[(size_t)k * N + n] : 0.f;
    __nv_bfloat16 h = __float2bfloat16(v);
    ph[idx] = h;
    pl[idx] = __float2bfloat16(v - __bfloat162float(h));
}

// ---------------------------------------------------------------------------
template<bool RELU>
__global__ void split_kernel(const float* __restrict__ in,
                             __nv_bfloat16* __restrict__ oh,
                             __nv_bfloat16* __restrict__ ol, int n4)
{
    int idx = blockIdx.x * blockDim.x + threadIdx.x;
    if (idx >= n4) return;
    float4 v = ((const float4*)in)[idx];
    if (RELU) {
        v.x = fmaxf(v.x, 0.f); v.y = fmaxf(v.y, 0.f);
        v.z = fmaxf(v.z, 0.f); v.w = fmaxf(v.w, 0.f);
    }
    uint32_t h01 = pack2(v.x, v.y);
    uint32_t h23 = pack2(v.z, v.w);
    __nv_bfloat162 hh01 = *(__nv_bfloat162*)&h01;
    __nv_bfloat162 hh23 = *(__nv_bfloat162*)&h23;
    uint32_t l01 = pack2(v.x - __bfloat162float(hh01.x), v.y - __bfloat162float(hh01.y));
    uint32_t l23 = pack2(v.z - __bfloat162float(hh23.x), v.w - __bfloat162float(hh23.y));
    ((uint2*)oh)[idx] = make_uint2(h01, h23);
    ((uint2*)ol)[idx] = make_uint2(l01, l23);
}

// ---------------------------------------------------------------------------
__global__ void concat_verts_kernel(const float* __restrict__ verts)
{
    int idx = blockIdx.x * blockDim.x + threadIdx.x;  // V * 32
    if (idx >= V_N * 32) return;
    int v = idx >> 5, c = idx & 31;
    float x = (c < 3) ? verts[v * 3 + c] : 0.f;
    __nv_bfloat16 h = __float2bfloat16(x);
    __nv_bfloat16 l = __float2bfloat16(x - __bfloat162float(h));
    size_t o = (size_t)v * 288 + 256 + c;
    g_h0h[o] = h;
    g_h0l[o] = l;
}

// ---------------------------------------------------------------------------
__global__ void delta_kernel(const __nv_bfloat16* __restrict__ hh,
                             const __nv_bfloat16* __restrict__ hl,
                             const float* __restrict__ Wo,
                             const float* __restrict__ bo,
                             float* __restrict__ out)
{
    __shared__ float sW[H_N * 3];
    __shared__ float sb[3];
    for (int i = threadIdx.x; i < H_N * 3; i += blockDim.x) sW[i] = Wo[i];
    if (threadIdx.x < 3) sb[threadIdx.x] = bo[threadIdx.x];
    __syncthreads();

    int idx = blockIdx.x * blockDim.x + threadIdx.x;
    if (idx >= V_N * 3) return;
    int v = idx / 3, c = idx % 3;
    const __nv_bfloat162* ph = (const __nv_bfloat162*)(hh + (size_t)v * H_N);
    const __nv_bfloat162* pl = (const __nv_bfloat162*)(hl + (size_t)v * H_N);
    float s = sb[c];
#pragma unroll 4
    for (int k = 0; k < H_N / 2; k++) {
        __nv_bfloat162 a = ph[k], b = pl[k];
        float x0 = __bfloat162float(a.x) + __bfloat162float(b.x);
        float x1 = __bfloat162float(a.y) + __bfloat162float(b.y);
        s = fmaf(x0, sW[(2 * k) * 3 + c], s);
        s = fmaf(x1, sW[(2 * k + 1) * 3 + c], s);
    }
    out[idx] = s;
}

// ---------------------------------------------------------------------------
__global__ void tail_kernel(const float* __restrict__ z2,
                            const float* __restrict__ A3,
                            const float* __restrict__ a3,
                            const float* __restrict__ A4,
                            const float* __restrict__ a4,
                            float* __restrict__ conf)
{
    __shared__ float sA3[64 * 32];
    __shared__ float sa3[32];
    __shared__ float sA4[32];
    for (int i = threadIdx.x; i < 64 * 32; i += blockDim.x) sA3[i] = A3[i];
    if (threadIdx.x < 32) {
        sa3[threadIdx.x] = a3[threadIdx.x];
        sA4[threadIdx.x] = A4[threadIdx.x];
    }
    __syncthreads();

    float b4 = a4[0];
    for (int v = blockIdx.x * blockDim.x + threadIdx.x; v < V_N;
         v += gridDim.x * blockDim.x) {
        float x[64];
        const float* zr = z2 + (size_t)v * 64;
#pragma unroll
        for (int k = 0; k < 64; k++) x[k] = zr[k];
        float acc = b4;
#pragma unroll 4
        for (int m = 0; m < 32; m++) {
            float s = sa3[m];
#pragma unroll
            for (int k = 0; k < 64; k++) s = fmaf(x[k], sA3[k * 32 + m], s);
            acc = fmaf(fmaxf(s, 0.f), sA4[m], acc);
        }
        conf[v] = 1.f / (1.f + expf(-acc));
    }
}

// ---------------------------------------------------------------------------
// Launcher
// ---------------------------------------------------------------------------
extern "C" void kernel_launch(void* const* d_in, const int* in_sizes, int n_in,
                              void* d_out, int out_size)
{
    (void)in_sizes; (void)n_in; (void)out_size;
    const float* X     = (const float*)d_in[0];
    const float* verts = (const float*)d_in[1];
    const int*   edges = (const int*)  d_in[2];
    const float* Wb    = (const float*)d_in[3];
    const float* bb    = (const float*)d_in[4];
    const float* W0_0  = (const float*)d_in[5];
    const float* b0_0  = (const float*)d_in[6];
    const float* W1_0  = (const float*)d_in[7];
    const float* b1_0  = (const float*)d_in[8];
    const float* gW0   = (const float*)d_in[9];
    const float* gb0   = (const float*)d_in[10];
    const float* gW1   = (const float*)d_in[11];
    const float* gb1   = (const float*)d_in[12];
    const float* Wo    = (const float*)d_in[13];
    const float* bo    = (const float*)d_in[14];
    const float* A1    = (const float*)d_in[15];
    const float* a1    = (const float*)d_in[16];
    const float* A2    = (const float*)d_in[17];
    const float* a2    = (const float*)d_in[18];
    const float* A3    = (const float*)d_in[19];
    const float* a3    = (const float*)d_in[20];
    const float* A4    = (const float*)d_in[21];
    const float* a4    = (const float*)d_in[22];
    float* out = (float*)d_out;

    __nv_bfloat16 *pxh, *pxl, *ph0h, *ph0l, *pah, *pal, *pbh, *pbl, *pz1h, *pz1l;
    float *pt0, *pt1, *pz2;
    cudaGetSymbolAddress((void**)&pxh,  g_xh);   cudaGetSymbolAddress((void**)&pxl,  g_xl);
    cudaGetSymbolAddress((void**)&ph0h, g_h0h);  cudaGetSymbolAddress((void**)&ph0l, g_h0l);
    cudaGetSymbolAddress((void**)&pah,  g_ah);   cudaGetSymbolAddress((void**)&pal,  g_al);
    cudaGetSymbolAddress((void**)&pbh,  g_bh);   cudaGetSymbolAddress((void**)&pbl,  g_bl);
    cudaGetSymbolAddress((void**)&pz1h, g_z1h);  cudaGetSymbolAddress((void**)&pz1l, g_z1l);
    cudaGetSymbolAddress((void**)&pt0,  g_t0);   cudaGetSymbolAddress((void**)&pt1,  g_t1);
    cudaGetSymbolAddress((void**)&pz2,  g_z2);

    __nv_bfloat16 *pwb_h, *pwb_l, *pw0_h, *pw0_l, *pw1_h, *pw1_l;
    __nv_bfloat16 *pg0_h, *pg0_l, *pg1_h, *pg1_l, *pa1_h, *pa1_l, *pa2_h, *pa2_l;
    cudaGetSymbolAddress((void**)&pwb_h, wb_h);  cudaGetSymbolAddress((void**)&pwb_l, wb_l);
    cudaGetSymbolAddress((void**)&pw0_h, w0_h);  cudaGetSymbolAddress((void**)&pw0_l, w0_l);
    cudaGetSymbolAddress((void**)&pw1_h, w1_h);  cudaGetSymbolAddress((void**)&pw1_l, w1_l);
    cudaGetSymbolAddress((void**)&pg0_h, gw0_h); cudaGetSymbolAddress((void**)&pg0_l, gw0_l);
    cudaGetSymbolAddress((void**)&pg1_h, gw1_h); cudaGetSymbolAddress((void**)&pg1_l, gw1_l);
    cudaGetSymbolAddress((void**)&pa1_h, a1_h);  cudaGetSymbolAddress((void**)&pa1_l, a1_l);
    cudaGetSymbolAddress((void**)&pa2_h, a2_h);  cudaGetSymbolAddress((void**)&pa2_l, a2_l);

    const int SMEM = 65536;
    cudaFuncSetAttribute(gemm_bb<0>, cudaFuncAttributeMaxDynamicSharedMemorySize, SMEM);
    cudaFuncSetAttribute(gemm_bb<1>, cudaFuncAttributeMaxDynamicSharedMemorySize, SMEM);
    cudaFuncSetAttribute(gemm_bb<2>, cudaFuncAttributeMaxDynamicSharedMemorySize, SMEM);

    const int MT = (V_N + 127) / 128;   // 161
    const dim3 blk(256);
    const dim3 g2(2, MT);   // N=256
    const dim3 g1(1, MT);   // N<=128
    const int GATHER_GRID = (V_N + 3) / 4;   // 5124

    // ---- CSR build ----
    csr_zero_kernel<<<(V_N + 255) / 256, 256>>>();
    csr_count_kernel<<<(E_N + 255) / 256, 256>>>(edges);
    csr_scan_kernel<<<1, 1024>>>();
    csr_fill_kernel<<<(E_N + 255) / 256, 256>>>(edges);

    // ---- weight prep ----
    {
        int n;
        n = 256 * 3840;
        prep_w_kernel<<<dim3((n + 255) / 256, 1), 256>>>(Wb, pwb_h, pwb_l, 3840, 256, 3840, 0, 0);
        n = 256 * 288;
        prep_w_kernel<<<dim3((n + 255) / 256, 1), 256>>>(W0_0, pw0_h, pw0_l, 259, 256, 288, 0, 0);
        prep_w_kernel<<<dim3((n + 255) / 256, 1), 256>>>(W1_0, pw1_h, pw1_l, 259, 256, 288, 0, 0);
        n = 256 * 256;
        prep_w_kernel<<<dim3((n + 255) / 256, 9), 256>>>(gW0, pg0_h, pg0_l, 256, 256, 256, 65536, 65536);
        prep_w_kernel<<<dim3((n + 255) / 256, 9), 256>>>(gW1, pg1_h, pg1_l, 256, 256, 256, 65536, 65536);
        prep_w_kernel<<<dim3((n + 255) / 256, 1), 256>>>(A1, pa1_h, pa1_l, 256, 256, 256, 0, 0);
        n = 64 * 256;
        prep_w_kernel<<<dim3((n + 255) / 256, 1), 256>>>(A2, pa2_h, pa2_l, 256, 64, 256, 0, 0);
    }

    // ---- split X ----
    {
        int n4 = (V_N * F_N) / 4;
        split_kernel<false><<<(n4 + 255) / 256, 256>>>(X, pxh, pxl, n4);
    }

    // 1) backbone: h0[:, :256] = relu(X @ Wb + bb), written split
    gemm_bb<2><<<g2, blk, SMEM>>>(pxh, pxl, pwb_h, pwb_l, bb,
                                  nullptr, ph0h, ph0l, V_N, 256, 3840, 3840, 288);
    // 2) concat verts (split) into cols 256..287
    concat_verts_kernel<<<(V_N * 32 + 255) / 256, 256>>>(verts);

    // 3) layer 0 (K_pad=288): W0 -> self (pt0), W1 -> nbr (pt1), gather+split
    gemm_bb<0><<<g2, blk, SMEM>>>(ph0h, ph0l, pw0_h, pw0_l, b0_0,
                                  pt0, nullptr, nullptr, V_N, 256, 288, 288, 256);
    gemm_bb<0><<<g2, blk, SMEM>>>(ph0h, ph0l, pw1_h, pw1_l, b1_0,
                                  pt1, nullptr, nullptr, V_N, 256, 288, 288, 256);
    gather_split_kernel<<<GATHER_GRID, 256>>>(pt0, pt1, pah, pal);

    // 4) layers 1..9
    __nv_bfloat16 *curh = pah, *curl = pal, *nxth = pbh, *nxtl = pbl;
    for (int k = 0; k < 9; k++) {
        const __nv_bfloat16* W0h = pg0_h + (size_t)k * 65536;
        const __nv_bfloat16* W0l = pg0_l + (size_t)k * 65536;
        const __nv_bfloat16* W1h = pg1_h + (size_t)k * 65536;
        const __nv_bfloat16* W1l = pg1_l + (size_t)k * 65536;
        const float* B0 = gb0 + (size_t)k * H_N;
        const float* B1 = gb1 + (size_t)k * H_N;
        gemm_bb<0><<<g2, blk, SMEM>>>(curh, curl, W0h, W0l, B0,
                                      pt0, nullptr, nullptr, V_N, 256, 256, 256, 256);
        gemm_bb<0><<<g2, blk, SMEM>>>(curh, curl, W1h, W1l, B1,
                                      pt1, nullptr, nullptr, V_N, 256, 256, 256, 256);
        gather_split_kernel<<<GATHER_GRID, 256>>>(pt0, pt1, nxth, nxtl);
        __nv_bfloat16* t;
        t = curh; curh = nxth; nxth = t;
        t = curl; curl = nxtl; nxtl = t;
    }
    // final relu(h) split in (curh, curl)

    // 5) delta_v -> out[0 : V*3]
    delta_kernel<<<(V_N * 3 + 255) / 256, 256>>>(curh, curl, Wo, bo, out);

    // 6) z1 = relu(h_relu @ A1 + a1), written split
    gemm_bb<2><<<g2, blk, SMEM>>>(curh, curl, pa1_h, pa1_l, a1,
                                  nullptr, pz1h, pz1l, V_N, 256, 256, 256, 256);

    // 7) z2 = relu(z1 @ A2 + a2) fp32
    gemm_bb<1><<<g1, blk, SMEM>>>(pz1h, pz1l, pa2_h, pa2_l, a2,
                                  pz2, nullptr, nullptr, V_N, 64, 256, 256, 64);

    // 8) conf -> out[V*3 : V*4]
    tail_kernel<<<128, 256>>>(pz2, A3, a3, A4, a4, out + (size_t)V_N * 3);
}

// round 6
// speedup vs baseline: 3.9327x; 1.0962x over previous
#include <cuda_runtime.h>
#include <cuda_bf16.h>
#include <math.h>
#include <stdint.h>

#define V_N 20496
#define E_N 61440
#define F_N 3840
#define H_N 256

// ---------------------------------------------------------------------------
// Scratch (static device globals — no allocation allowed)
// ---------------------------------------------------------------------------
__device__ __align__(16) __nv_bfloat16 g_xh [(size_t)V_N * F_N];
__device__ __align__(16) __nv_bfloat16 g_xl [(size_t)V_N * F_N];
__device__ __align__(16) __nv_bfloat16 g_h0h[(size_t)V_N * 288];
__device__ __align__(16) __nv_bfloat16 g_h0l[(size_t)V_N * 288];
__device__ __align__(16) __nv_bfloat16 g_ah [(size_t)V_N * H_N];
__device__ __align__(16) __nv_bfloat16 g_al [(size_t)V_N * H_N];
__device__ __align__(16) __nv_bfloat16 g_bh [(size_t)V_N * H_N];
__device__ __align__(16) __nv_bfloat16 g_bl [(size_t)V_N * H_N];
__device__ __align__(16) __nv_bfloat16 g_z1h[(size_t)V_N * H_N];
__device__ __align__(16) __nv_bfloat16 g_z1l[(size_t)V_N * H_N];
__device__ __align__(16) float g_t0 [(size_t)V_N * H_N];   // self contribution
__device__ __align__(16) float g_t1 [(size_t)V_N * H_N];   // nbr contribution
__device__ __align__(16) float g_z2 [(size_t)V_N * 64];

// CSR adjacency (built once per call)
__device__ int g_deg[V_N];
__device__ int g_cur[V_N];
__device__ int g_off[V_N + 1];
__device__ int g_adj[2 * E_N];

// weight scratch: transposed [N, K_pad] bf16 hi/lo
__device__ __align__(16) __nv_bfloat16 wb_h [256 * 3840];
__device__ __align__(16) __nv_bfloat16 wb_l [256 * 3840];
__device__ __align__(16) __nv_bfloat16 w0_h [256 * 288];
__device__ __align__(16) __nv_bfloat16 w0_l [256 * 288];
__device__ __align__(16) __nv_bfloat16 w1_h [256 * 288];
__device__ __align__(16) __nv_bfloat16 w1_l [256 * 288];
__device__ __align__(16) __nv_bfloat16 gw0_h[9 * 256 * 256];
__device__ __align__(16) __nv_bfloat16 gw0_l[9 * 256 * 256];
__device__ __align__(16) __nv_bfloat16 gw1_h[9 * 256 * 256];
__device__ __align__(16) __nv_bfloat16 gw1_l[9 * 256 * 256];
__device__ __align__(16) __nv_bfloat16 a1_h [256 * 256];
__device__ __align__(16) __nv_bfloat16 a1_l [256 * 256];
__device__ __align__(16) __nv_bfloat16 a2_h [64 * 256];
__device__ __align__(16) __nv_bfloat16 a2_l [64 * 256];

// ---------------------------------------------------------------------------
// PTX helpers (plain compute_103-legal: mma.sync / ldmatrix / cp.async)
// ---------------------------------------------------------------------------
__device__ __forceinline__ void ldsm_x4(uint32_t* r, uint32_t addr) {
    asm volatile("ldmatrix.sync.aligned.m8n8.x4.shared.b16 {%0,%1,%2,%3}, [%4];"
        : "=r"(r[0]), "=r"(r[1]), "=r"(r[2]), "=r"(r[3]) : "r"(addr));
}
__device__ __forceinline__ void mma16816(float* d, const uint32_t* a, const uint32_t* b) {
    asm volatile(
        "mma.sync.aligned.m16n8k16.row.col.f32.bf16.bf16.f32 "
        "{%0,%1,%2,%3}, {%4,%5,%6,%7}, {%8,%9}, {%0,%1,%2,%3};"
        : "+f"(d[0]), "+f"(d[1]), "+f"(d[2]), "+f"(d[3])
        : "r"(a[0]), "r"(a[1]), "r"(a[2]), "r"(a[3]), "r"(b[0]), "r"(b[1]));
}
__device__ __forceinline__ void cp_async16(uint32_t dst, const void* src, bool pred) {
    int sz = pred ? 16 : 0;
    asm volatile("cp.async.cg.shared.global [%0], [%1], 16, %2;"
                 :: "r"(dst), "l"(src), "r"(sz));
}
#define CP_COMMIT() asm volatile("cp.async.commit_group;")
#define CP_WAIT(n)  asm volatile("cp.async.wait_group %0;" :: "n"(n))

__device__ __forceinline__ uint32_t pack2(float f0, float f1) {
    __nv_bfloat162 p;
    p.x = __float2bfloat16(f0);
    p.y = __float2bfloat16(f1);
    return *(uint32_t*)&p;
}

// ---------------------------------------------------------------------------
// Split-bf16 3-pass mma.sync GEMM.
// PAIR=true: grid.x=4, computes TWO GEMMs sharing A (sel = blockIdx.x>>1).
// OUT_MODE: 0=fp32, 1=fp32+relu, 2=bf16 split+relu.
// SMEM stage: Ahi(8K) Alo(8K) Bhi(8K) Blo(8K); 64B rows, XOR swizzle.
// ---------------------------------------------------------------------------
#define OFF_ALO 8192
#define OFF_BHI 16384
#define OFF_BLO 24576
#define STAGE_B 32768

template<int OUT_MODE, bool PAIR>
__global__ void __launch_bounds__(256, 2)
gemm_bb(const __nv_bfloat16* __restrict__ Ahi, const __nv_bfloat16* __restrict__ Alo,
        const __nv_bfloat16* __restrict__ Bhi0, const __nv_bfloat16* __restrict__ Blo0,
        const float* __restrict__ bias0, float* __restrict__ Cf0,
        const __nv_bfloat16* __restrict__ Bhi1, const __nv_bfloat16* __restrict__ Blo1,
        const float* __restrict__ bias1, float* __restrict__ Cf1,
        __nv_bfloat16* __restrict__ Chi, __nv_bfloat16* __restrict__ Clo,
        int M, int N, int K_pad, int lda, int ldc)
{
    extern __shared__ char smp[];
    const uint32_t sbase = (uint32_t)__cvta_generic_to_shared(smp);

    const int tid  = threadIdx.x;
    const int lane = tid & 31;
    const int w    = tid >> 5;
    const int mw   = w & 3;
    const int nw   = w >> 2;
    const int bm   = blockIdx.y * 128;

    int sel, bn;
    if (PAIR) { sel = blockIdx.x >> 1; bn = (blockIdx.x & 1) * 128; }
    else      { sel = 0;               bn = blockIdx.x * 128; }

    const __nv_bfloat16* Bhi = sel ? Bhi1 : Bhi0;
    const __nv_bfloat16* Blo = sel ? Blo1 : Blo0;
    const float* bias        = sel ? bias1 : bias0;
    float* Cf                = sel ? Cf1 : Cf0;

    float acc[2][8][4];
#pragma unroll
    for (int a = 0; a < 2; a++)
#pragma unroll
        for (int b = 0; b < 8; b++)
#pragma unroll
            for (int c = 0; c < 4; c++) acc[a][b][c] = 0.f;

    const int nc = K_pad >> 5;

#define LOAD_CHUNK(cidx, stg_u32)                                                   \
    {                                                                               \
        const int col0 = (cidx) << 5;                                               \
        _Pragma("unroll")                                                           \
        for (int g = 0; g < 2; g++) {                                               \
            int id = tid + g * 256;                                                 \
            int br = id >> 2, bc = id & 3;                                          \
            uint32_t dst = (stg_u32) + (uint32_t)(br * 64 + ((bc ^ ((br >> 1) & 3)) << 4)); \
            bool pa = (bm + br) < M;                                                \
            size_t ga = (size_t)(bm + br) * lda + col0 + bc * 8;                    \
            cp_async16(dst,           Ahi + ga, pa);                                \
            cp_async16(dst + OFF_ALO, Alo + ga, pa);                                \
            bool pb = (bn + br) < N;                                                \
            size_t gb = (size_t)(bn + br) * K_pad + col0 + bc * 8;                  \
            cp_async16(dst + OFF_BHI, Bhi + gb, pb);                                \
            cp_async16(dst + OFF_BLO, Blo + gb, pb);                                \
        }                                                                           \
        CP_COMMIT();                                                                \
    }

    LOAD_CHUNK(0, sbase);

    for (int c = 0; c < nc; c++) {
        const int s = c & 1;
        const uint32_t stg = sbase + (uint32_t)(s * STAGE_B);

        if (c + 1 < nc) {
            LOAD_CHUNK(c + 1, sbase + (uint32_t)((s ^ 1) * STAGE_B));
            CP_WAIT(1);
        } else {
            CP_WAIT(0);
        }
        __syncthreads();

#pragma unroll
        for (int kk = 0; kk < 2; kk++) {
            uint32_t ah[2][4], al[2][4];
#pragma unroll
            for (int mi = 0; mi < 2; mi++) {
                int row = mw * 32 + mi * 16 + (lane & 15);
                int ch  = 2 * kk + (lane >> 4);
                int phys = ch ^ ((row >> 1) & 3);
                uint32_t off = stg + (uint32_t)(row * 64 + phys * 16);
                ldsm_x4(ah[mi], off);
                ldsm_x4(al[mi], off + OFF_ALO);
            }
#pragma unroll
            for (int h2 = 0; h2 < 2; h2++) {
                uint32_t bh[2][4], bl[2][4];
#pragma unroll
                for (int t4 = 0; t4 < 2; t4++) {
                    int row = nw * 64 + (h2 * 2 + t4) * 16 + (lane & 7) + ((lane >> 4) << 3);
                    int ch  = 2 * kk + ((lane >> 3) & 1);
                    int phys = ch ^ ((row >> 1) & 3);
                    uint32_t off = stg + (uint32_t)(row * 64 + phys * 16);
                    ldsm_x4(bh[t4], off + OFF_BHI);
                    ldsm_x4(bl[t4], off + OFF_BLO);
                }
#pragma unroll
                for (int mi = 0; mi < 2; mi++)
#pragma unroll
                    for (int q = 0; q < 4; q++) {
                        const uint32_t* pbh = &bh[q >> 1][(q & 1) * 2];
                        const uint32_t* pbl = &bl[q >> 1][(q & 1) * 2];
                        float* d = acc[mi][h2 * 4 + q];
                        mma16816(d, ah[mi], pbh);
                        mma16816(d, ah[mi], pbl);
                        mma16816(d, al[mi], pbh);
                    }
            }
        }
        __syncthreads();
    }

#pragma unroll
    for (int mi = 0; mi < 2; mi++) {
        int row0 = bm + mw * 32 + mi * 16 + (lane >> 2);
#pragma unroll
        for (int n8 = 0; n8 < 8; n8++) {
            int col = bn + nw * 64 + n8 * 8 + (lane & 3) * 2;
            if (col >= N) continue;
            float b0 = bias[col], b1 = bias[col + 1];
            float* d = acc[mi][n8];
            float v0 = d[0] + b0, v1 = d[1] + b1;
            float v2 = d[2] + b0, v3 = d[3] + b1;
            if (OUT_MODE >= 1) {
                v0 = fmaxf(v0, 0.f); v1 = fmaxf(v1, 0.f);
                v2 = fmaxf(v2, 0.f); v3 = fmaxf(v3, 0.f);
            }
            if (OUT_MODE == 2) {
                uint32_t h01 = pack2(v0, v1);
                float r0f = __bfloat162float(((__nv_bfloat162*)&h01)->x);
                float r1f = __bfloat162float(((__nv_bfloat162*)&h01)->y);
                uint32_t l01 = pack2(v0 - r0f, v1 - r1f);
                uint32_t h23 = pack2(v2, v3);
                float r2f = __bfloat162float(((__nv_bfloat162*)&h23)->x);
                float r3f = __bfloat162float(((__nv_bfloat162*)&h23)->y);
                uint32_t l23 = pack2(v2 - r2f, v3 - r3f);
                if (row0 < M) {
                    *(uint32_t*)(Chi + (size_t)row0 * ldc + col) = h01;
                    *(uint32_t*)(Clo + (size_t)row0 * ldc + col) = l01;
                }
                if (row0 + 8 < M) {
                    *(uint32_t*)(Chi + (size_t)(row0 + 8) * ldc + col) = h23;
                    *(uint32_t*)(Clo + (size_t)(row0 + 8) * ldc + col) = l23;
                }
            } else {
                if (row0 < M)     *(float2*)(Cf + (size_t)row0 * ldc + col)       = make_float2(v0, v1);
                if (row0 + 8 < M) *(float2*)(Cf + (size_t)(row0 + 8) * ldc + col) = make_float2(v2, v3);
            }
        }
    }
}

// ---------------------------------------------------------------------------
// CSR build kernels
// ---------------------------------------------------------------------------
__global__ void csr_zero_kernel()
{
    int v = blockIdx.x * blockDim.x + threadIdx.x;
    if (v < V_N) { g_deg[v] = 0; g_cur[v] = 0; }
}

__global__ void csr_count_kernel(const int* __restrict__ edges)
{
    int e = blockIdx.x * blockDim.x + threadIdx.x;
    if (e >= E_N) return;
    atomicAdd(&g_deg[edges[2 * e]], 1);
    atomicAdd(&g_deg[edges[2 * e + 1]], 1);
}

__global__ void __launch_bounds__(1024) csr_scan_kernel()
{
    __shared__ int part[1024];
    const int tid = threadIdx.x;
    const int CH = (V_N + 1023) / 1024;   // 21
    const int base = tid * CH;
    int s = 0;
#pragma unroll
    for (int q = 0; q < CH; q++) {
        int idx = base + q;
        if (idx < V_N) s += g_deg[idx];
    }
    part[tid] = s;
    __syncthreads();
    for (int o = 1; o < 1024; o <<= 1) {
        int t = (tid >= o) ? part[tid - o] : 0;
        __syncthreads();
        part[tid] += t;
        __syncthreads();
    }
    int run = part[tid] - s;
    for (int q = 0; q < CH; q++) {
        int idx = base + q;
        if (idx < V_N) {
            g_off[idx] = run;
            run += g_deg[idx];
        }
    }
    if (tid == 1023) g_off[V_N] = part[1023];
}

__global__ void csr_fill_kernel(const int* __restrict__ edges)
{
    int e = blockIdx.x * blockDim.x + threadIdx.x;
    if (e >= E_N) return;
    int i = edges[2 * e], j = edges[2 * e + 1];
    int p = g_off[i] + atomicAdd(&g_cur[i], 1);
    g_adj[p] = j;
    p = g_off[j] + atomicAdd(&g_cur[j], 1);
    g_adj[p] = i;
}

// ---------------------------------------------------------------------------
// Fused gather + relu + split
// ---------------------------------------------------------------------------
__global__ void __launch_bounds__(256)
gather_split_kernel(const float* __restrict__ self, const float* __restrict__ nbr,
                    __nv_bfloat16* __restrict__ oh, __nv_bfloat16* __restrict__ ol)
{
    int v = blockIdx.x * 4 + (threadIdx.x >> 6);
    if (v >= V_N) return;
    int c = (threadIdx.x & 63) << 2;

    float4 acc = *(const float4*)(self + (size_t)v * H_N + c);
    int s = g_off[v], e = g_off[v + 1];
    for (int p = s; p < e; p++) {
        int u = g_adj[p];
        float4 w = *(const float4*)(nbr + (size_t)u * H_N + c);
        acc.x += w.x; acc.y += w.y; acc.z += w.z; acc.w += w.w;
    }
    acc.x = fmaxf(acc.x, 0.f); acc.y = fmaxf(acc.y, 0.f);
    acc.z = fmaxf(acc.z, 0.f); acc.w = fmaxf(acc.w, 0.f);

    uint32_t h01 = pack2(acc.x, acc.y);
    uint32_t h23 = pack2(acc.z, acc.w);
    __nv_bfloat162 hh01 = *(__nv_bfloat162*)&h01;
    __nv_bfloat162 hh23 = *(__nv_bfloat162*)&h23;
    uint32_t l01 = pack2(acc.x - __bfloat162float(hh01.x), acc.y - __bfloat162float(hh01.y));
    uint32_t l23 = pack2(acc.z - __bfloat162float(hh23.x), acc.w - __bfloat162float(hh23.y));
    *(uint2*)(oh + (size_t)v * H_N + c) = make_uint2(h01, h23);
    *(uint2*)(ol + (size_t)v * H_N + c) = make_uint2(l01, l23);
}

// ---------------------------------------------------------------------------
__global__ void prep_w_kernel(const float* __restrict__ W,
                              __nv_bfloat16* __restrict__ oh,
                              __nv_bfloat16* __restrict__ ol,
                              int Kin, int N, int K_pad,
                              size_t in_stride, size_t out_stride)
{
    int mat = blockIdx.y;
    const float* w = W + (size_t)mat * in_stride;
    __nv_bfloat16* ph = oh + (size_t)mat * out_stride;
    __nv_bfloat16* pl = ol + (size_t)mat * out_stride;
    int total = N * K_pad;
    int idx = blockIdx.x * blockDim.x + threadIdx.x;
    if (idx >= total) return;
    int n = idx / K_pad, k = idx - n * K_pad;
    float v = (k < Kin) ? w[(size_t)k * N + n] : 0.f;
    __nv_bfloat16 h = __float2bfloat16(v);
    ph[idx] = h;
    pl[idx] = __float2bfloat16(v - __bfloat162float(h));
}

// ---------------------------------------------------------------------------
template<bool RELU>
__global__ void split_kernel(const float* __restrict__ in,
                             __nv_bfloat16* __restrict__ oh,
                             __nv_bfloat16* __restrict__ ol, int n4)
{
    int idx = blockIdx.x * blockDim.x + threadIdx.x;
    if (idx >= n4) return;
    float4 v = ((const float4*)in)[idx];
    if (RELU) {
        v.x = fmaxf(v.x, 0.f); v.y = fmaxf(v.y, 0.f);
        v.z = fmaxf(v.z, 0.f); v.w = fmaxf(v.w, 0.f);
    }
    uint32_t h01 = pack2(v.x, v.y);
    uint32_t h23 = pack2(v.z, v.w);
    __nv_bfloat162 hh01 = *(__nv_bfloat162*)&h01;
    __nv_bfloat162 hh23 = *(__nv_bfloat162*)&h23;
    uint32_t l01 = pack2(v.x - __bfloat162float(hh01.x), v.y - __bfloat162float(hh01.y));
    uint32_t l23 = pack2(v.z - __bfloat162float(hh23.x), v.w - __bfloat162float(hh23.y));
    ((uint2*)oh)[idx] = make_uint2(h01, h23);
    ((uint2*)ol)[idx] = make_uint2(l01, l23);
}

// ---------------------------------------------------------------------------
__global__ void concat_verts_kernel(const float* __restrict__ verts)
{
    int idx = blockIdx.x * blockDim.x + threadIdx.x;  // V * 32
    if (idx >= V_N * 32) return;
    int v = idx >> 5, c = idx & 31;
    float x = (c < 3) ? verts[v * 3 + c] : 0.f;
    __nv_bfloat16 h = __float2bfloat16(x);
    __nv_bfloat16 l = __float2bfloat16(x - __bfloat162float(h));
    size_t o = (size_t)v * 288 + 256 + c;
    g_h0h[o] = h;
    g_h0l[o] = l;
}

// ---------------------------------------------------------------------------
__global__ void delta_kernel(const __nv_bfloat16* __restrict__ hh,
                             const __nv_bfloat16* __restrict__ hl,
                             const float* __restrict__ Wo,
                             const float* __restrict__ bo,
                             float* __restrict__ out)
{
    __shared__ float sW[H_N * 3];
    __shared__ float sb[3];
    for (int i = threadIdx.x; i < H_N * 3; i += blockDim.x) sW[i] = Wo[i];
    if (threadIdx.x < 3) sb[threadIdx.x] = bo[threadIdx.x];
    __syncthreads();

    int idx = blockIdx.x * blockDim.x + threadIdx.x;
    if (idx >= V_N * 3) return;
    int v = idx / 3, c = idx % 3;
    const __nv_bfloat162* ph = (const __nv_bfloat162*)(hh + (size_t)v * H_N);
    const __nv_bfloat162* pl = (const __nv_bfloat162*)(hl + (size_t)v * H_N);
    float s = sb[c];
#pragma unroll 4
    for (int k = 0; k < H_N / 2; k++) {
        __nv_bfloat162 a = ph[k], b = pl[k];
        float x0 = __bfloat162float(a.x) + __bfloat162float(b.x);
        float x1 = __bfloat162float(a.y) + __bfloat162float(b.y);
        s = fmaf(x0, sW[(2 * k) * 3 + c], s);
        s = fmaf(x1, sW[(2 * k + 1) * 3 + c], s);
    }
    out[idx] = s;
}

// ---------------------------------------------------------------------------
__global__ void tail_kernel(const float* __restrict__ z2,
                            const float* __restrict__ A3,
                            const float* __restrict__ a3,
                            const float* __restrict__ A4,
                            const float* __restrict__ a4,
                            float* __restrict__ conf)
{
    __shared__ float sA3[64 * 32];
    __shared__ float sa3[32];
    __shared__ float sA4[32];
    for (int i = threadIdx.x; i < 64 * 32; i += blockDim.x) sA3[i] = A3[i];
    if (threadIdx.x < 32) {
        sa3[threadIdx.x] = a3[threadIdx.x];
        sA4[threadIdx.x] = A4[threadIdx.x];
    }
    __syncthreads();

    float b4 = a4[0];
    for (int v = blockIdx.x * blockDim.x + threadIdx.x; v < V_N;
         v += gridDim.x * blockDim.x) {
        float x[64];
        const float* zr = z2 + (size_t)v * 64;
#pragma unroll
        for (int k = 0; k < 64; k++) x[k] = zr[k];
        float acc = b4;
#pragma unroll 4
        for (int m = 0; m < 32; m++) {
            float s = sa3[m];
#pragma unroll
            for (int k = 0; k < 64; k++) s = fmaf(x[k], sA3[k * 32 + m], s);
            acc = fmaf(fmaxf(s, 0.f), sA4[m], acc);
        }
        conf[v] = 1.f / (1.f + expf(-acc));
    }
}

// ---------------------------------------------------------------------------
// Launcher
// ---------------------------------------------------------------------------
extern "C" void kernel_launch(void* const* d_in, const int* in_sizes, int n_in,
                              void* d_out, int out_size)
{
    (void)in_sizes; (void)n_in; (void)out_size;
    const float* X     = (const float*)d_in[0];
    const float* verts = (const float*)d_in[1];
    const int*   edges = (const int*)  d_in[2];
    const float* Wb    = (const float*)d_in[3];
    const float* bb    = (const float*)d_in[4];
    const float* W0_0  = (const float*)d_in[5];
    const float* b0_0  = (const float*)d_in[6];
    const float* W1_0  = (const float*)d_in[7];
    const float* b1_0  = (const float*)d_in[8];
    const float* gW0   = (const float*)d_in[9];
    const float* gb0   = (const float*)d_in[10];
    const float* gW1   = (const float*)d_in[11];
    const float* gb1   = (const float*)d_in[12];
    const float* Wo    = (const float*)d_in[13];
    const float* bo    = (const float*)d_in[14];
    const float* A1    = (const float*)d_in[15];
    const float* a1    = (const float*)d_in[16];
    const float* A2    = (const float*)d_in[17];
    const float* a2    = (const float*)d_in[18];
    const float* A3    = (const float*)d_in[19];
    const float* a3    = (const float*)d_in[20];
    const float* A4    = (const float*)d_in[21];
    const float* a4    = (const float*)d_in[22];
    float* out = (float*)d_out;

    __nv_bfloat16 *pxh, *pxl, *ph0h, *ph0l, *pah, *pal, *pbh, *pbl, *pz1h, *pz1l;
    float *pt0, *pt1, *pz2;
    cudaGetSymbolAddress((void**)&pxh,  g_xh);   cudaGetSymbolAddress((void**)&pxl,  g_xl);
    cudaGetSymbolAddress((void**)&ph0h, g_h0h);  cudaGetSymbolAddress((void**)&ph0l, g_h0l);
    cudaGetSymbolAddress((void**)&pah,  g_ah);   cudaGetSymbolAddress((void**)&pal,  g_al);
    cudaGetSymbolAddress((void**)&pbh,  g_bh);   cudaGetSymbolAddress((void**)&pbl,  g_bl);
    cudaGetSymbolAddress((void**)&pz1h, g_z1h);  cudaGetSymbolAddress((void**)&pz1l, g_z1l);
    cudaGetSymbolAddress((void**)&pt0,  g_t0);   cudaGetSymbolAddress((void**)&pt1,  g_t1);
    cudaGetSymbolAddress((void**)&pz2,  g_z2);

    __nv_bfloat16 *pwb_h, *pwb_l, *pw0_h, *pw0_l, *pw1_h, *pw1_l;
    __nv_bfloat16 *pg0_h, *pg0_l, *pg1_h, *pg1_l, *pa1_h, *pa1_l, *pa2_h, *pa2_l;
    cudaGetSymbolAddress((void**)&pwb_h, wb_h);  cudaGetSymbolAddress((void**)&pwb_l, wb_l);
    cudaGetSymbolAddress((void**)&pw0_h, w0_h);  cudaGetSymbolAddress((void**)&pw0_l, w0_l);
    cudaGetSymbolAddress((void**)&pw1_h, w1_h);  cudaGetSymbolAddress((void**)&pw1_l, w1_l);
    cudaGetSymbolAddress((void**)&pg0_h, gw0_h); cudaGetSymbolAddress((void**)&pg0_l, gw0_l);
    cudaGetSymbolAddress((void**)&pg1_h, gw1_h); cudaGetSymbolAddress((void**)&pg1_l, gw1_l);
    cudaGetSymbolAddress((void**)&pa1_h, a1_h);  cudaGetSymbolAddress((void**)&pa1_l, a1_l);
    cudaGetSymbolAddress((void**)&pa2_h, a2_h);  cudaGetSymbolAddress((void**)&pa2_l, a2_l);

    const int SMEM = 65536;
    cudaFuncSetAttribute((const void*)gemm_bb<0, false>, cudaFuncAttributeMaxDynamicSharedMemorySize, SMEM);
    cudaFuncSetAttribute((const void*)gemm_bb<1, false>, cudaFuncAttributeMaxDynamicSharedMemorySize, SMEM);
    cudaFuncSetAttribute((const void*)gemm_bb<2, false>, cudaFuncAttributeMaxDynamicSharedMemorySize, SMEM);
    cudaFuncSetAttribute((const void*)gemm_bb<0, true >, cudaFuncAttributeMaxDynamicSharedMemorySize, SMEM);

    const int MT = (V_N + 127) / 128;   // 161
    const dim3 blk(256);
    const dim3 g2(2, MT);   // single GEMM, N=256
    const dim3 g1(1, MT);   // single GEMM, N<=128
    const dim3 g4(4, MT);   // fused pair, N=256 each
    const int GATHER_GRID = (V_N + 3) / 4;

    // ---- CSR build ----
    csr_zero_kernel<<<(V_N + 255) / 256, 256>>>();
    csr_count_kernel<<<(E_N + 255) / 256, 256>>>(edges);
    csr_scan_kernel<<<1, 1024>>>();
    csr_fill_kernel<<<(E_N + 255) / 256, 256>>>(edges);

    // ---- weight prep ----
    {
        int n;
        n = 256 * 3840;
        prep_w_kernel<<<dim3((n + 255) / 256, 1), 256>>>(Wb, pwb_h, pwb_l, 3840, 256, 3840, 0, 0);
        n = 256 * 288;
        prep_w_kernel<<<dim3((n + 255) / 256, 1), 256>>>(W0_0, pw0_h, pw0_l, 259, 256, 288, 0, 0);
        prep_w_kernel<<<dim3((n + 255) / 256, 1), 256>>>(W1_0, pw1_h, pw1_l, 259, 256, 288, 0, 0);
        n = 256 * 256;
        prep_w_kernel<<<dim3((n + 255) / 256, 9), 256>>>(gW0, pg0_h, pg0_l, 256, 256, 256, 65536, 65536);
        prep_w_kernel<<<dim3((n + 255) / 256, 9), 256>>>(gW1, pg1_h, pg1_l, 256, 256, 256, 65536, 65536);
        prep_w_kernel<<<dim3((n + 255) / 256, 1), 256>>>(A1, pa1_h, pa1_l, 256, 256, 256, 0, 0);
        n = 64 * 256;
        prep_w_kernel<<<dim3((n + 255) / 256, 1), 256>>>(A2, pa2_h, pa2_l, 256, 64, 256, 0, 0);
    }

    // ---- split X ----
    {
        int n4 = (V_N * F_N) / 4;
        split_kernel<false><<<(n4 + 255) / 256, 256>>>(X, pxh, pxl, n4);
    }

    // 1) backbone: h0[:, :256] = relu(X @ Wb + bb), written split
    gemm_bb<2, false><<<g2, blk, SMEM>>>(pxh, pxl, pwb_h, pwb_l, bb, nullptr,
                                         nullptr, nullptr, nullptr, nullptr,
                                         ph0h, ph0l, V_N, 256, 3840, 3840, 288);
    // 2) concat verts (split) into cols 256..287
    concat_verts_kernel<<<(V_N * 32 + 255) / 256, 256>>>(verts);

    // 3) layer 0 fused pair (K_pad=288): W0->pt0 (self), W1->pt1 (nbr)
    gemm_bb<0, true><<<g4, blk, SMEM>>>(ph0h, ph0l,
                                        pw0_h, pw0_l, b0_0, pt0,
                                        pw1_h, pw1_l, b1_0, pt1,
                                        nullptr, nullptr, V_N, 256, 288, 288, 256);
    gather_split_kernel<<<GATHER_GRID, 256>>>(pt0, pt1, pah, pal);

    // 4) layers 1..9, fused pairs
    __nv_bfloat16 *curh = pah, *curl = pal, *nxth = pbh, *nxtl = pbl;
    for (int k = 0; k < 9; k++) {
        const __nv_bfloat16* W0h = pg0_h + (size_t)k * 65536;
        const __nv_bfloat16* W0l = pg0_l + (size_t)k * 65536;
        const __nv_bfloat16* W1h = pg1_h + (size_t)k * 65536;
        const __nv_bfloat16* W1l = pg1_l + (size_t)k * 65536;
        const float* B0 = gb0 + (size_t)k * H_N;
        const float* B1 = gb1 + (size_t)k * H_N;
        gemm_bb<0, true><<<g4, blk, SMEM>>>(curh, curl,
                                            W0h, W0l, B0, pt0,
                                            W1h, W1l, B1, pt1,
                                            nullptr, nullptr, V_N, 256, 256, 256, 256);
        gather_split_kernel<<<GATHER_GRID, 256>>>(pt0, pt1, nxth, nxtl);
        __nv_bfloat16* t;
        t = curh; curh = nxth; nxth = t;
        t = curl; curl = nxtl; nxtl = t;
    }
    // final relu(h) split in (curh, curl)

    // 5) delta_v -> out[0 : V*3]
    delta_kernel<<<(V_N * 3 + 255) / 256, 256>>>(curh, curl, Wo, bo, out);

    // 6) z1 = relu(h_relu @ A1 + a1), written split
    gemm_bb<2, false><<<g2, blk, SMEM>>>(curh, curl, pa1_h, pa1_l, a1, nullptr,
                                         nullptr, nullptr, nullptr, nullptr,
                                         pz1h, pz1l, V_N, 256, 256, 256, 256);

    // 7) z2 = relu(z1 @ A2 + a2) fp32
    gemm_bb<1, false><<<g1, blk, SMEM>>>(pz1h, pz1l, pa2_h, pa2_l, a2, pz2,
                                         nullptr, nullptr, nullptr, nullptr,
                                         nullptr, nullptr, V_N, 64, 256, 256, 64);

    // 8) conf -> out[V*3 : V*4]
    tail_kernel<<<128, 256>>>(pz2, A3, a3, A4, a4, out + (size_t)V_N * 3);
}

// round 7
// speedup vs baseline: 4.8695x; 1.2382x over previous
#include <cuda_runtime.h>
#include <cuda_bf16.h>
#include <cuda_fp16.h>
#include <math.h>
#include <stdint.h>

#define V_N 20496
#define E_N 61440
#define F_N 3840
#define H_N 256

// ---------------------------------------------------------------------------
// Scratch (static device globals — no allocation allowed)
// ---------------------------------------------------------------------------
__device__ __align__(16) __half        g_xf [(size_t)V_N * F_N];   // fp16 X
__device__ __align__(16) __nv_bfloat16 g_h0h[(size_t)V_N * 288];
__device__ __align__(16) __nv_bfloat16 g_h0l[(size_t)V_N * 288];
__device__ __align__(16) __nv_bfloat16 g_ah [(size_t)V_N * H_N];
__device__ __align__(16) __nv_bfloat16 g_al [(size_t)V_N * H_N];
__device__ __align__(16) __nv_bfloat16 g_bh [(size_t)V_N * H_N];
__device__ __align__(16) __nv_bfloat16 g_bl [(size_t)V_N * H_N];
__device__ __align__(16) __nv_bfloat16 g_z1h[(size_t)V_N * H_N];
__device__ __align__(16) __nv_bfloat16 g_z1l[(size_t)V_N * H_N];
__device__ __align__(16) float g_t0 [(size_t)V_N * H_N];
__device__ __align__(16) float g_t1 [(size_t)V_N * H_N];
__device__ __align__(16) float g_z2 [(size_t)V_N * 64];

// CSR adjacency
__device__ int g_deg[V_N];
__device__ int g_cur[V_N];
__device__ int g_off[V_N + 1];
__device__ int g_adj[2 * E_N];

// weight scratch
__device__ __align__(16) __half        wb_f [256 * 3840];          // fp16 backbone W^T
__device__ __align__(16) __nv_bfloat16 w0_h [256 * 288];
__device__ __align__(16) __nv_bfloat16 w0_l [256 * 288];
__device__ __align__(16) __nv_bfloat16 w1_h [256 * 288];
__device__ __align__(16) __nv_bfloat16 w1_l [256 * 288];
__device__ __align__(16) __nv_bfloat16 gw0_h[9 * 256 * 256];
__device__ __align__(16) __nv_bfloat16 gw0_l[9 * 256 * 256];
__device__ __align__(16) __nv_bfloat16 gw1_h[9 * 256 * 256];
__device__ __align__(16) __nv_bfloat16 gw1_l[9 * 256 * 256];
__device__ __align__(16) __nv_bfloat16 a1_h [256 * 256];
__device__ __align__(16) __nv_bfloat16 a1_l [256 * 256];
__device__ __align__(16) __nv_bfloat16 a2_h [64 * 256];
__device__ __align__(16) __nv_bfloat16 a2_l [64 * 256];

// ---------------------------------------------------------------------------
// PTX helpers
// ---------------------------------------------------------------------------
__device__ __forceinline__ void ldsm_x4(uint32_t* r, uint32_t addr) {
    asm volatile("ldmatrix.sync.aligned.m8n8.x4.shared.b16 {%0,%1,%2,%3}, [%4];"
        : "=r"(r[0]), "=r"(r[1]), "=r"(r[2]), "=r"(r[3]) : "r"(addr));
}
__device__ __forceinline__ void mma16816(float* d, const uint32_t* a, const uint32_t* b) {
    asm volatile(
        "mma.sync.aligned.m16n8k16.row.col.f32.bf16.bf16.f32 "
        "{%0,%1,%2,%3}, {%4,%5,%6,%7}, {%8,%9}, {%0,%1,%2,%3};"
        : "+f"(d[0]), "+f"(d[1]), "+f"(d[2]), "+f"(d[3])
        : "r"(a[0]), "r"(a[1]), "r"(a[2]), "r"(a[3]), "r"(b[0]), "r"(b[1]));
}
__device__ __forceinline__ void mma16816h(float* d, const uint32_t* a, const uint32_t* b) {
    asm volatile(
        "mma.sync.aligned.m16n8k16.row.col.f32.f16.f16.f32 "
        "{%0,%1,%2,%3}, {%4,%5,%6,%7}, {%8,%9}, {%0,%1,%2,%3};"
        : "+f"(d[0]), "+f"(d[1]), "+f"(d[2]), "+f"(d[3])
        : "r"(a[0]), "r"(a[1]), "r"(a[2]), "r"(a[3]), "r"(b[0]), "r"(b[1]));
}
__device__ __forceinline__ void cp_async16(uint32_t dst, const void* src, bool pred) {
    int sz = pred ? 16 : 0;
    asm volatile("cp.async.cg.shared.global [%0], [%1], 16, %2;"
                 :: "r"(dst), "l"(src), "r"(sz));
}
#define CP_COMMIT() asm volatile("cp.async.commit_group;")
#define CP_WAIT(n)  asm volatile("cp.async.wait_group %0;" :: "n"(n))

__device__ __forceinline__ uint32_t pack2(float f0, float f1) {
    __nv_bfloat162 p;
    p.x = __float2bfloat16(f0);
    p.y = __float2bfloat16(f1);
    return *(uint32_t*)&p;
}
// bias + relu + bf16 hi/lo split store of a 2-row epilogue fragment
__device__ __forceinline__ void epi_split_store(
    __nv_bfloat16* Chi, __nv_bfloat16* Clo, int ldc, int M,
    int row0, int col, float b0, float b1, const float* d)
{
    float v0 = fmaxf(d[0] + b0, 0.f), v1 = fmaxf(d[1] + b1, 0.f);
    float v2 = fmaxf(d[2] + b0, 0.f), v3 = fmaxf(d[3] + b1, 0.f);
    uint32_t h01 = pack2(v0, v1);
    float r0f = __bfloat162float(((__nv_bfloat162*)&h01)->x);
    float r1f = __bfloat162float(((__nv_bfloat162*)&h01)->y);
    uint32_t l01 = pack2(v0 - r0f, v1 - r1f);
    uint32_t h23 = pack2(v2, v3);
    float r2f = __bfloat162float(((__nv_bfloat162*)&h23)->x);
    float r3f = __bfloat162float(((__nv_bfloat162*)&h23)->y);
    uint32_t l23 = pack2(v2 - r2f, v3 - r3f);
    if (row0 < M) {
        *(uint32_t*)(Chi + (size_t)row0 * ldc + col) = h01;
        *(uint32_t*)(Clo + (size_t)row0 * ldc + col) = l01;
    }
    if (row0 + 8 < M) {
        *(uint32_t*)(Chi + (size_t)(row0 + 8) * ldc + col) = h23;
        *(uint32_t*)(Clo + (size_t)(row0 + 8) * ldc + col) = l23;
    }
}

// ---------------------------------------------------------------------------
// Split-bf16 3-pass mma.sync GEMM (graph layers / z1 / z2).
// PAIR=true: grid.x=4, two GEMMs sharing A.
// OUT_MODE: 0=fp32, 1=fp32+relu, 2=bf16 split+relu.
// ---------------------------------------------------------------------------
#define OFF_ALO 8192
#define OFF_BHI 16384
#define OFF_BLO 24576
#define STAGE_B 32768

template<int OUT_MODE, bool PAIR>
__global__ void __launch_bounds__(256, 2)
gemm_bb(const __nv_bfloat16* __restrict__ Ahi, const __nv_bfloat16* __restrict__ Alo,
        const __nv_bfloat16* __restrict__ Bhi0, const __nv_bfloat16* __restrict__ Blo0,
        const float* __restrict__ bias0, float* __restrict__ Cf0,
        const __nv_bfloat16* __restrict__ Bhi1, const __nv_bfloat16* __restrict__ Blo1,
        const float* __restrict__ bias1, float* __restrict__ Cf1,
        __nv_bfloat16* __restrict__ Chi, __nv_bfloat16* __restrict__ Clo,
        int M, int N, int K_pad, int lda, int ldc)
{
    extern __shared__ char smp[];
    const uint32_t sbase = (uint32_t)__cvta_generic_to_shared(smp);

    const int tid  = threadIdx.x;
    const int lane = tid & 31;
    const int w    = tid >> 5;
    const int mw   = w & 3;
    const int nw   = w >> 2;
    const int bm   = blockIdx.y * 128;

    int sel, bn;
    if (PAIR) { sel = blockIdx.x >> 1; bn = (blockIdx.x & 1) * 128; }
    else      { sel = 0;               bn = blockIdx.x * 128; }

    const __nv_bfloat16* Bhi = sel ? Bhi1 : Bhi0;
    const __nv_bfloat16* Blo = sel ? Blo1 : Blo0;
    const float* bias        = sel ? bias1 : bias0;
    float* Cf                = sel ? Cf1 : Cf0;

    float acc[2][8][4];
#pragma unroll
    for (int a = 0; a < 2; a++)
#pragma unroll
        for (int b = 0; b < 8; b++)
#pragma unroll
            for (int c = 0; c < 4; c++) acc[a][b][c] = 0.f;

    const int nc = K_pad >> 5;

#define LOAD_CHUNK(cidx, stg_u32)                                                   \
    {                                                                               \
        const int col0 = (cidx) << 5;                                               \
        _Pragma("unroll")                                                           \
        for (int g = 0; g < 2; g++) {                                               \
            int id = tid + g * 256;                                                 \
            int br = id >> 2, bc = id & 3;                                          \
            uint32_t dst = (stg_u32) + (uint32_t)(br * 64 + ((bc ^ ((br >> 1) & 3)) << 4)); \
            bool pa = (bm + br) < M;                                                \
            size_t ga = (size_t)(bm + br) * lda + col0 + bc * 8;                    \
            cp_async16(dst,           Ahi + ga, pa);                                \
            cp_async16(dst + OFF_ALO, Alo + ga, pa);                                \
            bool pb = (bn + br) < N;                                                \
            size_t gb = (size_t)(bn + br) * K_pad + col0 + bc * 8;                  \
            cp_async16(dst + OFF_BHI, Bhi + gb, pb);                                \
            cp_async16(dst + OFF_BLO, Blo + gb, pb);                                \
        }                                                                           \
        CP_COMMIT();                                                                \
    }

    LOAD_CHUNK(0, sbase);

    for (int c = 0; c < nc; c++) {
        const int s = c & 1;
        const uint32_t stg = sbase + (uint32_t)(s * STAGE_B);

        if (c + 1 < nc) {
            LOAD_CHUNK(c + 1, sbase + (uint32_t)((s ^ 1) * STAGE_B));
            CP_WAIT(1);
        } else {
            CP_WAIT(0);
        }
        __syncthreads();

#pragma unroll
        for (int kk = 0; kk < 2; kk++) {
            uint32_t ah[2][4], al[2][4];
#pragma unroll
            for (int mi = 0; mi < 2; mi++) {
                int row = mw * 32 + mi * 16 + (lane & 15);
                int ch  = 2 * kk + (lane >> 4);
                int phys = ch ^ ((row >> 1) & 3);
                uint32_t off = stg + (uint32_t)(row * 64 + phys * 16);
                ldsm_x4(ah[mi], off);
                ldsm_x4(al[mi], off + OFF_ALO);
            }
#pragma unroll
            for (int h2 = 0; h2 < 2; h2++) {
                uint32_t bh[2][4], bl[2][4];
#pragma unroll
                for (int t4 = 0; t4 < 2; t4++) {
                    int row = nw * 64 + (h2 * 2 + t4) * 16 + (lane & 7) + ((lane >> 4) << 3);
                    int ch  = 2 * kk + ((lane >> 3) & 1);
                    int phys = ch ^ ((row >> 1) & 3);
                    uint32_t off = stg + (uint32_t)(row * 64 + phys * 16);
                    ldsm_x4(bh[t4], off + OFF_BHI);
                    ldsm_x4(bl[t4], off + OFF_BLO);
                }
#pragma unroll
                for (int mi = 0; mi < 2; mi++)
#pragma unroll
                    for (int q = 0; q < 4; q++) {
                        const uint32_t* pbh = &bh[q >> 1][(q & 1) * 2];
                        const uint32_t* pbl = &bl[q >> 1][(q & 1) * 2];
                        float* d = acc[mi][h2 * 4 + q];
                        mma16816(d, ah[mi], pbh);
                        mma16816(d, ah[mi], pbl);
                        mma16816(d, al[mi], pbh);
                    }
            }
        }
        __syncthreads();
    }

#pragma unroll
    for (int mi = 0; mi < 2; mi++) {
        int row0 = bm + mw * 32 + mi * 16 + (lane >> 2);
#pragma unroll
        for (int n8 = 0; n8 < 8; n8++) {
            int col = bn + nw * 64 + n8 * 8 + (lane & 3) * 2;
            if (col >= N) continue;
            float b0 = bias[col], b1 = bias[col + 1];
            float* d = acc[mi][n8];
            if (OUT_MODE == 2) {
                epi_split_store(Chi, Clo, ldc, M, row0, col, b0, b1, d);
            } else {
                float v0 = d[0] + b0, v1 = d[1] + b1;
                float v2 = d[2] + b0, v3 = d[3] + b1;
                if (OUT_MODE == 1) {
                    v0 = fmaxf(v0, 0.f); v1 = fmaxf(v1, 0.f);
                    v2 = fmaxf(v2, 0.f); v3 = fmaxf(v3, 0.f);
                }
                if (row0 < M)     *(float2*)(Cf + (size_t)row0 * ldc + col)       = make_float2(v0, v1);
                if (row0 + 8 < M) *(float2*)(Cf + (size_t)(row0 + 8) * ldc + col) = make_float2(v2, v3);
            }
        }
    }
}

// ---------------------------------------------------------------------------
// Single-pass fp16 GEMM (backbone). A fp16 [M,K], B fp16 [N,K].
// C = relu(A@B^T + bias) written as bf16 hi/lo split.
// SMEM stage: A(8K) B(8K); 64B rows, XOR swizzle.  STAGE 16K, 2 stages.
// ---------------------------------------------------------------------------
#define F16_OFF_B 8192
#define F16_STAGE 16384

__global__ void __launch_bounds__(256, 2)
gemm_f16(const __half* __restrict__ A, const __half* __restrict__ B,
         const float* __restrict__ bias,
         __nv_bfloat16* __restrict__ Chi, __nv_bfloat16* __restrict__ Clo,
         int M, int N, int K, int lda, int ldc)
{
    extern __shared__ char smp[];
    const uint32_t sbase = (uint32_t)__cvta_generic_to_shared(smp);

    const int tid  = threadIdx.x;
    const int lane = tid & 31;
    const int w    = tid >> 5;
    const int mw   = w & 3;
    const int nw   = w >> 2;
    const int bm   = blockIdx.y * 128;
    const int bn   = blockIdx.x * 128;

    float acc[2][8][4];
#pragma unroll
    for (int a = 0; a < 2; a++)
#pragma unroll
        for (int b = 0; b < 8; b++)
#pragma unroll
            for (int c = 0; c < 4; c++) acc[a][b][c] = 0.f;

    const int nc = K >> 5;

#define LOAD_CHUNK_F16(cidx, stg_u32)                                               \
    {                                                                               \
        const int col0 = (cidx) << 5;                                               \
        _Pragma("unroll")                                                           \
        for (int g = 0; g < 2; g++) {                                               \
            int id = tid + g * 256;                                                 \
            int br = id >> 2, bc = id & 3;                                          \
            uint32_t dst = (stg_u32) + (uint32_t)(br * 64 + ((bc ^ ((br >> 1) & 3)) << 4)); \
            bool pa = (bm + br) < M;                                                \
            size_t ga = (size_t)(bm + br) * lda + col0 + bc * 8;                    \
            cp_async16(dst, A + ga, pa);                                            \
            bool pb = (bn + br) < N;                                                \
            size_t gb = (size_t)(bn + br) * K + col0 + bc * 8;                      \
            cp_async16(dst + F16_OFF_B, B + gb, pb);                                \
        }                                                                           \
        CP_COMMIT();                                                                \
    }

    LOAD_CHUNK_F16(0, sbase);

    for (int c = 0; c < nc; c++) {
        const int s = c & 1;
        const uint32_t stg = sbase + (uint32_t)(s * F16_STAGE);

        if (c + 1 < nc) {
            LOAD_CHUNK_F16(c + 1, sbase + (uint32_t)((s ^ 1) * F16_STAGE));
            CP_WAIT(1);
        } else {
            CP_WAIT(0);
        }
        __syncthreads();

#pragma unroll
        for (int kk = 0; kk < 2; kk++) {
            uint32_t ah[2][4];
#pragma unroll
            for (int mi = 0; mi < 2; mi++) {
                int row = mw * 32 + mi * 16 + (lane & 15);
                int ch  = 2 * kk + (lane >> 4);
                int phys = ch ^ ((row >> 1) & 3);
                uint32_t off = stg + (uint32_t)(row * 64 + phys * 16);
                ldsm_x4(ah[mi], off);
            }
#pragma unroll
            for (int h2 = 0; h2 < 2; h2++) {
                uint32_t bh[2][4];
#pragma unroll
                for (int t4 = 0; t4 < 2; t4++) {
                    int row = nw * 64 + (h2 * 2 + t4) * 16 + (lane & 7) + ((lane >> 4) << 3);
                    int ch  = 2 * kk + ((lane >> 3) & 1);
                    int phys = ch ^ ((row >> 1) & 3);
                    uint32_t off = stg + (uint32_t)(row * 64 + phys * 16);
                    ldsm_x4(bh[t4], off + F16_OFF_B);
                }
#pragma unroll
                for (int mi = 0; mi < 2; mi++)
#pragma unroll
                    for (int q = 0; q < 4; q++)
                        mma16816h(acc[mi][h2 * 4 + q], ah[mi], &bh[q >> 1][(q & 1) * 2]);
            }
        }
        __syncthreads();
    }

#pragma unroll
    for (int mi = 0; mi < 2; mi++) {
        int row0 = bm + mw * 32 + mi * 16 + (lane >> 2);
#pragma unroll
        for (int n8 = 0; n8 < 8; n8++) {
            int col = bn + nw * 64 + n8 * 8 + (lane & 3) * 2;
            if (col >= N) continue;
            epi_split_store(Chi, Clo, ldc, M, row0, col,
                            bias[col], bias[col + 1], acc[mi][n8]);
        }
    }
}

// ---------------------------------------------------------------------------
// CSR build kernels
// ---------------------------------------------------------------------------
__global__ void csr_zero_kernel()
{
    int v = blockIdx.x * blockDim.x + threadIdx.x;
    if (v < V_N) { g_deg[v] = 0; g_cur[v] = 0; }
}

__global__ void csr_count_kernel(const int* __restrict__ edges)
{
    int e = blockIdx.x * blockDim.x + threadIdx.x;
    if (e >= E_N) return;
    atomicAdd(&g_deg[edges[2 * e]], 1);
    atomicAdd(&g_deg[edges[2 * e + 1]], 1);
}

__global__ void __launch_bounds__(1024) csr_scan_kernel()
{
    __shared__ int part[1024];
    const int tid = threadIdx.x;
    const int CH = (V_N + 1023) / 1024;
    const int base = tid * CH;
    int s = 0;
#pragma unroll
    for (int q = 0; q < CH; q++) {
        int idx = base + q;
        if (idx < V_N) s += g_deg[idx];
    }
    part[tid] = s;
    __syncthreads();
    for (int o = 1; o < 1024; o <<= 1) {
        int t = (tid >= o) ? part[tid - o] : 0;
        __syncthreads();
        part[tid] += t;
        __syncthreads();
    }
    int run = part[tid] - s;
    for (int q = 0; q < CH; q++) {
        int idx = base + q;
        if (idx < V_N) {
            g_off[idx] = run;
            run += g_deg[idx];
        }
    }
    if (tid == 1023) g_off[V_N] = part[1023];
}

__global__ void csr_fill_kernel(const int* __restrict__ edges)
{
    int e = blockIdx.x * blockDim.x + threadIdx.x;
    if (e >= E_N) return;
    int i = edges[2 * e], j = edges[2 * e + 1];
    int p = g_off[i] + atomicAdd(&g_cur[i], 1);
    g_adj[p] = j;
    p = g_off[j] + atomicAdd(&g_cur[j], 1);
    g_adj[p] = i;
}

// ---------------------------------------------------------------------------
// Fused gather + relu + split
// ---------------------------------------------------------------------------
__global__ void __launch_bounds__(256)
gather_split_kernel(const float* __restrict__ self, const float* __restrict__ nbr,
                    __nv_bfloat16* __restrict__ oh, __nv_bfloat16* __restrict__ ol)
{
    int v = blockIdx.x * 4 + (threadIdx.x >> 6);
    if (v >= V_N) return;
    int c = (threadIdx.x & 63) << 2;

    float4 acc = *(const float4*)(self + (size_t)v * H_N + c);
    int s = g_off[v], e = g_off[v + 1];
    for (int p = s; p < e; p++) {
        int u = g_adj[p];
        float4 w = *(const float4*)(nbr + (size_t)u * H_N + c);
        acc.x += w.x; acc.y += w.y; acc.z += w.z; acc.w += w.w;
    }
    acc.x = fmaxf(acc.x, 0.f); acc.y = fmaxf(acc.y, 0.f);
    acc.z = fmaxf(acc.z, 0.f); acc.w = fmaxf(acc.w, 0.f);

    uint32_t h01 = pack2(acc.x, acc.y);
    uint32_t h23 = pack2(acc.z, acc.w);
    __nv_bfloat162 hh01 = *(__nv_bfloat162*)&h01;
    __nv_bfloat162 hh23 = *(__nv_bfloat162*)&h23;
    uint32_t l01 = pack2(acc.x - __bfloat162float(hh01.x), acc.y - __bfloat162float(hh01.y));
    uint32_t l23 = pack2(acc.z - __bfloat162float(hh23.x), acc.w - __bfloat162float(hh23.y));
    *(uint2*)(oh + (size_t)v * H_N + c) = make_uint2(h01, h23);
    *(uint2*)(ol + (size_t)v * H_N + c) = make_uint2(l01, l23);
}

// ---------------------------------------------------------------------------
__global__ void prep_w_kernel(const float* __restrict__ W,
                              __nv_bfloat16* __restrict__ oh,
                              __nv_bfloat16* __restrict__ ol,
                              int Kin, int N, int K_pad,
                              size_t in_stride, size_t out_stride)
{
    int mat = blockIdx.y;
    const float* w = W + (size_t)mat * in_stride;
    __nv_bfloat16* ph = oh + (size_t)mat * out_stride;
    __nv_bfloat16* pl = ol + (size_t)mat * out_stride;
    int total = N * K_pad;
    int idx = blockIdx.x * blockDim.x + threadIdx.x;
    if (idx >= total) return;
    int n = idx / K_pad, k = idx - n * K_pad;
    float v = (k < Kin) ? w[(size_t)k * N + n] : 0.f;
    __nv_bfloat16 h = __float2bfloat16(v);
    ph[idx] = h;
    pl[idx] = __float2bfloat16(v - __bfloat162float(h));
}

// Wb[K,N] fp32 -> wt[N,K] fp16 (transpose, single precision level)
__global__ void prep_w_f16_kernel(const float* __restrict__ W,
                                  __half* __restrict__ o, int K, int N)
{
    int idx = blockIdx.x * blockDim.x + threadIdx.x;
    if (idx >= N * K) return;
    int n = idx / K, k = idx - n * K;
    o[idx] = __float2half(W[(size_t)k * N + n]);
}

// fp32 -> fp16 convert (X)
__global__ void split_f16_kernel(const float* __restrict__ in,
                                 __half* __restrict__ o, int n4)
{
    int idx = blockIdx.x * blockDim.x + threadIdx.x;
    if (idx >= n4) return;
    float4 v = ((const float4*)in)[idx];
    __half2 p0 = __floats2half2_rn(v.x, v.y);
    __half2 p1 = __floats2half2_rn(v.z, v.w);
    ((uint2*)o)[idx] = make_uint2(*(uint32_t*)&p0, *(uint32_t*)&p1);
}

// ---------------------------------------------------------------------------
__global__ void concat_verts_kernel(const float* __restrict__ verts)
{
    int idx = blockIdx.x * blockDim.x + threadIdx.x;  // V * 32
    if (idx >= V_N * 32) return;
    int v = idx >> 5, c = idx & 31;
    float x = (c < 3) ? verts[v * 3 + c] : 0.f;
    __nv_bfloat16 h = __float2bfloat16(x);
    __nv_bfloat16 l = __float2bfloat16(x - __bfloat162float(h));
    size_t o = (size_t)v * 288 + 256 + c;
    g_h0h[o] = h;
    g_h0l[o] = l;
}

// ---------------------------------------------------------------------------
__global__ void delta_kernel(const __nv_bfloat16* __restrict__ hh,
                             const __nv_bfloat16* __restrict__ hl,
                             const float* __restrict__ Wo,
                             const float* __restrict__ bo,
                             float* __restrict__ out)
{
    __shared__ float sW[H_N * 3];
    __shared__ float sb[3];
    for (int i = threadIdx.x; i < H_N * 3; i += blockDim.x) sW[i] = Wo[i];
    if (threadIdx.x < 3) sb[threadIdx.x] = bo[threadIdx.x];
    __syncthreads();

    int idx = blockIdx.x * blockDim.x + threadIdx.x;
    if (idx >= V_N * 3) return;
    int v = idx / 3, c = idx % 3;
    const __nv_bfloat162* ph = (const __nv_bfloat162*)(hh + (size_t)v * H_N);
    const __nv_bfloat162* pl = (const __nv_bfloat162*)(hl + (size_t)v * H_N);
    float s = sb[c];
#pragma unroll 4
    for (int k = 0; k < H_N / 2; k++) {
        __nv_bfloat162 a = ph[k], b = pl[k];
        float x0 = __bfloat162float(a.x) + __bfloat162float(b.x);
        float x1 = __bfloat162float(a.y) + __bfloat162float(b.y);
        s = fmaf(x0, sW[(2 * k) * 3 + c], s);
        s = fmaf(x1, sW[(2 * k + 1) * 3 + c], s);
    }
    out[idx] = s;
}

// ---------------------------------------------------------------------------
__global__ void tail_kernel(const float* __restrict__ z2,
                            const float* __restrict__ A3,
                            const float* __restrict__ a3,
                            const float* __restrict__ A4,
                            const float* __restrict__ a4,
                            float* __restrict__ conf)
{
    __shared__ float sA3[64 * 32];
    __shared__ float sa3[32];
    __shared__ float sA4[32];
    for (int i = threadIdx.x; i < 64 * 32; i += blockDim.x) sA3[i] = A3[i];
    if (threadIdx.x < 32) {
        sa3[threadIdx.x] = a3[threadIdx.x];
        sA4[threadIdx.x] = A4[threadIdx.x];
    }
    __syncthreads();

    float b4 = a4[0];
    for (int v = blockIdx.x * blockDim.x + threadIdx.x; v < V_N;
         v += gridDim.x * blockDim.x) {
        float x[64];
        const float* zr = z2 + (size_t)v * 64;
#pragma unroll
        for (int k = 0; k < 64; k++) x[k] = zr[k];
        float acc = b4;
#pragma unroll 4
        for (int m = 0; m < 32; m++) {
            float s = sa3[m];
#pragma unroll
            for (int k = 0; k < 64; k++) s = fmaf(x[k], sA3[k * 32 + m], s);
            acc = fmaf(fmaxf(s, 0.f), sA4[m], acc);
        }
        conf[v] = 1.f / (1.f + expf(-acc));
    }
}

// ---------------------------------------------------------------------------
// Launcher
// ---------------------------------------------------------------------------
extern "C" void kernel_launch(void* const* d_in, const int* in_sizes, int n_in,
                              void* d_out, int out_size)
{
    (void)in_sizes; (void)n_in; (void)out_size;
    const float* X     = (const float*)d_in[0];
    const float* verts = (const float*)d_in[1];
    const int*   edges = (const int*)  d_in[2];
    const float* Wb    = (const float*)d_in[3];
    const float* bb    = (const float*)d_in[4];
    const float* W0_0  = (const float*)d_in[5];
    const float* b0_0  = (const float*)d_in[6];
    const float* W1_0  = (const float*)d_in[7];
    const float* b1_0  = (const float*)d_in[8];
    const float* gW0   = (const float*)d_in[9];
    const float* gb0   = (const float*)d_in[10];
    const float* gW1   = (const float*)d_in[11];
    const float* gb1   = (const float*)d_in[12];
    const float* Wo    = (const float*)d_in[13];
    const float* bo    = (const float*)d_in[14];
    const float* A1    = (const float*)d_in[15];
    const float* a1    = (const float*)d_in[16];
    const float* A2    = (const float*)d_in[17];
    const float* a2    = (const float*)d_in[18];
    const float* A3    = (const float*)d_in[19];
    const float* a3    = (const float*)d_in[20];
    const float* A4    = (const float*)d_in[21];
    const float* a4    = (const float*)d_in[22];
    float* out = (float*)d_out;

    __half *pxf, *pwbf;
    __nv_bfloat16 *ph0h, *ph0l, *pah, *pal, *pbh, *pbl, *pz1h, *pz1l;
    float *pt0, *pt1, *pz2;
    cudaGetSymbolAddress((void**)&pxf,  g_xf);
    cudaGetSymbolAddress((void**)&pwbf, wb_f);
    cudaGetSymbolAddress((void**)&ph0h, g_h0h);  cudaGetSymbolAddress((void**)&ph0l, g_h0l);
    cudaGetSymbolAddress((void**)&pah,  g_ah);   cudaGetSymbolAddress((void**)&pal,  g_al);
    cudaGetSymbolAddress((void**)&pbh,  g_bh);   cudaGetSymbolAddress((void**)&pbl,  g_bl);
    cudaGetSymbolAddress((void**)&pz1h, g_z1h);  cudaGetSymbolAddress((void**)&pz1l, g_z1l);
    cudaGetSymbolAddress((void**)&pt0,  g_t0);   cudaGetSymbolAddress((void**)&pt1,  g_t1);
    cudaGetSymbolAddress((void**)&pz2,  g_z2);

    __nv_bfloat16 *pw0_h, *pw0_l, *pw1_h, *pw1_l;
    __nv_bfloat16 *pg0_h, *pg0_l, *pg1_h, *pg1_l, *pa1_h, *pa1_l, *pa2_h, *pa2_l;
    cudaGetSymbolAddress((void**)&pw0_h, w0_h);  cudaGetSymbolAddress((void**)&pw0_l, w0_l);
    cudaGetSymbolAddress((void**)&pw1_h, w1_h);  cudaGetSymbolAddress((void**)&pw1_l, w1_l);
    cudaGetSymbolAddress((void**)&pg0_h, gw0_h); cudaGetSymbolAddress((void**)&pg0_l, gw0_l);
    cudaGetSymbolAddress((void**)&pg1_h, gw1_h); cudaGetSymbolAddress((void**)&pg1_l, gw1_l);
    cudaGetSymbolAddress((void**)&pa1_h, a1_h);  cudaGetSymbolAddress((void**)&pa1_l, a1_l);
    cudaGetSymbolAddress((void**)&pa2_h, a2_h);  cudaGetSymbolAddress((void**)&pa2_l, a2_l);

    const int SMEM = 65536;
    const int SMEMF = 32768;
    cudaFuncSetAttribute((const void*)gemm_bb<0, false>, cudaFuncAttributeMaxDynamicSharedMemorySize, SMEM);
    cudaFuncSetAttribute((const void*)gemm_bb<1, false>, cudaFuncAttributeMaxDynamicSharedMemorySize, SMEM);
    cudaFuncSetAttribute((const void*)gemm_bb<2, false>, cudaFuncAttributeMaxDynamicSharedMemorySize, SMEM);
    cudaFuncSetAttribute((const void*)gemm_bb<0, true >, cudaFuncAttributeMaxDynamicSharedMemorySize, SMEM);
    cudaFuncSetAttribute((const void*)gemm_f16, cudaFuncAttributeMaxDynamicSharedMemorySize, SMEMF);

    const int MT = (V_N + 127) / 128;   // 161
    const dim3 blk(256);
    const dim3 g2(2, MT);
    const dim3 g1(1, MT);
    const dim3 g4(4, MT);
    const int GATHER_GRID = (V_N + 3) / 4;

    // ---- CSR build ----
    csr_zero_kernel<<<(V_N + 255) / 256, 256>>>();
    csr_count_kernel<<<(E_N + 255) / 256, 256>>>(edges);
    csr_scan_kernel<<<1, 1024>>>();
    csr_fill_kernel<<<(E_N + 255) / 256, 256>>>(edges);

    // ---- weight prep ----
    {
        int n;
        n = 256 * 3840;
        prep_w_f16_kernel<<<(n + 255) / 256, 256>>>(Wb, pwbf, 3840, 256);
        n = 256 * 288;
        prep_w_kernel<<<dim3((n + 255) / 256, 1), 256>>>(W0_0, pw0_h, pw0_l, 259, 256, 288, 0, 0);
        prep_w_kernel<<<dim3((n + 255) / 256, 1), 256>>>(W1_0, pw1_h, pw1_l, 259, 256, 288, 0, 0);
        n = 256 * 256;
        prep_w_kernel<<<dim3((n + 255) / 256, 9), 256>>>(gW0, pg0_h, pg0_l, 256, 256, 256, 65536, 65536);
        prep_w_kernel<<<dim3((n + 255) / 256, 9), 256>>>(gW1, pg1_h, pg1_l, 256, 256, 256, 65536, 65536);
        prep_w_kernel<<<dim3((n + 255) / 256, 1), 256>>>(A1, pa1_h, pa1_l, 256, 256, 256, 0, 0);
        n = 64 * 256;
        prep_w_kernel<<<dim3((n + 255) / 256, 1), 256>>>(A2, pa2_h, pa2_l, 256, 64, 256, 0, 0);
    }

    // ---- X -> fp16 ----
    {
        int n4 = (V_N * F_N) / 4;
        split_f16_kernel<<<(n4 + 255) / 256, 256>>>(X, pxf, n4);
    }

    // 1) backbone (fp16 single-pass): h0[:, :256] = relu(X @ Wb + bb), split bf16
    gemm_f16<<<g2, blk, SMEMF>>>(pxf, pwbf, bb, ph0h, ph0l, V_N, 256, 3840, 3840, 288);

    // 2) concat verts
    concat_verts_kernel<<<(V_N * 32 + 255) / 256, 256>>>(verts);

    // 3) layer 0 fused pair (K_pad=288)
    gemm_bb<0, true><<<g4, blk, SMEM>>>(ph0h, ph0l,
                                        pw0_h, pw0_l, b0_0, pt0,
                                        pw1_h, pw1_l, b1_0, pt1,
                                        nullptr, nullptr, V_N, 256, 288, 288, 256);
    gather_split_kernel<<<GATHER_GRID, 256>>>(pt0, pt1, pah, pal);

    // 4) layers 1..9
    __nv_bfloat16 *curh = pah, *curl = pal, *nxth = pbh, *nxtl = pbl;
    for (int k = 0; k < 9; k++) {
        const __nv_bfloat16* W0h = pg0_h + (size_t)k * 65536;
        const __nv_bfloat16* W0l = pg0_l + (size_t)k * 65536;
        const __nv_bfloat16* W1h = pg1_h + (size_t)k * 65536;
        const __nv_bfloat16* W1l = pg1_l + (size_t)k * 65536;
        const float* B0 = gb0 + (size_t)k * H_N;
        const float* B1 = gb1 + (size_t)k * H_N;
        gemm_bb<0, true><<<g4, blk, SMEM>>>(curh, curl,
                                            W0h, W0l, B0, pt0,
                                            W1h, W1l, B1, pt1,
                                            nullptr, nullptr, V_N, 256, 256, 256, 256);
        gather_split_kernel<<<GATHER_GRID, 256>>>(pt0, pt1, nxth, nxtl);
        __nv_bfloat16* t;
        t = curh; curh = nxth; nxth = t;
        t = curl; curl = nxtl; nxtl = t;
    }

    // 5) delta_v -> out[0 : V*3]
    delta_kernel<<<(V_N * 3 + 255) / 256, 256>>>(curh, curl, Wo, bo, out);

    // 6) z1 = relu(h_relu @ A1 + a1), split bf16
    gemm_bb<2, false><<<g2, blk, SMEM>>>(curh, curl, pa1_h, pa1_l, a1, nullptr,
                                         nullptr, nullptr, nullptr, nullptr,
                                         pz1h, pz1l, V_N, 256, 256, 256, 256);

    // 7) z2 = relu(z1 @ A2 + a2) fp32
    gemm_bb<1, false><<<g1, blk, SMEM>>>(pz1h, pz1l, pa2_h, pa2_l, a2, pz2,
                                         nullptr, nullptr, nullptr, nullptr,
                                         nullptr, nullptr, V_N, 64, 256, 256, 64);

    // 8) conf -> out[V*3 : V*4]
    tail_kernel<<<128, 256>>>(pz2, A3, a3, A4, a4, out + (size_t)V_N * 3);
}

// round 10
// speedup vs baseline: 5.8157x; 1.1943x over previous
#include <cuda_runtime.h>
#include <cuda_fp16.h>
#include <math.h>
#include <stdint.h>

#define V_N 20496
#define E_N 61440
#define F_N 3840
#define H_N 256

// ---------------------------------------------------------------------------
// Scratch (static device globals — no allocation allowed)
// ---------------------------------------------------------------------------
__device__ __align__(16) __half g_xf [(size_t)V_N * F_N];   // fp16 X
__device__ __align__(16) __half g_h0 [(size_t)V_N * 288];   // fp16 concat(h_img, verts)
__device__ __align__(16) __half g_a  [(size_t)V_N * H_N];   // fp16 act ping
__device__ __align__(16) __half g_b  [(size_t)V_N * H_N];   // fp16 act pong
__device__ __align__(16) __half g_z1 [(size_t)V_N * H_N];
__device__ __align__(16) float  g_t0 [(size_t)V_N * H_N];
__device__ __align__(16) float  g_t1 [(size_t)V_N * H_N];
__device__ __align__(16) float  g_z2 [(size_t)V_N * 64];

// CSR adjacency
__device__ int g_deg[V_N];
__device__ int g_cur[V_N];
__device__ int g_off[V_N + 1];
__device__ int g_adj[2 * E_N];

// weight scratch, transposed [N, K_pad]
__device__ __align__(16) __half wb_f [256 * 3840];            // backbone single fp16
__device__ __align__(16) __half w0_h [256 * 288];
__device__ __align__(16) __half w0_l [256 * 288];
__device__ __align__(16) __half w1_h [256 * 288];
__device__ __align__(16) __half w1_l [256 * 288];
__device__ __align__(16) __half gw0_h[9 * 256 * 256];
__device__ __align__(16) __half gw0_l[9 * 256 * 256];
__device__ __align__(16) __half gw1_h[9 * 256 * 256];
__device__ __align__(16) __half gw1_l[9 * 256 * 256];
__device__ __align__(16) __half a1_h [256 * 256];
__device__ __align__(16) __half a1_l [256 * 256];
__device__ __align__(16) __half a2_h [64 * 256];
__device__ __align__(16) __half a2_l [64 * 256];

// ---------------------------------------------------------------------------
// PTX helpers
// ---------------------------------------------------------------------------
__device__ __forceinline__ void ldsm_x4(uint32_t* r, uint32_t addr) {
    asm volatile("ldmatrix.sync.aligned.m8n8.x4.shared.b16 {%0,%1,%2,%3}, [%4];"
        : "=r"(r[0]), "=r"(r[1]), "=r"(r[2]), "=r"(r[3]) : "r"(addr));
}
__device__ __forceinline__ void mma16816h(float* d, const uint32_t* a, const uint32_t* b) {
    asm volatile(
        "mma.sync.aligned.m16n8k16.row.col.f32.f16.f16.f32 "
        "{%0,%1,%2,%3}, {%4,%5,%6,%7}, {%8,%9}, {%0,%1,%2,%3};"
        : "+f"(d[0]), "+f"(d[1]), "+f"(d[2]), "+f"(d[3])
        : "r"(a[0]), "r"(a[1]), "r"(a[2]), "r"(a[3]), "r"(b[0]), "r"(b[1]));
}
__device__ __forceinline__ void cp_async16(uint32_t dst, const void* src, bool pred) {
    int sz = pred ? 16 : 0;
    asm volatile("cp.async.cg.shared.global [%0], [%1], 16, %2;"
                 :: "r"(dst), "l"(src), "r"(sz));
}
#define CP_COMMIT() asm volatile("cp.async.commit_group;")
#define CP_WAIT(n)  asm volatile("cp.async.wait_group %0;" :: "n"(n))

__device__ __forceinline__ uint32_t pack2h(float f0, float f1) {
    __half2 p = __floats2half2_rn(f0, f1);
    return *(uint32_t*)&p;
}

// ---------------------------------------------------------------------------
// fp16 mma.sync GEMM.
// WSPLIT: B given as fp16 hi/lo; acc += A*Bh + A*Bl (2 passes, weight exact).
// PAIR: grid.x=4, two GEMMs sharing A (sel = blockIdx.x>>1).
// OUT_MODE: 0 = fp32 out, 1 = fp32 + relu, 3 = fp16 + relu.
// SMEM stage: A(8K) Bh(8K) [Bl(8K)]; 64B rows, XOR swizzle.
// ---------------------------------------------------------------------------
template<int OUT_MODE, bool PAIR, bool WSPLIT>
__global__ void __launch_bounds__(256, 2)
gemm_tpl(const __half* __restrict__ A,
         const __half* __restrict__ B0h, const __half* __restrict__ B0l,
         const float* __restrict__ bias0, float* __restrict__ Cf0, __half* __restrict__ Ch0,
         const __half* __restrict__ B1h, const __half* __restrict__ B1l,
         const float* __restrict__ bias1, float* __restrict__ Cf1, __half* __restrict__ Ch1,
         int M, int N, int K_pad, int lda, int ldc)
{
    constexpr uint32_t BH_OFF = 8192;
    constexpr uint32_t BL_OFF = 16384;
    constexpr uint32_t STAGE  = WSPLIT ? 24576 : 16384;

    extern __shared__ char smp[];
    const uint32_t sbase = (uint32_t)__cvta_generic_to_shared(smp);

    const int tid  = threadIdx.x;
    const int lane = tid & 31;
    const int w    = tid >> 5;
    const int mw   = w & 3;
    const int nw   = w >> 2;
    const int bm   = blockIdx.y * 128;

    int sel, bn;
    if (PAIR) { sel = blockIdx.x >> 1; bn = (blockIdx.x & 1) * 128; }
    else      { sel = 0;               bn = blockIdx.x * 128; }

    const __half* Bh   = sel ? B1h : B0h;
    const __half* Bl   = sel ? B1l : B0l;
    const float*  bias = sel ? bias1 : bias0;
    float*        Cf   = sel ? Cf1 : Cf0;
    __half*       Ch   = sel ? Ch1 : Ch0;

    float acc[2][8][4];
#pragma unroll
    for (int a = 0; a < 2; a++)
#pragma unroll
        for (int b = 0; b < 8; b++)
#pragma unroll
            for (int c = 0; c < 4; c++) acc[a][b][c] = 0.f;

    const int nc = K_pad >> 5;

#define LOAD_CHUNK_T(cidx, stg_u32)                                                 \
    {                                                                               \
        const int col0 = (cidx) << 5;                                               \
        _Pragma("unroll")                                                           \
        for (int g = 0; g < 2; g++) {                                               \
            int id = tid + g * 256;                                                 \
            int br = id >> 2, bc = id & 3;                                          \
            uint32_t dst = (stg_u32) + (uint32_t)(br * 64 + ((bc ^ ((br >> 1) & 3)) << 4)); \
            bool pa = (bm + br) < M;                                                \
            size_t ga = (size_t)(bm + br) * lda + col0 + bc * 8;                    \
            cp_async16(dst, A + ga, pa);                                            \
            bool pb = (bn + br) < N;                                                \
            size_t gb = (size_t)(bn + br) * K_pad + col0 + bc * 8;                  \
            cp_async16(dst + BH_OFF, Bh + gb, pb);                                  \
            if (WSPLIT) cp_async16(dst + BL_OFF, Bl + gb, pb);                      \
        }                                                                           \
        CP_COMMIT();                                                                \
    }

    LOAD_CHUNK_T(0, sbase);

    for (int c = 0; c < nc; c++) {
        const int s = c & 1;
        const uint32_t stg = sbase + (uint32_t)(s * STAGE);

        if (c + 1 < nc) {
            LOAD_CHUNK_T(c + 1, sbase + (uint32_t)((s ^ 1) * STAGE));
            CP_WAIT(1);
        } else {
            CP_WAIT(0);
        }
        __syncthreads();

#pragma unroll
        for (int kk = 0; kk < 2; kk++) {
            uint32_t ar[2][4];
#pragma unroll
            for (int mi = 0; mi < 2; mi++) {
                int row = mw * 32 + mi * 16 + (lane & 15);
                int ch  = 2 * kk + (lane >> 4);
                int phys = ch ^ ((row >> 1) & 3);
                uint32_t off = stg + (uint32_t)(row * 64 + phys * 16);
                ldsm_x4(ar[mi], off);
            }
#pragma unroll
            for (int h2 = 0; h2 < 2; h2++) {
                uint32_t bh[2][4], bl[2][4];
#pragma unroll
                for (int t4 = 0; t4 < 2; t4++) {
                    int row = nw * 64 + (h2 * 2 + t4) * 16 + (lane & 7) + ((lane >> 4) << 3);
                    int ch  = 2 * kk + ((lane >> 3) & 1);
                    int phys = ch ^ ((row >> 1) & 3);
                    uint32_t off = stg + (uint32_t)(row * 64 + phys * 16);
                    ldsm_x4(bh[t4], off + BH_OFF);
                    if (WSPLIT) ldsm_x4(bl[t4], off + BL_OFF);
                }
#pragma unroll
                for (int mi = 0; mi < 2; mi++)
#pragma unroll
                    for (int q = 0; q < 4; q++) {
                        float* d = acc[mi][h2 * 4 + q];
                        mma16816h(d, ar[mi], &bh[q >> 1][(q & 1) * 2]);
                        if (WSPLIT) mma16816h(d, ar[mi], &bl[q >> 1][(q & 1) * 2]);
                    }
            }
        }
        __syncthreads();
    }

    // ---------------- epilogue ----------------
#pragma unroll
    for (int mi = 0; mi < 2; mi++) {
        int row0 = bm + mw * 32 + mi * 16 + (lane >> 2);
#pragma unroll
        for (int n8 = 0; n8 < 8; n8++) {
            int col = bn + nw * 64 + n8 * 8 + (lane & 3) * 2;
            if (col >= N) continue;
            float b0 = bias[col], b1 = bias[col + 1];
            float* d = acc[mi][n8];
            float v0 = d[0] + b0, v1 = d[1] + b1;
            float v2 = d[2] + b0, v3 = d[3] + b1;
            if (OUT_MODE >= 1) {
                v0 = fmaxf(v0, 0.f); v1 = fmaxf(v1, 0.f);
                v2 = fmaxf(v2, 0.f); v3 = fmaxf(v3, 0.f);
            }
            if (OUT_MODE == 3) {
                if (row0 < M)     *(uint32_t*)(Ch + (size_t)row0 * ldc + col)       = pack2h(v0, v1);
                if (row0 + 8 < M) *(uint32_t*)(Ch + (size_t)(row0 + 8) * ldc + col) = pack2h(v2, v3);
            } else {
                if (row0 < M)     *(float2*)(Cf + (size_t)row0 * ldc + col)       = make_float2(v0, v1);
                if (row0 + 8 < M) *(float2*)(Cf + (size_t)(row0 + 8) * ldc + col) = make_float2(v2, v3);
            }
        }
    }
}

// ---------------------------------------------------------------------------
// CSR build kernels
// ---------------------------------------------------------------------------
__global__ void csr_zero_kernel()
{
    int v = blockIdx.x * blockDim.x + threadIdx.x;
    if (v < V_N) { g_deg[v] = 0; g_cur[v] = 0; }
}

__global__ void csr_count_kernel(const int* __restrict__ edges)
{
    int e = blockIdx.x * blockDim.x + threadIdx.x;
    if (e >= E_N) return;
    atomicAdd(&g_deg[edges[2 * e]], 1);
    atomicAdd(&g_deg[edges[2 * e + 1]], 1);
}

__global__ void __launch_bounds__(1024) csr_scan_kernel()
{
    __shared__ int part[1024];
    const int tid = threadIdx.x;
    const int CH = (V_N + 1023) / 1024;
    const int base = tid * CH;
    int s = 0;
#pragma unroll
    for (int q = 0; q < CH; q++) {
        int idx = base + q;
        if (idx < V_N) s += g_deg[idx];
    }
    part[tid] = s;
    __syncthreads();
    for (int o = 1; o < 1024; o <<= 1) {
        int t = (tid >= o) ? part[tid - o] : 0;
        __syncthreads();
        part[tid] += t;
        __syncthreads();
    }
    int run = part[tid] - s;
    for (int q = 0; q < CH; q++) {
        int idx = base + q;
        if (idx < V_N) {
            g_off[idx] = run;
            run += g_deg[idx];
        }
    }
    if (tid == 1023) g_off[V_N] = part[1023];
}

__global__ void csr_fill_kernel(const int* __restrict__ edges)
{
    int e = blockIdx.x * blockDim.x + threadIdx.x;
    if (e >= E_N) return;
    int i = edges[2 * e], j = edges[2 * e + 1];
    int p = g_off[i] + atomicAdd(&g_cur[i], 1);
    g_adj[p] = j;
    p = g_off[j] + atomicAdd(&g_cur[j], 1);
    g_adj[p] = i;
}

// ---------------------------------------------------------------------------
// Fused gather + relu -> fp16
// ---------------------------------------------------------------------------
__global__ void __launch_bounds__(256)
gather_f16_kernel(const float* __restrict__ self, const float* __restrict__ nbr,
                  __half* __restrict__ oh)
{
    int v = blockIdx.x * 4 + (threadIdx.x >> 6);
    if (v >= V_N) return;
    int c = (threadIdx.x & 63) << 2;

    float4 acc = *(const float4*)(self + (size_t)v * H_N + c);
    int s = g_off[v], e = g_off[v + 1];
    for (int p = s; p < e; p++) {
        int u = g_adj[p];
        float4 w = *(const float4*)(nbr + (size_t)u * H_N + c);
        acc.x += w.x; acc.y += w.y; acc.z += w.z; acc.w += w.w;
    }
    acc.x = fmaxf(acc.x, 0.f); acc.y = fmaxf(acc.y, 0.f);
    acc.z = fmaxf(acc.z, 0.f); acc.w = fmaxf(acc.w, 0.f);

    *(uint2*)(oh + (size_t)v * H_N + c) =
        make_uint2(pack2h(acc.x, acc.y), pack2h(acc.z, acc.w));
}

// ---------------------------------------------------------------------------
// Weight prep: W[Kin,N] fp32 -> Wt[N,K_pad] fp16 hi + lo (transpose), batched
// ---------------------------------------------------------------------------
__global__ void prep_w_hl_kernel(const float* __restrict__ W,
                                 __half* __restrict__ oh, __half* __restrict__ ol,
                                 int Kin, int N, int K_pad,
                                 size_t in_stride, size_t out_stride)
{
    int mat = blockIdx.y;
    const float* w = W + (size_t)mat * in_stride;
    __half* ph = oh + (size_t)mat * out_stride;
    __half* pl = ol + (size_t)mat * out_stride;
    int idx = blockIdx.x * blockDim.x + threadIdx.x;
    if (idx >= N * K_pad) return;
    int n = idx / K_pad, k = idx - n * K_pad;
    float v = (k < Kin) ? w[(size_t)k * N + n] : 0.f;
    __half h = __float2half_rn(v);
    ph[idx] = h;
    pl[idx] = __float2half_rn(v - __half2float(h));
}

// backbone: single fp16 transpose
__global__ void prep_w_f16_kernel(const float* __restrict__ W,
                                  __half* __restrict__ o, int K, int N)
{
    int idx = blockIdx.x * blockDim.x + threadIdx.x;
    if (idx >= N * K) return;
    int n = idx / K, k = idx - n * K;
    o[idx] = __float2half(W[(size_t)k * N + n]);
}

// fp32 -> fp16 convert (X)
__global__ void conv_f16_kernel(const float* __restrict__ in,
                                __half* __restrict__ o, int n4)
{
    int idx = blockIdx.x * blockDim.x + threadIdx.x;
    if (idx >= n4) return;
    float4 v = ((const float4*)in)[idx];
    ((uint2*)o)[idx] = make_uint2(pack2h(v.x, v.y), pack2h(v.z, v.w));
}

// ---------------------------------------------------------------------------
__global__ void concat_verts_kernel(const float* __restrict__ verts)
{
    int idx = blockIdx.x * blockDim.x + threadIdx.x;  // V * 32
    if (idx >= V_N * 32) return;
    int v = idx >> 5, c = idx & 31;
    float x = (c < 3) ? verts[v * 3 + c] : 0.f;
    g_h0[(size_t)v * 288 + 256 + c] = __float2half(x);
}

// ---------------------------------------------------------------------------
// delta_v = h @ Wo + bo   (h fp16, relu already applied)
// ---------------------------------------------------------------------------
__global__ void delta_kernel(const __half* __restrict__ h,
                             const float* __restrict__ Wo,
                             const float* __restrict__ bo,
                             float* __restrict__ out)
{
    __shared__ float sW[H_N * 3];
    __shared__ float sb[3];
    for (int i = threadIdx.x; i < H_N * 3; i += blockDim.x) sW[i] = Wo[i];
    if (threadIdx.x < 3) sb[threadIdx.x] = bo[threadIdx.x];
    __syncthreads();

    int idx = blockIdx.x * blockDim.x + threadIdx.x;
    if (idx >= V_N * 3) return;
    int v = idx / 3, c = idx % 3;
    const __half2* ph = (const __half2*)(h + (size_t)v * H_N);
    float s = sb[c];
#pragma unroll 4
    for (int k = 0; k < H_N / 2; k++) {
        float2 a = __half22float2(ph[k]);
        s = fmaf(a.x, sW[(2 * k) * 3 + c], s);
        s = fmaf(a.y, sW[(2 * k + 1) * 3 + c], s);
    }
    out[idx] = s;
}

// ---------------------------------------------------------------------------
__global__ void tail_kernel(const float* __restrict__ z2,
                            const float* __restrict__ A3,
                            const float* __restrict__ a3,
                            const float* __restrict__ A4,
                            const float* __restrict__ a4,
                            float* __restrict__ conf)
{
    __shared__ float sA3[64 * 32];
    __shared__ float sa3[32];
    __shared__ float sA4[32];
    for (int i = threadIdx.x; i < 64 * 32; i += blockDim.x) sA3[i] = A3[i];
    if (threadIdx.x < 32) {
        sa3[threadIdx.x] = a3[threadIdx.x];
        sA4[threadIdx.x] = A4[threadIdx.x];
    }
    __syncthreads();

    float b4 = a4[0];
    for (int v = blockIdx.x * blockDim.x + threadIdx.x; v < V_N;
         v += gridDim.x * blockDim.x) {
        float x[64];
        const float* zr = z2 + (size_t)v * 64;
#pragma unroll
        for (int k = 0; k < 64; k++) x[k] = zr[k];
        float acc = b4;
#pragma unroll 4
        for (int m = 0; m < 32; m++) {
            float s = sa3[m];
#pragma unroll
            for (int k = 0; k < 64; k++) s = fmaf(x[k], sA3[k * 32 + m], s);
            acc = fmaf(fmaxf(s, 0.f), sA4[m], acc);
        }
        conf[v] = 1.f / (1.f + expf(-acc));
    }
}

// ---------------------------------------------------------------------------
// Launcher
// ---------------------------------------------------------------------------
extern "C" void kernel_launch(void* const* d_in, const int* in_sizes, int n_in,
                              void* d_out, int out_size)
{
    (void)in_sizes; (void)n_in; (void)out_size;
    const float* X     = (const float*)d_in[0];
    const float* verts = (const float*)d_in[1];
    const int*   edges = (const int*)  d_in[2];
    const float* Wb    = (const float*)d_in[3];
    const float* bb    = (const float*)d_in[4];
    const float* W0_0  = (const float*)d_in[5];
    const float* b0_0  = (const float*)d_in[6];
    const float* W1_0  = (const float*)d_in[7];
    const float* b1_0  = (const float*)d_in[8];
    const float* gW0   = (const float*)d_in[9];
    const float* gb0   = (const float*)d_in[10];
    const float* gW1   = (const float*)d_in[11];
    const float* gb1   = (const float*)d_in[12];
    const float* Wo    = (const float*)d_in[13];
    const float* bo    = (const float*)d_in[14];
    const float* A1    = (const float*)d_in[15];
    const float* a1    = (const float*)d_in[16];
    const float* A2    = (const float*)d_in[17];
    const float* a2    = (const float*)d_in[18];
    const float* A3    = (const float*)d_in[19];
    const float* a3    = (const float*)d_in[20];
    const float* A4    = (const float*)d_in[21];
    const float* a4    = (const float*)d_in[22];
    float* out = (float*)d_out;

    __half *pxf, *ph0, *pa, *pb, *pz1;
    float *pt0, *pt1, *pz2;
    cudaGetSymbolAddress((void**)&pxf, g_xf);
    cudaGetSymbolAddress((void**)&ph0, g_h0);
    cudaGetSymbolAddress((void**)&pa,  g_a);
    cudaGetSymbolAddress((void**)&pb,  g_b);
    cudaGetSymbolAddress((void**)&pz1, g_z1);
    cudaGetSymbolAddress((void**)&pt0, g_t0);
    cudaGetSymbolAddress((void**)&pt1, g_t1);
    cudaGetSymbolAddress((void**)&pz2, g_z2);

    __half *pwb, *pw0h, *pw0l, *pw1h, *pw1l;
    __half *pg0h, *pg0l, *pg1h, *pg1l, *pa1h, *pa1l, *pa2h, *pa2l;
    cudaGetSymbolAddress((void**)&pwb,  wb_f);
    cudaGetSymbolAddress((void**)&pw0h, w0_h);  cudaGetSymbolAddress((void**)&pw0l, w0_l);
    cudaGetSymbolAddress((void**)&pw1h, w1_h);  cudaGetSymbolAddress((void**)&pw1l, w1_l);
    cudaGetSymbolAddress((void**)&pg0h, gw0_h); cudaGetSymbolAddress((void**)&pg0l, gw0_l);
    cudaGetSymbolAddress((void**)&pg1h, gw1_h); cudaGetSymbolAddress((void**)&pg1l, gw1_l);
    cudaGetSymbolAddress((void**)&pa1h, a1_h);  cudaGetSymbolAddress((void**)&pa1l, a1_l);
    cudaGetSymbolAddress((void**)&pa2h, a2_h);  cudaGetSymbolAddress((void**)&pa2l, a2_l);

    const int SMEM1 = 32768;   // single-pass
    const int SMEM2 = 49152;   // weight-split 2-pass
    cudaFuncSetAttribute((const void*)gemm_tpl<3, false, false>, cudaFuncAttributeMaxDynamicSharedMemorySize, SMEM1);
    cudaFuncSetAttribute((const void*)gemm_tpl<0, true,  true >, cudaFuncAttributeMaxDynamicSharedMemorySize, SMEM2);
    cudaFuncSetAttribute((const void*)gemm_tpl<3, false, true >, cudaFuncAttributeMaxDynamicSharedMemorySize, SMEM2);
    cudaFuncSetAttribute((const void*)gemm_tpl<1, false, true >, cudaFuncAttributeMaxDynamicSharedMemorySize, SMEM2);

    const int MT = (V_N + 127) / 128;   // 161
    const dim3 blk(256);
    const dim3 g2(2, MT);
    const dim3 g1(1, MT);
    const dim3 g4(4, MT);
    const int GATHER_GRID = (V_N + 3) / 4;

    // ---- CSR build ----
    csr_zero_kernel<<<(V_N + 255) / 256, 256>>>();
    csr_count_kernel<<<(E_N + 255) / 256, 256>>>(edges);
    csr_scan_kernel<<<1, 1024>>>();
    csr_fill_kernel<<<(E_N + 255) / 256, 256>>>(edges);

    // ---- weight prep ----
    {
        int n;
        n = 256 * 3840;
        prep_w_f16_kernel<<<(n + 255) / 256, 256>>>(Wb, pwb, 3840, 256);
        n = 256 * 288;
        prep_w_hl_kernel<<<dim3((n + 255) / 256, 1), 256>>>(W0_0, pw0h, pw0l, 259, 256, 288, 0, 0);
        prep_w_hl_kernel<<<dim3((n + 255) / 256, 1), 256>>>(W1_0, pw1h, pw1l, 259, 256, 288, 0, 0);
        n = 256 * 256;
        prep_w_hl_kernel<<<dim3((n + 255) / 256, 9), 256>>>(gW0, pg0h, pg0l, 256, 256, 256, 65536, 65536);
        prep_w_hl_kernel<<<dim3((n + 255) / 256, 9), 256>>>(gW1, pg1h, pg1l, 256, 256, 256, 65536, 65536);
        prep_w_hl_kernel<<<dim3((n + 255) / 256, 1), 256>>>(A1, pa1h, pa1l, 256, 256, 256, 0, 0);
        n = 64 * 256;
        prep_w_hl_kernel<<<dim3((n + 255) / 256, 1), 256>>>(A2, pa2h, pa2l, 256, 64, 256, 0, 0);
    }

    // ---- X -> fp16 ----
    {
        int n4 = (V_N * F_N) / 4;
        conv_f16_kernel<<<(n4 + 255) / 256, 256>>>(X, pxf, n4);
    }

    // 1) backbone (single-pass fp16): h0 = relu(X @ Wb + bb), fp16 out
    gemm_tpl<3, false, false><<<g2, blk, SMEM1>>>(
        pxf,
        pwb, nullptr, bb, nullptr, ph0,
        nullptr, nullptr, nullptr, nullptr, nullptr,
        V_N, 256, 3840, 3840, 288);

    // 2) concat verts (fp16)
    concat_verts_kernel<<<(V_N * 32 + 255) / 256, 256>>>(verts);

    // 3) layer 0 fused pair (weight-split 2-pass, K_pad=288)
    gemm_tpl<0, true, true><<<g4, blk, SMEM2>>>(
        ph0,
        pw0h, pw0l, b0_0, pt0, nullptr,
        pw1h, pw1l, b1_0, pt1, nullptr,
        V_N, 256, 288, 288, 256);
    gather_f16_kernel<<<GATHER_GRID, 256>>>(pt0, pt1, pa);

    // 4) layers 1..9, fused pairs (weight-split 2-pass)
    __half *cur = pa, *nxt = pb;
    for (int k = 0; k < 9; k++) {
        const __half* W0h = pg0h + (size_t)k * 65536;
        const __half* W0l = pg0l + (size_t)k * 65536;
        const __half* W1h = pg1h + (size_t)k * 65536;
        const __half* W1l = pg1l + (size_t)k * 65536;
        const float* B0 = gb0 + (size_t)k * H_N;
        const float* B1 = gb1 + (size_t)k * H_N;
        gemm_tpl<0, true, true><<<g4, blk, SMEM2>>>(
            cur,
            W0h, W0l, B0, pt0, nullptr,
            W1h, W1l, B1, pt1, nullptr,
            V_N, 256, 256, 256, 256);
        gather_f16_kernel<<<GATHER_GRID, 256>>>(pt0, pt1, nxt);
        __half* t = cur; cur = nxt; nxt = t;
    }
    // final relu(h) fp16 in cur

    // 5) delta_v -> out[0 : V*3]
    delta_kernel<<<(V_N * 3 + 255) / 256, 256>>>(cur, Wo, bo, out);

    // 6) z1 = relu(h @ A1 + a1), weight-split 2-pass, fp16 out
    gemm_tpl<3, false, true><<<g2, blk, SMEM2>>>(
        cur,
        pa1h, pa1l, a1, nullptr, pz1,
        nullptr, nullptr, nullptr, nullptr, nullptr,
        V_N, 256, 256, 256, 256);

    // 7) z2 = relu(z1 @ A2 + a2), weight-split 2-pass, fp32 out
    gemm_tpl<1, false, true><<<g1, blk, SMEM2>>>(
        pz1,
        pa2h, pa2l, a2, pz2, nullptr,
        nullptr, nullptr, nullptr, nullptr, nullptr,
        V_N, 64, 256, 256, 64);

    // 8) conf -> out[V*3 : V*4]
    tail_kernel<<<128, 256>>>(pz2, A3, a3, A4, a4, out + (size_t)V_N * 3);
}

// round 11
// speedup vs baseline: 5.9417x; 1.0217x over previous
#include <cuda_runtime.h>
#include <cuda_fp16.h>
#include <math.h>
#include <stdint.h>

#define V_N 20496
#define E_N 61440
#define F_N 3840
#define H_N 256

// ---------------------------------------------------------------------------
// Scratch (static device globals — no allocation allowed)
// ---------------------------------------------------------------------------
__device__ __align__(16) __half g_xf [(size_t)V_N * F_N];   // fp16 X
__device__ __align__(16) __half g_h0 [(size_t)V_N * 288];   // fp16 concat(h_img, verts)
__device__ __align__(16) __half g_a  [(size_t)V_N * H_N];   // fp16 act ping
__device__ __align__(16) __half g_b  [(size_t)V_N * H_N];   // fp16 act pong
__device__ __align__(16) __half g_z1 [(size_t)V_N * H_N];
__device__ __align__(16) float  g_t0 [(size_t)V_N * H_N];
__device__ __align__(16) float  g_t1 [(size_t)V_N * H_N];
__device__ __align__(16) float  g_z2 [(size_t)V_N * 64];

// CSR adjacency
__device__ int g_deg[V_N];
__device__ int g_cur[V_N];
__device__ int g_off[V_N + 1];
__device__ int g_adj[2 * E_N];

// weight scratch, transposed [N, K_pad]
__device__ __align__(16) __half wb_f [256 * 3840];            // backbone single fp16
__device__ __align__(16) __half w0_h [256 * 288];
__device__ __align__(16) __half w0_l [256 * 288];
__device__ __align__(16) __half w1_h [256 * 288];
__device__ __align__(16) __half w1_l [256 * 288];
__device__ __align__(16) __half gw0_h[9 * 256 * 256];
__device__ __align__(16) __half gw0_l[9 * 256 * 256];
__device__ __align__(16) __half gw1_h[9 * 256 * 256];
__device__ __align__(16) __half gw1_l[9 * 256 * 256];
__device__ __align__(16) __half a1_h [256 * 256];
__device__ __align__(16) __half a1_l [256 * 256];
__device__ __align__(16) __half a2_h [64 * 256];
__device__ __align__(16) __half a2_l [64 * 256];

// ---------------------------------------------------------------------------
// PTX helpers
// ---------------------------------------------------------------------------
__device__ __forceinline__ void ldsm_x4(uint32_t* r, uint32_t addr) {
    asm volatile("ldmatrix.sync.aligned.m8n8.x4.shared.b16 {%0,%1,%2,%3}, [%4];"
        : "=r"(r[0]), "=r"(r[1]), "=r"(r[2]), "=r"(r[3]) : "r"(addr));
}
__device__ __forceinline__ void mma16816h(float* d, const uint32_t* a, const uint32_t* b) {
    asm volatile(
        "mma.sync.aligned.m16n8k16.row.col.f32.f16.f16.f32 "
        "{%0,%1,%2,%3}, {%4,%5,%6,%7}, {%8,%9}, {%0,%1,%2,%3};"
        : "+f"(d[0]), "+f"(d[1]), "+f"(d[2]), "+f"(d[3])
        : "r"(a[0]), "r"(a[1]), "r"(a[2]), "r"(a[3]), "r"(b[0]), "r"(b[1]));
}
__device__ __forceinline__ void cp_async16(uint32_t dst, const void* src, bool pred) {
    int sz = pred ? 16 : 0;
    asm volatile("cp.async.cg.shared.global [%0], [%1], 16, %2;"
                 :: "r"(dst), "l"(src), "r"(sz));
}
#define CP_COMMIT() asm volatile("cp.async.commit_group;")
#define CP_WAIT(n)  asm volatile("cp.async.wait_group %0;" :: "n"(n))

__device__ __forceinline__ uint32_t pack2h(float f0, float f1) {
    __half2 p = __floats2half2_rn(f0, f1);
    return *(uint32_t*)&p;
}

// ---------------------------------------------------------------------------
// Persistent fp16 mma.sync GEMM.
// Tiles are 128x128; ntiles = Mtiles * nx, tile t -> bm = t/nx, r = t%nx.
// PAIR: nx=4, two GEMMs sharing A (sel = r>>1, bn = (r&1)*128).
// else: bn = r*128.
// WSPLIT: B fp16 hi/lo, acc += A*Bh + A*Bl.
// OUT_MODE: 0 = fp32 out, 1 = fp32 + relu, 3 = fp16 + relu.
// SMEM stage: A(8K) Bh(8K) [Bl(8K)]; 64B rows, XOR swizzle.
// ---------------------------------------------------------------------------
template<int OUT_MODE, bool PAIR, bool WSPLIT>
__global__ void __launch_bounds__(256, 2)
gemm_tpl(const __half* __restrict__ A,
         const __half* __restrict__ B0h, const __half* __restrict__ B0l,
         const float* __restrict__ bias0, float* __restrict__ Cf0, __half* __restrict__ Ch0,
         const __half* __restrict__ B1h, const __half* __restrict__ B1l,
         const float* __restrict__ bias1, float* __restrict__ Cf1, __half* __restrict__ Ch1,
         int M, int N, int K_pad, int lda, int ldc, int ntiles, int nx)
{
    constexpr uint32_t BH_OFF = 8192;
    constexpr uint32_t BL_OFF = 16384;
    constexpr uint32_t STAGE  = WSPLIT ? 24576 : 16384;

    extern __shared__ char smp[];
    const uint32_t sbase = (uint32_t)__cvta_generic_to_shared(smp);

    const int tid  = threadIdx.x;
    const int lane = tid & 31;
    const int w    = tid >> 5;
    const int mw   = w & 3;
    const int nw   = w >> 2;
    const int nc   = K_pad >> 5;

#define LOAD_CHUNK_T(cidx, stg_u32, bm_, bn_, Bh_)                                  \
    {                                                                               \
        const int col0 = (cidx) << 5;                                               \
        _Pragma("unroll")                                                           \
        for (int g = 0; g < 2; g++) {                                               \
            int id = tid + g * 256;                                                 \
            int br = id >> 2, bc = id & 3;                                          \
            uint32_t dst = (stg_u32) + (uint32_t)(br * 64 + ((bc ^ ((br >> 1) & 3)) << 4)); \
            bool pa = ((bm_) + br) < M;                                             \
            size_t ga = (size_t)((bm_) + br) * lda + col0 + bc * 8;                 \
            cp_async16(dst, A + ga, pa);                                            \
            bool pb = ((bn_) + br) < N;                                             \
            size_t gb = (size_t)((bn_) + br) * K_pad + col0 + bc * 8;               \
            cp_async16(dst + BH_OFF, (Bh_) + gb, pb);                               \
            if (WSPLIT) cp_async16(dst + BL_OFF, (Bh_) + ((WSPLIT) ? ((sel ? B1l : B0l) - (Bh_)) : 0) + gb, pb); \
        }                                                                           \
        CP_COMMIT();                                                                \
    }

    for (int t = blockIdx.x; t < ntiles; t += gridDim.x) {
        const int bm = (t / nx) * 128;
        const int r  = t - (t / nx) * nx;
        int sel, bn;
        if (PAIR) { sel = r >> 1; bn = (r & 1) * 128; }
        else      { sel = 0;      bn = r * 128; }

        const __half* Bh   = sel ? B1h : B0h;
        const __half* Bl   = sel ? B1l : B0l;
        const float*  bias = sel ? bias1 : bias0;
        float*        Cf   = sel ? Cf1 : Cf0;
        __half*       Ch   = sel ? Ch1 : Ch0;

        float acc[2][8][4];
#pragma unroll
        for (int a = 0; a < 2; a++)
#pragma unroll
            for (int b = 0; b < 8; b++)
#pragma unroll
                for (int c = 0; c < 4; c++) acc[a][b][c] = 0.f;

        // prologue chunk 0
        {
            const int col0 = 0;
#pragma unroll
            for (int g = 0; g < 2; g++) {
                int id = tid + g * 256;
                int br = id >> 2, bc = id & 3;
                uint32_t dst = sbase + (uint32_t)(br * 64 + ((bc ^ ((br >> 1) & 3)) << 4));
                bool pa = (bm + br) < M;
                size_t ga = (size_t)(bm + br) * lda + col0 + bc * 8;
                cp_async16(dst, A + ga, pa);
                bool pb = (bn + br) < N;
                size_t gb = (size_t)(bn + br) * K_pad + col0 + bc * 8;
                cp_async16(dst + BH_OFF, Bh + gb, pb);
                if (WSPLIT) cp_async16(dst + BL_OFF, Bl + gb, pb);
            }
            CP_COMMIT();
        }

        for (int c = 0; c < nc; c++) {
            const int s = c & 1;
            const uint32_t stg = sbase + (uint32_t)(s * STAGE);

            if (c + 1 < nc) {
                const int col0 = (c + 1) << 5;
                const uint32_t ostg = sbase + (uint32_t)((s ^ 1) * STAGE);
#pragma unroll
                for (int g = 0; g < 2; g++) {
                    int id = tid + g * 256;
                    int br = id >> 2, bc = id & 3;
                    uint32_t dst = ostg + (uint32_t)(br * 64 + ((bc ^ ((br >> 1) & 3)) << 4));
                    bool pa = (bm + br) < M;
                    size_t ga = (size_t)(bm + br) * lda + col0 + bc * 8;
                    cp_async16(dst, A + ga, pa);
                    bool pb = (bn + br) < N;
                    size_t gb = (size_t)(bn + br) * K_pad + col0 + bc * 8;
                    cp_async16(dst + BH_OFF, Bh + gb, pb);
                    if (WSPLIT) cp_async16(dst + BL_OFF, Bl + gb, pb);
                }
                CP_COMMIT();
                CP_WAIT(1);
            } else {
                CP_WAIT(0);
            }
            __syncthreads();

#pragma unroll
            for (int kk = 0; kk < 2; kk++) {
                uint32_t ar[2][4];
#pragma unroll
                for (int mi = 0; mi < 2; mi++) {
                    int row = mw * 32 + mi * 16 + (lane & 15);
                    int ch  = 2 * kk + (lane >> 4);
                    int phys = ch ^ ((row >> 1) & 3);
                    uint32_t off = stg + (uint32_t)(row * 64 + phys * 16);
                    ldsm_x4(ar[mi], off);
                }
#pragma unroll
                for (int h2 = 0; h2 < 2; h2++) {
                    uint32_t bh[2][4], bl[2][4];
#pragma unroll
                    for (int t4 = 0; t4 < 2; t4++) {
                        int row = nw * 64 + (h2 * 2 + t4) * 16 + (lane & 7) + ((lane >> 4) << 3);
                        int ch  = 2 * kk + ((lane >> 3) & 1);
                        int phys = ch ^ ((row >> 1) & 3);
                        uint32_t off = stg + (uint32_t)(row * 64 + phys * 16);
                        ldsm_x4(bh[t4], off + BH_OFF);
                        if (WSPLIT) ldsm_x4(bl[t4], off + BL_OFF);
                    }
#pragma unroll
                    for (int mi = 0; mi < 2; mi++)
#pragma unroll
                        for (int q = 0; q < 4; q++) {
                            float* d = acc[mi][h2 * 4 + q];
                            mma16816h(d, ar[mi], &bh[q >> 1][(q & 1) * 2]);
                            if (WSPLIT) mma16816h(d, ar[mi], &bl[q >> 1][(q & 1) * 2]);
                        }
                }
            }
            __syncthreads();
        }

        // ---------------- epilogue ----------------
#pragma unroll
        for (int mi = 0; mi < 2; mi++) {
            int row0 = bm + mw * 32 + mi * 16 + (lane >> 2);
#pragma unroll
            for (int n8 = 0; n8 < 8; n8++) {
                int col = bn + nw * 64 + n8 * 8 + (lane & 3) * 2;
                if (col >= N) continue;
                float b0 = bias[col], b1 = bias[col + 1];
                float* d = acc[mi][n8];
                float v0 = d[0] + b0, v1 = d[1] + b1;
                float v2 = d[2] + b0, v3 = d[3] + b1;
                if (OUT_MODE >= 1) {
                    v0 = fmaxf(v0, 0.f); v1 = fmaxf(v1, 0.f);
                    v2 = fmaxf(v2, 0.f); v3 = fmaxf(v3, 0.f);
                }
                if (OUT_MODE == 3) {
                    if (row0 < M)     *(uint32_t*)(Ch + (size_t)row0 * ldc + col)       = pack2h(v0, v1);
                    if (row0 + 8 < M) *(uint32_t*)(Ch + (size_t)(row0 + 8) * ldc + col) = pack2h(v2, v3);
                } else {
                    if (row0 < M)     *(float2*)(Cf + (size_t)row0 * ldc + col)       = make_float2(v0, v1);
                    if (row0 + 8 < M) *(float2*)(Cf + (size_t)(row0 + 8) * ldc + col) = make_float2(v2, v3);
                }
            }
        }
    }
}

// ---------------------------------------------------------------------------
// CSR build kernels
// ---------------------------------------------------------------------------
__global__ void csr_zero_kernel()
{
    int v = blockIdx.x * blockDim.x + threadIdx.x;
    if (v < V_N) { g_deg[v] = 0; g_cur[v] = 0; }
}

__global__ void csr_count_kernel(const int* __restrict__ edges)
{
    int e = blockIdx.x * blockDim.x + threadIdx.x;
    if (e >= E_N) return;
    atomicAdd(&g_deg[edges[2 * e]], 1);
    atomicAdd(&g_deg[edges[2 * e + 1]], 1);
}

__global__ void __launch_bounds__(1024) csr_scan_kernel()
{
    __shared__ int part[1024];
    const int tid = threadIdx.x;
    const int CH = (V_N + 1023) / 1024;
    const int base = tid * CH;
    int s = 0;
#pragma unroll
    for (int q = 0; q < CH; q++) {
        int idx = base + q;
        if (idx < V_N) s += g_deg[idx];
    }
    part[tid] = s;
    __syncthreads();
    for (int o = 1; o < 1024; o <<= 1) {
        int t = (tid >= o) ? part[tid - o] : 0;
        __syncthreads();
        part[tid] += t;
        __syncthreads();
    }
    int run = part[tid] - s;
    for (int q = 0; q < CH; q++) {
        int idx = base + q;
        if (idx < V_N) {
            g_off[idx] = run;
            run += g_deg[idx];
        }
    }
    if (tid == 1023) g_off[V_N] = part[1023];
}

__global__ void csr_fill_kernel(const int* __restrict__ edges)
{
    int e = blockIdx.x * blockDim.x + threadIdx.x;
    if (e >= E_N) return;
    int i = edges[2 * e], j = edges[2 * e + 1];
    int p = g_off[i] + atomicAdd(&g_cur[i], 1);
    g_adj[p] = j;
    p = g_off[j] + atomicAdd(&g_cur[j], 1);
    g_adj[p] = i;
}

// ---------------------------------------------------------------------------
// Fused gather + relu -> fp16
// ---------------------------------------------------------------------------
__global__ void __launch_bounds__(256)
gather_f16_kernel(const float* __restrict__ self, const float* __restrict__ nbr,
                  __half* __restrict__ oh)
{
    int v = blockIdx.x * 4 + (threadIdx.x >> 6);
    if (v >= V_N) return;
    int c = (threadIdx.x & 63) << 2;

    float4 acc = *(const float4*)(self + (size_t)v * H_N + c);
    int s = g_off[v], e = g_off[v + 1];
    for (int p = s; p < e; p++) {
        int u = g_adj[p];
        float4 w = *(const float4*)(nbr + (size_t)u * H_N + c);
        acc.x += w.x; acc.y += w.y; acc.z += w.z; acc.w += w.w;
    }
    acc.x = fmaxf(acc.x, 0.f); acc.y = fmaxf(acc.y, 0.f);
    acc.z = fmaxf(acc.z, 0.f); acc.w = fmaxf(acc.w, 0.f);

    *(uint2*)(oh + (size_t)v * H_N + c) =
        make_uint2(pack2h(acc.x, acc.y), pack2h(acc.z, acc.w));
}

// ---------------------------------------------------------------------------
// Weight prep: W[Kin,N] fp32 -> Wt[N,K_pad] fp16 hi + lo (transpose), batched
// ---------------------------------------------------------------------------
__global__ void prep_w_hl_kernel(const float* __restrict__ W,
                                 __half* __restrict__ oh, __half* __restrict__ ol,
                                 int Kin, int N, int K_pad,
                                 size_t in_stride, size_t out_stride)
{
    int mat = blockIdx.y;
    const float* w = W + (size_t)mat * in_stride;
    __half* ph = oh + (size_t)mat * out_stride;
    __half* pl = ol + (size_t)mat * out_stride;
    int idx = blockIdx.x * blockDim.x + threadIdx.x;
    if (idx >= N * K_pad) return;
    int n = idx / K_pad, k = idx - n * K_pad;
    float v = (k < Kin) ? w[(size_t)k * N + n] : 0.f;
    __half h = __float2half_rn(v);
    ph[idx] = h;
    pl[idx] = __float2half_rn(v - __half2float(h));
}

// backbone: single fp16 transpose
__global__ void prep_w_f16_kernel(const float* __restrict__ W,
                                  __half* __restrict__ o, int K, int N)
{
    int idx = blockIdx.x * blockDim.x + threadIdx.x;
    if (idx >= N * K) return;
    int n = idx / K, k = idx - n * K;
    o[idx] = __float2half(W[(size_t)k * N + n]);
}

// fp32 -> fp16 convert (X)
__global__ void conv_f16_kernel(const float* __restrict__ in,
                                __half* __restrict__ o, int n4)
{
    int idx = blockIdx.x * blockDim.x + threadIdx.x;
    if (idx >= n4) return;
    float4 v = ((const float4*)in)[idx];
    ((uint2*)o)[idx] = make_uint2(pack2h(v.x, v.y), pack2h(v.z, v.w));
}

// ---------------------------------------------------------------------------
__global__ void concat_verts_kernel(const float* __restrict__ verts)
{
    int idx = blockIdx.x * blockDim.x + threadIdx.x;  // V * 32
    if (idx >= V_N * 32) return;
    int v = idx >> 5, c = idx & 31;
    float x = (c < 3) ? verts[v * 3 + c] : 0.f;
    g_h0[(size_t)v * 288 + 256 + c] = __float2half(x);
}

// ---------------------------------------------------------------------------
// delta_v = h @ Wo + bo   (h fp16, relu already applied)
// ---------------------------------------------------------------------------
__global__ void delta_kernel(const __half* __restrict__ h,
                             const float* __restrict__ Wo,
                             const float* __restrict__ bo,
                             float* __restrict__ out)
{
    __shared__ float sW[H_N * 3];
    __shared__ float sb[3];
    for (int i = threadIdx.x; i < H_N * 3; i += blockDim.x) sW[i] = Wo[i];
    if (threadIdx.x < 3) sb[threadIdx.x] = bo[threadIdx.x];
    __syncthreads();

    int idx = blockIdx.x * blockDim.x + threadIdx.x;
    if (idx >= V_N * 3) return;
    int v = idx / 3, c = idx % 3;
    const __half2* ph = (const __half2*)(h + (size_t)v * H_N);
    float s = sb[c];
#pragma unroll 4
    for (int k = 0; k < H_N / 2; k++) {
        float2 a = __half22float2(ph[k]);
        s = fmaf(a.x, sW[(2 * k) * 3 + c], s);
        s = fmaf(a.y, sW[(2 * k + 1) * 3 + c], s);
    }
    out[idx] = s;
}

// ---------------------------------------------------------------------------
__global__ void tail_kernel(const float* __restrict__ z2,
                            const float* __restrict__ A3,
                            const float* __restrict__ a3,
                            const float* __restrict__ A4,
                            const float* __restrict__ a4,
                            float* __restrict__ conf)
{
    __shared__ float sA3[64 * 32];
    __shared__ float sa3[32];
    __shared__ float sA4[32];
    for (int i = threadIdx.x; i < 64 * 32; i += blockDim.x) sA3[i] = A3[i];
    if (threadIdx.x < 32) {
        sa3[threadIdx.x] = a3[threadIdx.x];
        sA4[threadIdx.x] = A4[threadIdx.x];
    }
    __syncthreads();

    float b4 = a4[0];
    for (int v = blockIdx.x * blockDim.x + threadIdx.x; v < V_N;
         v += gridDim.x * blockDim.x) {
        float x[64];
        const float* zr = z2 + (size_t)v * 64;
#pragma unroll
        for (int k = 0; k < 64; k++) x[k] = zr[k];
        float acc = b4;
#pragma unroll 4
        for (int m = 0; m < 32; m++) {
            float s = sa3[m];
#pragma unroll
            for (int k = 0; k < 64; k++) s = fmaf(x[k], sA3[k * 32 + m], s);
            acc = fmaf(fmaxf(s, 0.f), sA4[m], acc);
        }
        conf[v] = 1.f / (1.f + expf(-acc));
    }
}

// ---------------------------------------------------------------------------
// Launcher
// ---------------------------------------------------------------------------
extern "C" void kernel_launch(void* const* d_in, const int* in_sizes, int n_in,
                              void* d_out, int out_size)
{
    (void)in_sizes; (void)n_in; (void)out_size;
    const float* X     = (const float*)d_in[0];
    const float* verts = (const float*)d_in[1];
    const int*   edges = (const int*)  d_in[2];
    const float* Wb    = (const float*)d_in[3];
    const float* bb    = (const float*)d_in[4];
    const float* W0_0  = (const float*)d_in[5];
    const float* b0_0  = (const float*)d_in[6];
    const float* W1_0  = (const float*)d_in[7];
    const float* b1_0  = (const float*)d_in[8];
    const float* gW0   = (const float*)d_in[9];
    const float* gb0   = (const float*)d_in[10];
    const float* gW1   = (const float*)d_in[11];
    const float* gb1   = (const float*)d_in[12];
    const float* Wo    = (const float*)d_in[13];
    const float* bo    = (const float*)d_in[14];
    const float* A1    = (const float*)d_in[15];
    const float* a1    = (const float*)d_in[16];
    const float* A2    = (const float*)d_in[17];
    const float* a2    = (const float*)d_in[18];
    const float* A3    = (const float*)d_in[19];
    const float* a3    = (const float*)d_in[20];
    const float* A4    = (const float*)d_in[21];
    const float* a4    = (const float*)d_in[22];
    float* out = (float*)d_out;

    __half *pxf, *ph0, *pa, *pb, *pz1;
    float *pt0, *pt1, *pz2;
    cudaGetSymbolAddress((void**)&pxf, g_xf);
    cudaGetSymbolAddress((void**)&ph0, g_h0);
    cudaGetSymbolAddress((void**)&pa,  g_a);
    cudaGetSymbolAddress((void**)&pb,  g_b);
    cudaGetSymbolAddress((void**)&pz1, g_z1);
    cudaGetSymbolAddress((void**)&pt0, g_t0);
    cudaGetSymbolAddress((void**)&pt1, g_t1);
    cudaGetSymbolAddress((void**)&pz2, g_z2);

    __half *pwb, *pw0h, *pw0l, *pw1h, *pw1l;
    __half *pg0h, *pg0l, *pg1h, *pg1l, *pa1h, *pa1l, *pa2h, *pa2l;
    cudaGetSymbolAddress((void**)&pwb,  wb_f);
    cudaGetSymbolAddress((void**)&pw0h, w0_h);  cudaGetSymbolAddress((void**)&pw0l, w0_l);
    cudaGetSymbolAddress((void**)&pw1h, w1_h);  cudaGetSymbolAddress((void**)&pw1l, w1_l);
    cudaGetSymbolAddress((void**)&pg0h, gw0_h); cudaGetSymbolAddress((void**)&pg0l, gw0_l);
    cudaGetSymbolAddress((void**)&pg1h, gw1_h); cudaGetSymbolAddress((void**)&pg1l, gw1_l);
    cudaGetSymbolAddress((void**)&pa1h, a1_h);  cudaGetSymbolAddress((void**)&pa1l, a1_l);
    cudaGetSymbolAddress((void**)&pa2h, a2_h);  cudaGetSymbolAddress((void**)&pa2l, a2_l);

    const int SMEM1 = 32768;   // single-pass
    const int SMEM2 = 49152;   // weight-split 2-pass
    cudaFuncSetAttribute((const void*)gemm_tpl<3, false, false>, cudaFuncAttributeMaxDynamicSharedMemorySize, SMEM1);
    cudaFuncSetAttribute((const void*)gemm_tpl<0, true,  true >, cudaFuncAttributeMaxDynamicSharedMemorySize, SMEM2);
    cudaFuncSetAttribute((const void*)gemm_tpl<3, false, true >, cudaFuncAttributeMaxDynamicSharedMemorySize, SMEM2);
    cudaFuncSetAttribute((const void*)gemm_tpl<1, false, true >, cudaFuncAttributeMaxDynamicSharedMemorySize, SMEM2);

    const int MT = (V_N + 127) / 128;   // 161
    const int SLOTS = 296;              // 148 SMs x 2 CTAs
    const dim3 blk(256);
    const int GATHER_GRID = (V_N + 3) / 4;

    // ---- CSR build ----
    csr_zero_kernel<<<(V_N + 255) / 256, 256>>>();
    csr_count_kernel<<<(E_N + 255) / 256, 256>>>(edges);
    csr_scan_kernel<<<1, 1024>>>();
    csr_fill_kernel<<<(E_N + 255) / 256, 256>>>(edges);

    // ---- weight prep ----
    {
        int n;
        n = 256 * 3840;
        prep_w_f16_kernel<<<(n + 255) / 256, 256>>>(Wb, pwb, 3840, 256);
        n = 256 * 288;
        prep_w_hl_kernel<<<dim3((n + 255) / 256, 1), 256>>>(W0_0, pw0h, pw0l, 259, 256, 288, 0, 0);
        prep_w_hl_kernel<<<dim3((n + 255) / 256, 1), 256>>>(W1_0, pw1h, pw1l, 259, 256, 288, 0, 0);
        n = 256 * 256;
        prep_w_hl_kernel<<<dim3((n + 255) / 256, 9), 256>>>(gW0, pg0h, pg0l, 256, 256, 256, 65536, 65536);
        prep_w_hl_kernel<<<dim3((n + 255) / 256, 9), 256>>>(gW1, pg1h, pg1l, 256, 256, 256, 65536, 65536);
        prep_w_hl_kernel<<<dim3((n + 255) / 256, 1), 256>>>(A1, pa1h, pa1l, 256, 256, 256, 0, 0);
        n = 64 * 256;
        prep_w_hl_kernel<<<dim3((n + 255) / 256, 1), 256>>>(A2, pa2h, pa2l, 256, 64, 256, 0, 0);
    }

    // ---- X -> fp16 ----
    {
        int n4 = (V_N * F_N) / 4;
        conv_f16_kernel<<<(n4 + 255) / 256, 256>>>(X, pxf, n4);
    }

    // 1) backbone (persistent, single-pass fp16): h0 = relu(X @ Wb + bb)
    {
        int ntiles = MT * 2;
        int grid = ntiles < SLOTS ? ntiles : SLOTS;
        gemm_tpl<3, false, false><<<grid, blk, SMEM1>>>(
            pxf,
            pwb, nullptr, bb, nullptr, ph0,
            nullptr, nullptr, nullptr, nullptr, nullptr,
            V_N, 256, 3840, 3840, 288, ntiles, 2);
    }

    // 2) concat verts (fp16)
    concat_verts_kernel<<<(V_N * 32 + 255) / 256, 256>>>(verts);

    // 3) layer 0 fused pair (persistent, weight-split, K_pad=288)
    {
        int ntiles = MT * 4;
        int grid = ntiles < SLOTS ? ntiles : SLOTS;
        gemm_tpl<0, true, true><<<grid, blk, SMEM2>>>(
            ph0,
            pw0h, pw0l, b0_0, pt0, nullptr,
            pw1h, pw1l, b1_0, pt1, nullptr,
            V_N, 256, 288, 288, 256, ntiles, 4);
    }
    gather_f16_kernel<<<GATHER_GRID, 256>>>(pt0, pt1, pa);

    // 4) layers 1..9, persistent fused pairs
    __half *cur = pa, *nxt = pb;
    {
        int ntiles = MT * 4;
        int grid = ntiles < SLOTS ? ntiles : SLOTS;
        for (int k = 0; k < 9; k++) {
            const __half* W0h = pg0h + (size_t)k * 65536;
            const __half* W0l = pg0l + (size_t)k * 65536;
            const __half* W1h = pg1h + (size_t)k * 65536;
            const __half* W1l = pg1l + (size_t)k * 65536;
            const float* B0 = gb0 + (size_t)k * H_N;
            const float* B1 = gb1 + (size_t)k * H_N;
            gemm_tpl<0, true, true><<<grid, blk, SMEM2>>>(
                cur,
                W0h, W0l, B0, pt0, nullptr,
                W1h, W1l, B1, pt1, nullptr,
                V_N, 256, 256, 256, 256, ntiles, 4);
            gather_f16_kernel<<<GATHER_GRID, 256>>>(pt0, pt1, nxt);
            __half* t = cur; cur = nxt; nxt = t;
        }
    }
    // final relu(h) fp16 in cur

    // 5) delta_v -> out[0 : V*3]
    delta_kernel<<<(V_N * 3 + 255) / 256, 256>>>(cur, Wo, bo, out);

    // 6) z1 = relu(h @ A1 + a1), persistent weight-split, fp16 out
    {
        int ntiles = MT * 2;
        int grid = ntiles < SLOTS ? ntiles : SLOTS;
        gemm_tpl<3, false, true><<<grid, blk, SMEM2>>>(
            cur,
            pa1h, pa1l, a1, nullptr, pz1,
            nullptr, nullptr, nullptr, nullptr, nullptr,
            V_N, 256, 256, 256, 256, ntiles, 2);
    }

    // 7) z2 = relu(z1 @ A2 + a2), persistent weight-split, fp32 out
    {
        int ntiles = MT;
        int grid = ntiles < SLOTS ? ntiles : SLOTS;
        gemm_tpl<1, false, true><<<grid, blk, SMEM2>>>(
            pz1,
            pa2h, pa2l, a2, pz2, nullptr,
            nullptr, nullptr, nullptr, nullptr, nullptr,
            V_N, 64, 256, 256, 64, ntiles, 1);
    }

    // 8) conf -> out[V*3 : V*4]
    tail_kernel<<<128, 256>>>(pz2, A3, a3, A4, a4, out + (size_t)V_N * 3);
}

// round 12
// speedup vs baseline: 6.1966x; 1.0429x over previous
#include <cuda_runtime.h>
#include <cuda_fp16.h>
#include <math.h>
#include <stdint.h>

#define V_N 20496
#define E_N 61440
#define F_N 3840
#define H_N 256

// ---------------------------------------------------------------------------
// Scratch (static device globals — no allocation allowed)
// ---------------------------------------------------------------------------
__device__ __align__(16) __half g_h0 [(size_t)V_N * 288];   // fp16 concat(h_img, verts)
__device__ __align__(16) __half g_a  [(size_t)V_N * H_N];   // fp16 act ping
__device__ __align__(16) __half g_b  [(size_t)V_N * H_N];   // fp16 act pong
__device__ __align__(16) __half g_z1 [(size_t)V_N * H_N];
__device__ __align__(16) float  g_t0 [(size_t)V_N * H_N];
__device__ __align__(16) float  g_t1 [(size_t)V_N * H_N];
__device__ __align__(16) float  g_z2 [(size_t)V_N * 64];

// CSR adjacency
__device__ int g_deg[V_N];
__device__ int g_cur[V_N];
__device__ int g_off[V_N + 1];
__device__ int g_adj[2 * E_N];

// weight scratch, transposed [N, K_pad]
__device__ __align__(16) __half wb_f [256 * 3840];            // backbone single fp16
__device__ __align__(16) __half w0_h [256 * 288];
__device__ __align__(16) __half w0_l [256 * 288];
__device__ __align__(16) __half w1_h [256 * 288];
__device__ __align__(16) __half w1_l [256 * 288];
__device__ __align__(16) __half gw0_h[9 * 256 * 256];
__device__ __align__(16) __half gw0_l[9 * 256 * 256];
__device__ __align__(16) __half gw1_h[9 * 256 * 256];
__device__ __align__(16) __half gw1_l[9 * 256 * 256];
__device__ __align__(16) __half a1_h [256 * 256];
__device__ __align__(16) __half a1_l [256 * 256];
__device__ __align__(16) __half a2_h [64 * 256];
__device__ __align__(16) __half a2_l [64 * 256];

// ---------------------------------------------------------------------------
// PTX helpers
// ---------------------------------------------------------------------------
__device__ __forceinline__ void ldsm_x4(uint32_t* r, uint32_t addr) {
    asm volatile("ldmatrix.sync.aligned.m8n8.x4.shared.b16 {%0,%1,%2,%3}, [%4];"
        : "=r"(r[0]), "=r"(r[1]), "=r"(r[2]), "=r"(r[3]) : "r"(addr));
}
__device__ __forceinline__ void mma16816h(float* d, const uint32_t* a, const uint32_t* b) {
    asm volatile(
        "mma.sync.aligned.m16n8k16.row.col.f32.f16.f16.f32 "
        "{%0,%1,%2,%3}, {%4,%5,%6,%7}, {%8,%9}, {%0,%1,%2,%3};"
        : "+f"(d[0]), "+f"(d[1]), "+f"(d[2]), "+f"(d[3])
        : "r"(a[0]), "r"(a[1]), "r"(a[2]), "r"(a[3]), "r"(b[0]), "r"(b[1]));
}
__device__ __forceinline__ void cp_async16(uint32_t dst, const void* src, bool pred) {
    int sz = pred ? 16 : 0;
    asm volatile("cp.async.cg.shared.global [%0], [%1], 16, %2;"
                 :: "r"(dst), "l"(src), "r"(sz));
}
#define CP_COMMIT() asm volatile("cp.async.commit_group;")
#define CP_WAIT(n)  asm volatile("cp.async.wait_group %0;" :: "n"(n))

__device__ __forceinline__ uint32_t pack2h(float f0, float f1) {
    __half2 p = __floats2half2_rn(f0, f1);
    return *(uint32_t*)&p;
}

// ---------------------------------------------------------------------------
// Persistent fp16 mma.sync GEMM (graph layers / z1 / z2).
// PAIR: nx=4, two GEMMs sharing A; WSPLIT: B fp16 hi/lo 2-pass.
// OUT_MODE: 0 = fp32, 1 = fp32+relu, 3 = fp16+relu.
// ---------------------------------------------------------------------------
template<int OUT_MODE, bool PAIR, bool WSPLIT>
__global__ void __launch_bounds__(256, 2)
gemm_tpl(const __half* __restrict__ A,
         const __half* __restrict__ B0h, const __half* __restrict__ B0l,
         const float* __restrict__ bias0, float* __restrict__ Cf0, __half* __restrict__ Ch0,
         const __half* __restrict__ B1h, const __half* __restrict__ B1l,
         const float* __restrict__ bias1, float* __restrict__ Cf1, __half* __restrict__ Ch1,
         int M, int N, int K_pad, int lda, int ldc, int ntiles, int nx)
{
    constexpr uint32_t BH_OFF = 8192;
    constexpr uint32_t BL_OFF = 16384;
    constexpr uint32_t STAGE  = WSPLIT ? 24576 : 16384;

    extern __shared__ char smp[];
    const uint32_t sbase = (uint32_t)__cvta_generic_to_shared(smp);

    const int tid  = threadIdx.x;
    const int lane = tid & 31;
    const int w    = tid >> 5;
    const int mw   = w & 3;
    const int nw   = w >> 2;
    const int nc   = K_pad >> 5;

    for (int t = blockIdx.x; t < ntiles; t += gridDim.x) {
        const int bm = (t / nx) * 128;
        const int r  = t - (t / nx) * nx;
        int sel, bn;
        if (PAIR) { sel = r >> 1; bn = (r & 1) * 128; }
        else      { sel = 0;      bn = r * 128; }

        const __half* Bh   = sel ? B1h : B0h;
        const __half* Bl   = sel ? B1l : B0l;
        const float*  bias = sel ? bias1 : bias0;
        float*        Cf   = sel ? Cf1 : Cf0;
        __half*       Ch   = sel ? Ch1 : Ch0;

        float acc[2][8][4];
#pragma unroll
        for (int a = 0; a < 2; a++)
#pragma unroll
            for (int b = 0; b < 8; b++)
#pragma unroll
                for (int c = 0; c < 4; c++) acc[a][b][c] = 0.f;

        // prologue chunk 0
        {
#pragma unroll
            for (int g = 0; g < 2; g++) {
                int id = tid + g * 256;
                int br = id >> 2, bc = id & 3;
                uint32_t dst = sbase + (uint32_t)(br * 64 + ((bc ^ ((br >> 1) & 3)) << 4));
                bool pa = (bm + br) < M;
                size_t ga = (size_t)(bm + br) * lda + bc * 8;
                cp_async16(dst, A + ga, pa);
                bool pb = (bn + br) < N;
                size_t gb = (size_t)(bn + br) * K_pad + bc * 8;
                cp_async16(dst + BH_OFF, Bh + gb, pb);
                if (WSPLIT) cp_async16(dst + BL_OFF, Bl + gb, pb);
            }
            CP_COMMIT();
        }

        for (int c = 0; c < nc; c++) {
            const int s = c & 1;
            const uint32_t stg = sbase + (uint32_t)(s * STAGE);

            if (c + 1 < nc) {
                const int col0 = (c + 1) << 5;
                const uint32_t ostg = sbase + (uint32_t)((s ^ 1) * STAGE);
#pragma unroll
                for (int g = 0; g < 2; g++) {
                    int id = tid + g * 256;
                    int br = id >> 2, bc = id & 3;
                    uint32_t dst = ostg + (uint32_t)(br * 64 + ((bc ^ ((br >> 1) & 3)) << 4));
                    bool pa = (bm + br) < M;
                    size_t ga = (size_t)(bm + br) * lda + col0 + bc * 8;
                    cp_async16(dst, A + ga, pa);
                    bool pb = (bn + br) < N;
                    size_t gb = (size_t)(bn + br) * K_pad + col0 + bc * 8;
                    cp_async16(dst + BH_OFF, Bh + gb, pb);
                    if (WSPLIT) cp_async16(dst + BL_OFF, Bl + gb, pb);
                }
                CP_COMMIT();
                CP_WAIT(1);
            } else {
                CP_WAIT(0);
            }
            __syncthreads();

#pragma unroll
            for (int kk = 0; kk < 2; kk++) {
                uint32_t ar[2][4];
#pragma unroll
                for (int mi = 0; mi < 2; mi++) {
                    int row = mw * 32 + mi * 16 + (lane & 15);
                    int ch  = 2 * kk + (lane >> 4);
                    int phys = ch ^ ((row >> 1) & 3);
                    uint32_t off = stg + (uint32_t)(row * 64 + phys * 16);
                    ldsm_x4(ar[mi], off);
                }
#pragma unroll
                for (int h2 = 0; h2 < 2; h2++) {
                    uint32_t bh[2][4], bl[2][4];
#pragma unroll
                    for (int t4 = 0; t4 < 2; t4++) {
                        int row = nw * 64 + (h2 * 2 + t4) * 16 + (lane & 7) + ((lane >> 4) << 3);
                        int ch  = 2 * kk + ((lane >> 3) & 1);
                        int phys = ch ^ ((row >> 1) & 3);
                        uint32_t off = stg + (uint32_t)(row * 64 + phys * 16);
                        ldsm_x4(bh[t4], off + BH_OFF);
                        if (WSPLIT) ldsm_x4(bl[t4], off + BL_OFF);
                    }
#pragma unroll
                    for (int mi = 0; mi < 2; mi++)
#pragma unroll
                        for (int q = 0; q < 4; q++) {
                            float* d = acc[mi][h2 * 4 + q];
                            mma16816h(d, ar[mi], &bh[q >> 1][(q & 1) * 2]);
                            if (WSPLIT) mma16816h(d, ar[mi], &bl[q >> 1][(q & 1) * 2]);
                        }
                }
            }
            __syncthreads();
        }

        // epilogue
#pragma unroll
        for (int mi = 0; mi < 2; mi++) {
            int row0 = bm + mw * 32 + mi * 16 + (lane >> 2);
#pragma unroll
            for (int n8 = 0; n8 < 8; n8++) {
                int col = bn + nw * 64 + n8 * 8 + (lane & 3) * 2;
                if (col >= N) continue;
                float b0 = bias[col], b1 = bias[col + 1];
                float* d = acc[mi][n8];
                float v0 = d[0] + b0, v1 = d[1] + b1;
                float v2 = d[2] + b0, v3 = d[3] + b1;
                if (OUT_MODE >= 1) {
                    v0 = fmaxf(v0, 0.f); v1 = fmaxf(v1, 0.f);
                    v2 = fmaxf(v2, 0.f); v3 = fmaxf(v3, 0.f);
                }
                if (OUT_MODE == 3) {
                    if (row0 < M)     *(uint32_t*)(Ch + (size_t)row0 * ldc + col)       = pack2h(v0, v1);
                    if (row0 + 8 < M) *(uint32_t*)(Ch + (size_t)(row0 + 8) * ldc + col) = pack2h(v2, v3);
                } else {
                    if (row0 < M)     *(float2*)(Cf + (size_t)row0 * ldc + col)       = make_float2(v0, v1);
                    if (row0 + 8 < M) *(float2*)(Cf + (size_t)(row0 + 8) * ldc + col) = make_float2(v2, v3);
                }
            }
        }
    }
}

// ---------------------------------------------------------------------------
// Persistent backbone GEMM: A fp32 (converted to fp16 in the loader,
// bit-identical to a standalone convert), B fp16 single, out fp16+relu.
// SMEM stage: A(8K) B(8K) = 16KB x 2 stages.
// ---------------------------------------------------------------------------
__global__ void __launch_bounds__(256, 2)
gemm_bbone(const float* __restrict__ A, const __half* __restrict__ B,
           const float* __restrict__ bias, __half* __restrict__ Ch,
           int M, int N, int K, int lda, int ldc, int ntiles, int nx)
{
    constexpr uint32_t B_OFF = 8192;
    constexpr uint32_t STAGE = 16384;

    extern __shared__ char smp[];
    const uint32_t sbase = (uint32_t)__cvta_generic_to_shared(smp);

    const int tid  = threadIdx.x;
    const int lane = tid & 31;
    const int w    = tid >> 5;
    const int mw   = w & 3;
    const int nw   = w >> 2;
    const int nc   = K >> 5;

    for (int t = blockIdx.x; t < ntiles; t += gridDim.x) {
        const int bm = (t / nx) * 128;
        const int bn = (t - (t / nx) * nx) * 128;

        float acc[2][8][4];
#pragma unroll
        for (int a = 0; a < 2; a++)
#pragma unroll
            for (int b = 0; b < 8; b++)
#pragma unroll
                for (int c = 0; c < 4; c++) acc[a][b][c] = 0.f;

        float rA[2][8];

        // prologue: regs <- A chunk0, cp.async B chunk0
        {
#pragma unroll
            for (int g = 0; g < 2; g++) {
                int id = tid + g * 256;
                int br = id >> 2, bc = id & 3;
                bool pa = (bm + br) < M;
                const float* src = A + (size_t)(bm + br) * lda + bc * 8;
                if (pa) {
                    float4 f0 = *(const float4*)(src);
                    float4 f1 = *(const float4*)(src + 4);
                    rA[g][0] = f0.x; rA[g][1] = f0.y; rA[g][2] = f0.z; rA[g][3] = f0.w;
                    rA[g][4] = f1.x; rA[g][5] = f1.y; rA[g][6] = f1.z; rA[g][7] = f1.w;
                } else {
#pragma unroll
                    for (int e = 0; e < 8; e++) rA[g][e] = 0.f;
                }
                bool pb = (bn + br) < N;
                size_t gb = (size_t)(bn + br) * K + bc * 8;
                uint32_t dst = sbase + (uint32_t)(br * 64 + ((bc ^ ((br >> 1) & 3)) << 4));
                cp_async16(dst + B_OFF, B + gb, pb);
            }
            CP_COMMIT();
        }

        for (int c = 0; c < nc; c++) {
            const int s = c & 1;
            const uint32_t stg = sbase + (uint32_t)(s * STAGE);

            // STS A chunk c (convert fp32 -> fp16)
#pragma unroll
            for (int g = 0; g < 2; g++) {
                int id = tid + g * 256;
                int br = id >> 2, bc = id & 3;
                uint32_t dst = stg + (uint32_t)(br * 64 + ((bc ^ ((br >> 1) & 3)) << 4));
                uint4 v;
                v.x = pack2h(rA[g][0], rA[g][1]);
                v.y = pack2h(rA[g][2], rA[g][3]);
                v.z = pack2h(rA[g][4], rA[g][5]);
                v.w = pack2h(rA[g][6], rA[g][7]);
                *(uint4*)(smp + (dst - sbase)) = v;
            }

            if (c + 1 < nc) {
                const int col0 = (c + 1) << 5;
                const uint32_t ostg = sbase + (uint32_t)((s ^ 1) * STAGE);
#pragma unroll
                for (int g = 0; g < 2; g++) {
                    int id = tid + g * 256;
                    int br = id >> 2, bc = id & 3;
                    bool pa = (bm + br) < M;
                    const float* src = A + (size_t)(bm + br) * lda + col0 + bc * 8;
                    if (pa) {
                        float4 f0 = *(const float4*)(src);
                        float4 f1 = *(const float4*)(src + 4);
                        rA[g][0] = f0.x; rA[g][1] = f0.y; rA[g][2] = f0.z; rA[g][3] = f0.w;
                        rA[g][4] = f1.x; rA[g][5] = f1.y; rA[g][6] = f1.z; rA[g][7] = f1.w;
                    } else {
#pragma unroll
                        for (int e = 0; e < 8; e++) rA[g][e] = 0.f;
                    }
                    bool pb = (bn + br) < N;
                    size_t gb = (size_t)(bn + br) * K + col0 + bc * 8;
                    uint32_t dst = ostg + (uint32_t)(br * 64 + ((bc ^ ((br >> 1) & 3)) << 4));
                    cp_async16(dst + B_OFF, B + gb, pb);
                }
                CP_COMMIT();
                CP_WAIT(1);
            } else {
                CP_WAIT(0);
            }
            __syncthreads();

#pragma unroll
            for (int kk = 0; kk < 2; kk++) {
                uint32_t ar[2][4];
#pragma unroll
                for (int mi = 0; mi < 2; mi++) {
                    int row = mw * 32 + mi * 16 + (lane & 15);
                    int ch  = 2 * kk + (lane >> 4);
                    int phys = ch ^ ((row >> 1) & 3);
                    uint32_t off = stg + (uint32_t)(row * 64 + phys * 16);
                    ldsm_x4(ar[mi], off);
                }
#pragma unroll
                for (int h2 = 0; h2 < 2; h2++) {
                    uint32_t bh[2][4];
#pragma unroll
                    for (int t4 = 0; t4 < 2; t4++) {
                        int row = nw * 64 + (h2 * 2 + t4) * 16 + (lane & 7) + ((lane >> 4) << 3);
                        int ch  = 2 * kk + ((lane >> 3) & 1);
                        int phys = ch ^ ((row >> 1) & 3);
                        uint32_t off = stg + (uint32_t)(row * 64 + phys * 16);
                        ldsm_x4(bh[t4], off + B_OFF);
                    }
#pragma unroll
                    for (int mi = 0; mi < 2; mi++)
#pragma unroll
                        for (int q = 0; q < 4; q++)
                            mma16816h(acc[mi][h2 * 4 + q], ar[mi], &bh[q >> 1][(q & 1) * 2]);
                }
            }
            __syncthreads();
        }

        // epilogue: relu + fp16
#pragma unroll
        for (int mi = 0; mi < 2; mi++) {
            int row0 = bm + mw * 32 + mi * 16 + (lane >> 2);
#pragma unroll
            for (int n8 = 0; n8 < 8; n8++) {
                int col = bn + nw * 64 + n8 * 8 + (lane & 3) * 2;
                if (col >= N) continue;
                float b0 = bias[col], b1 = bias[col + 1];
                float* d = acc[mi][n8];
                float v0 = fmaxf(d[0] + b0, 0.f), v1 = fmaxf(d[1] + b1, 0.f);
                float v2 = fmaxf(d[2] + b0, 0.f), v3 = fmaxf(d[3] + b1, 0.f);
                if (row0 < M)     *(uint32_t*)(Ch + (size_t)row0 * ldc + col)       = pack2h(v0, v1);
                if (row0 + 8 < M) *(uint32_t*)(Ch + (size_t)(row0 + 8) * ldc + col) = pack2h(v2, v3);
            }
        }
    }
}

// ---------------------------------------------------------------------------
// CSR build kernels
// ---------------------------------------------------------------------------
__global__ void csr_zero_kernel()
{
    int v = blockIdx.x * blockDim.x + threadIdx.x;
    if (v < V_N) { g_deg[v] = 0; g_cur[v] = 0; }
}

__global__ void csr_count_kernel(const int* __restrict__ edges)
{
    int e = blockIdx.x * blockDim.x + threadIdx.x;
    if (e >= E_N) return;
    atomicAdd(&g_deg[edges[2 * e]], 1);
    atomicAdd(&g_deg[edges[2 * e + 1]], 1);
}

__global__ void __launch_bounds__(1024) csr_scan_kernel()
{
    __shared__ int part[1024];
    const int tid = threadIdx.x;
    const int CH = (V_N + 1023) / 1024;
    const int base = tid * CH;
    int s = 0;
#pragma unroll
    for (int q = 0; q < CH; q++) {
        int idx = base + q;
        if (idx < V_N) s += g_deg[idx];
    }
    part[tid] = s;
    __syncthreads();
    for (int o = 1; o < 1024; o <<= 1) {
        int t = (tid >= o) ? part[tid - o] : 0;
        __syncthreads();
        part[tid] += t;
        __syncthreads();
    }
    int run = part[tid] - s;
    for (int q = 0; q < CH; q++) {
        int idx = base + q;
        if (idx < V_N) {
            g_off[idx] = run;
            run += g_deg[idx];
        }
    }
    if (tid == 1023) g_off[V_N] = part[1023];
}

__global__ void csr_fill_kernel(const int* __restrict__ edges)
{
    int e = blockIdx.x * blockDim.x + threadIdx.x;
    if (e >= E_N) return;
    int i = edges[2 * e], j = edges[2 * e + 1];
    int p = g_off[i] + atomicAdd(&g_cur[i], 1);
    g_adj[p] = j;
    p = g_off[j] + atomicAdd(&g_cur[j], 1);
    g_adj[p] = i;
}

// ---------------------------------------------------------------------------
// Fused gather + relu -> fp16
// ---------------------------------------------------------------------------
__global__ void __launch_bounds__(256)
gather_f16_kernel(const float* __restrict__ self, const float* __restrict__ nbr,
                  __half* __restrict__ oh)
{
    int v = blockIdx.x * 4 + (threadIdx.x >> 6);
    if (v >= V_N) return;
    int c = (threadIdx.x & 63) << 2;

    float4 acc = *(const float4*)(self + (size_t)v * H_N + c);
    int s = g_off[v], e = g_off[v + 1];
    for (int p = s; p < e; p++) {
        int u = g_adj[p];
        float4 w = *(const float4*)(nbr + (size_t)u * H_N + c);
        acc.x += w.x; acc.y += w.y; acc.z += w.z; acc.w += w.w;
    }
    acc.x = fmaxf(acc.x, 0.f); acc.y = fmaxf(acc.y, 0.f);
    acc.z = fmaxf(acc.z, 0.f); acc.w = fmaxf(acc.w, 0.f);

    *(uint2*)(oh + (size_t)v * H_N + c) =
        make_uint2(pack2h(acc.x, acc.y), pack2h(acc.z, acc.w));
}

// ---------------------------------------------------------------------------
// Merged weight prep: all hi/lo transposed splits in one launch.
// Segments: W0(288x256->73728) W1(73728) gW0(9x65536) gW1(9x65536)
//           A1(65536) A2(16384)
// ---------------------------------------------------------------------------
#define SEG0 73728
#define SEG1 73728
#define SEG2 589824
#define SEG3 589824
#define SEG4 65536
#define SEG5 16384
#define PREP_TOTAL (SEG0 + SEG1 + SEG2 + SEG3 + SEG4 + SEG5)

__global__ void prep_all_kernel(const float* __restrict__ W0, const float* __restrict__ W1,
                                const float* __restrict__ G0, const float* __restrict__ G1,
                                const float* __restrict__ A1, const float* __restrict__ A2)
{
    int idx = blockIdx.x * blockDim.x + threadIdx.x;
    if (idx >= PREP_TOTAL) return;

    float v;
    __half *ph, *pl;
    int o;
    if (idx < SEG0) {
        o = idx;
        int n = o / 288, k = o - n * 288;
        v = (k < 259) ? W0[(size_t)k * 256 + n] : 0.f;
        ph = w0_h; pl = w0_l;
    } else if (idx < SEG0 + SEG1) {
        o = idx - SEG0;
        int n = o / 288, k = o - n * 288;
        v = (k < 259) ? W1[(size_t)k * 256 + n] : 0.f;
        ph = w1_h; pl = w1_l;
    } else if (idx < SEG0 + SEG1 + SEG2) {
        o = idx - SEG0 - SEG1;
        int mat = o >> 16, r = o & 65535;
        int n = r >> 8, k = r & 255;
        v = G0[(size_t)mat * 65536 + (size_t)k * 256 + n];
        ph = gw0_h; pl = gw0_l;
    } else if (idx < SEG0 + SEG1 + SEG2 + SEG3) {
        o = idx - SEG0 - SEG1 - SEG2;
        int mat = o >> 16, r = o & 65535;
        int n = r >> 8, k = r & 255;
        v = G1[(size_t)mat * 65536 + (size_t)k * 256 + n];
        ph = gw1_h; pl = gw1_l;
    } else if (idx < SEG0 + SEG1 + SEG2 + SEG3 + SEG4) {
        o = idx - SEG0 - SEG1 - SEG2 - SEG3;
        int n = o >> 8, k = o & 255;
        v = A1[(size_t)k * 256 + n];
        ph = a1_h; pl = a1_l;
    } else {
        o = idx - SEG0 - SEG1 - SEG2 - SEG3 - SEG4;
        int n = o >> 8, k = o & 255;
        v = A2[(size_t)k * 64 + n];
        ph = a2_h; pl = a2_l;
    }
    __half h = __float2half_rn(v);
    ph[o] = h;
    pl[o] = __float2half_rn(v - __half2float(h));
}

// backbone: single fp16 transpose
__global__ void prep_w_f16_kernel(const float* __restrict__ W,
                                  __half* __restrict__ o, int K, int N)
{
    int idx = blockIdx.x * blockDim.x + threadIdx.x;
    if (idx >= N * K) return;
    int n = idx / K, k = idx - n * K;
    o[idx] = __float2half(W[(size_t)k * N + n]);
}

// ---------------------------------------------------------------------------
__global__ void concat_verts_kernel(const float* __restrict__ verts)
{
    int idx = blockIdx.x * blockDim.x + threadIdx.x;  // V * 32
    if (idx >= V_N * 32) return;
    int v = idx >> 5, c = idx & 31;
    float x = (c < 3) ? verts[v * 3 + c] : 0.f;
    g_h0[(size_t)v * 288 + 256 + c] = __float2half(x);
}

// ---------------------------------------------------------------------------
__global__ void delta_kernel(const __half* __restrict__ h,
                             const float* __restrict__ Wo,
                             const float* __restrict__ bo,
                             float* __restrict__ out)
{
    __shared__ float sW[H_N * 3];
    __shared__ float sb[3];
    for (int i = threadIdx.x; i < H_N * 3; i += blockDim.x) sW[i] = Wo[i];
    if (threadIdx.x < 3) sb[threadIdx.x] = bo[threadIdx.x];
    __syncthreads();

    int idx = blockIdx.x * blockDim.x + threadIdx.x;
    if (idx >= V_N * 3) return;
    int v = idx / 3, c = idx % 3;
    const __half2* ph = (const __half2*)(h + (size_t)v * H_N);
    float s = sb[c];
#pragma unroll 4
    for (int k = 0; k < H_N / 2; k++) {
        float2 a = __half22float2(ph[k]);
        s = fmaf(a.x, sW[(2 * k) * 3 + c], s);
        s = fmaf(a.y, sW[(2 * k + 1) * 3 + c], s);
    }
    out[idx] = s;
}

// ---------------------------------------------------------------------------
__global__ void tail_kernel(const float* __restrict__ z2,
                            const float* __restrict__ A3,
                            const float* __restrict__ a3,
                            const float* __restrict__ A4,
                            const float* __restrict__ a4,
                            float* __restrict__ conf)
{
    __shared__ float sA3[64 * 32];
    __shared__ float sa3[32];
    __shared__ float sA4[32];
    for (int i = threadIdx.x; i < 64 * 32; i += blockDim.x) sA3[i] = A3[i];
    if (threadIdx.x < 32) {
        sa3[threadIdx.x] = a3[threadIdx.x];
        sA4[threadIdx.x] = A4[threadIdx.x];
    }
    __syncthreads();

    float b4 = a4[0];
    for (int v = blockIdx.x * blockDim.x + threadIdx.x; v < V_N;
         v += gridDim.x * blockDim.x) {
        float x[64];
        const float* zr = z2 + (size_t)v * 64;
#pragma unroll
        for (int k = 0; k < 64; k++) x[k] = zr[k];
        float acc = b4;
#pragma unroll 4
        for (int m = 0; m < 32; m++) {
            float s = sa3[m];
#pragma unroll
            for (int k = 0; k < 64; k++) s = fmaf(x[k], sA3[k * 32 + m], s);
            acc = fmaf(fmaxf(s, 0.f), sA4[m], acc);
        }
        conf[v] = 1.f / (1.f + expf(-acc));
    }
}

// ---------------------------------------------------------------------------
// Launcher
// ---------------------------------------------------------------------------
extern "C" void kernel_launch(void* const* d_in, const int* in_sizes, int n_in,
                              void* d_out, int out_size)
{
    (void)in_sizes; (void)n_in; (void)out_size;
    const float* X     = (const float*)d_in[0];
    const float* verts = (const float*)d_in[1];
    const int*   edges = (const int*)  d_in[2];
    const float* Wb    = (const float*)d_in[3];
    const float* bb    = (const float*)d_in[4];
    const float* W0_0  = (const float*)d_in[5];
    const float* b0_0  = (const float*)d_in[6];
    const float* W1_0  = (const float*)d_in[7];
    const float* b1_0  = (const float*)d_in[8];
    const float* gW0   = (const float*)d_in[9];
    const float* gb0   = (const float*)d_in[10];
    const float* gW1   = (const float*)d_in[11];
    const float* gb1   = (const float*)d_in[12];
    const float* Wo    = (const float*)d_in[13];
    const float* bo    = (const float*)d_in[14];
    const float* A1    = (const float*)d_in[15];
    const float* a1    = (const float*)d_in[16];
    const float* A2    = (const float*)d_in[17];
    const float* a2    = (const float*)d_in[18];
    const float* A3    = (const float*)d_in[19];
    const float* a3    = (const float*)d_in[20];
    const float* A4    = (const float*)d_in[21];
    const float* a4    = (const float*)d_in[22];
    float* out = (float*)d_out;

    __half *ph0, *pa, *pb, *pz1;
    float *pt0, *pt1, *pz2;
    cudaGetSymbolAddress((void**)&ph0, g_h0);
    cudaGetSymbolAddress((void**)&pa,  g_a);
    cudaGetSymbolAddress((void**)&pb,  g_b);
    cudaGetSymbolAddress((void**)&pz1, g_z1);
    cudaGetSymbolAddress((void**)&pt0, g_t0);
    cudaGetSymbolAddress((void**)&pt1, g_t1);
    cudaGetSymbolAddress((void**)&pz2, g_z2);

    __half *pwb, *pw0h, *pw0l, *pw1h, *pw1l;
    __half *pg0h, *pg0l, *pg1h, *pg1l, *pa1h, *pa1l, *pa2h, *pa2l;
    cudaGetSymbolAddress((void**)&pwb,  wb_f);
    cudaGetSymbolAddress((void**)&pw0h, w0_h);  cudaGetSymbolAddress((void**)&pw0l, w0_l);
    cudaGetSymbolAddress((void**)&pw1h, w1_h);  cudaGetSymbolAddress((void**)&pw1l, w1_l);
    cudaGetSymbolAddress((void**)&pg0h, gw0_h); cudaGetSymbolAddress((void**)&pg0l, gw0_l);
    cudaGetSymbolAddress((void**)&pg1h, gw1_h); cudaGetSymbolAddress((void**)&pg1l, gw1_l);
    cudaGetSymbolAddress((void**)&pa1h, a1_h);  cudaGetSymbolAddress((void**)&pa1l, a1_l);
    cudaGetSymbolAddress((void**)&pa2h, a2_h);  cudaGetSymbolAddress((void**)&pa2l, a2_l);

    const int SMEM1 = 32768;   // single-pass / backbone
    const int SMEM2 = 49152;   // weight-split 2-pass
    cudaFuncSetAttribute((const void*)gemm_bbone, cudaFuncAttributeMaxDynamicSharedMemorySize, SMEM1);
    cudaFuncSetAttribute((const void*)gemm_tpl<0, true,  true >, cudaFuncAttributeMaxDynamicSharedMemorySize, SMEM2);
    cudaFuncSetAttribute((const void*)gemm_tpl<3, false, true >, cudaFuncAttributeMaxDynamicSharedMemorySize, SMEM2);
    cudaFuncSetAttribute((const void*)gemm_tpl<1, false, true >, cudaFuncAttributeMaxDynamicSharedMemorySize, SMEM2);

    const int MT = (V_N + 127) / 128;   // 161
    const int SLOTS = 296;              // 148 SMs x 2 CTAs
    const dim3 blk(256);
    const int GATHER_GRID = (V_N + 3) / 4;

    // ---- CSR build ----
    csr_zero_kernel<<<(V_N + 255) / 256, 256>>>();
    csr_count_kernel<<<(E_N + 255) / 256, 256>>>(edges);
    csr_scan_kernel<<<1, 1024>>>();
    csr_fill_kernel<<<(E_N + 255) / 256, 256>>>(edges);

    // ---- weight prep (2 launches) ----
    prep_w_f16_kernel<<<(256 * 3840 + 255) / 256, 256>>>(Wb, pwb, 3840, 256);
    prep_all_kernel<<<(PREP_TOTAL + 255) / 256, 256>>>(W0_0, W1_0, gW0, gW1, A1, A2);

    // 1) backbone (persistent, fp32 A converted in-loader): h0 = relu(X @ Wb + bb)
    {
        int ntiles = MT * 2;
        int grid = ntiles < SLOTS ? ntiles : SLOTS;
        gemm_bbone<<<grid, blk, SMEM1>>>(X, pwb, bb, ph0,
                                         V_N, 256, 3840, 3840, 288, ntiles, 2);
    }

    // 2) concat verts (fp16)
    concat_verts_kernel<<<(V_N * 32 + 255) / 256, 256>>>(verts);

    // 3) layer 0 fused pair (persistent, weight-split, K_pad=288)
    {
        int ntiles = MT * 4;
        int grid = ntiles < SLOTS ? ntiles : SLOTS;
        gemm_tpl<0, true, true><<<grid, blk, SMEM2>>>(
            ph0,
            pw0h, pw0l, b0_0, pt0, nullptr,
            pw1h, pw1l, b1_0, pt1, nullptr,
            V_N, 256, 288, 288, 256, ntiles, 4);
    }
    gather_f16_kernel<<<GATHER_GRID, 256>>>(pt0, pt1, pa);

    // 4) layers 1..9, persistent fused pairs
    __half *cur = pa, *nxt = pb;
    {
        int ntiles = MT * 4;
        int grid = ntiles < SLOTS ? ntiles : SLOTS;
        for (int k = 0; k < 9; k++) {
            const __half* W0h = pg0h + (size_t)k * 65536;
            const __half* W0l = pg0l + (size_t)k * 65536;
            const __half* W1h = pg1h + (size_t)k * 65536;
            const __half* W1l = pg1l + (size_t)k * 65536;
            const float* B0 = gb0 + (size_t)k * H_N;
            const float* B1 = gb1 + (size_t)k * H_N;
            gemm_tpl<0, true, true><<<grid, blk, SMEM2>>>(
                cur,
                W0h, W0l, B0, pt0, nullptr,
                W1h, W1l, B1, pt1, nullptr,
                V_N, 256, 256, 256, 256, ntiles, 4);
            gather_f16_kernel<<<GATHER_GRID, 256>>>(pt0, pt1, nxt);
            __half* t = cur; cur = nxt; nxt = t;
        }
    }
    // final relu(h) fp16 in cur

    // 5) delta_v -> out[0 : V*3]
    delta_kernel<<<(V_N * 3 + 255) / 256, 256>>>(cur, Wo, bo, out);

    // 6) z1 = relu(h @ A1 + a1), persistent weight-split, fp16 out
    {
        int ntiles = MT * 2;
        int grid = ntiles < SLOTS ? ntiles : SLOTS;
        gemm_tpl<3, false, true><<<grid, blk, SMEM2>>>(
            cur,
            pa1h, pa1l, a1, nullptr, pz1,
            nullptr, nullptr, nullptr, nullptr, nullptr,
            V_N, 256, 256, 256, 256, ntiles, 2);
    }

    // 7) z2 = relu(z1 @ A2 + a2), persistent weight-split, fp32 out
    {
        int ntiles = MT;
        int grid = ntiles < SLOTS ? ntiles : SLOTS;
        gemm_tpl<1, false, true><<<grid, blk, SMEM2>>>(
            pz1,
            pa2h, pa2l, a2, pz2, nullptr,
            nullptr, nullptr, nullptr, nullptr, nullptr,
            V_N, 64, 256, 256, 64, ntiles, 1);
    }

    // 8) conf -> out[V*3 : V*4]
    tail_kernel<<<128, 256>>>(pz2, A3, a3, A4, a4, out + (size_t)V_N * 3);
}